// round 4
// baseline (speedup 1.0000x reference)
#include <cuda_runtime.h>

#define EPSBN 1e-5f

// ---------------- device scratch ----------------
__device__ float  g_F1a[3145728];
__device__ float4 g_F1b[3145728];
__device__ float  g_h1[32505856];          // [1024,32,31,32] padded rows
__device__ float  g_part1[32*3844*2];
__device__ float  g_bn1p[64];
__device__ float  g_F2a[7372800];          // [1024,32,15,15]
__device__ float4 g_F2b[7372800];
__device__ float  g_h2[14680064];          // [1024,64,14,16] padded rows
__device__ float  g_part2[64*1568*2];
__device__ float  g_bn2p[128];
__device__ float  g_p2[3211264];           // [1024,3136]
__device__ float  g_fc1p[8*65536];
__device__ float  g_a1[65536];
__device__ float  g_bn3p[128];
__device__ float  g_W1[60*32];
__device__ float  g_W2[640*64];

// ---------------- f32x2 packed math ----------------
__device__ __forceinline__ void fma2(unsigned long long &d, unsigned long long a, unsigned long long b) {
    asm("fma.rn.f32x2 %0, %1, %2, %3;" : "=l"(d) : "l"(a), "l"(b), "l"(d));
}
__device__ __forceinline__ unsigned long long pack2(float v) {
    unsigned long long r;
    asm("mov.b64 %0, {%1, %1};" : "=l"(r) : "r"(__float_as_uint(v)));
    return r;
}
__device__ __forceinline__ float2 u2f(unsigned long long u) {
    float2 f;
    f.x = __uint_as_float((unsigned)u);
    f.y = __uint_as_float((unsigned)(u >> 32));
    return f;
}

// silu + 4 cubic B-spline bases on knots {-7,-5,...,7}
__device__ __forceinline__ void feats5(float v, float f[5]) {
    f[0] = v / (1.f + __expf(-v));
    float b[7];
#pragma unroll
    for (int j = 0; j < 7; j++) {
        float gj = 2.f * j - 7.f;
        b[j] = (v >= gj && v < gj + 2.f) ? 1.f : 0.f;
    }
#pragma unroll
    for (int p = 1; p <= 3; p++) {
        float inv = 1.f / (2.f * p);
#pragma unroll
        for (int j = 0; j < 7 - p; j++) {
            float gj = 2.f * j - 7.f;
            b[j] = ((v - gj) * b[j] + (gj + 2.f * (p + 1) - v) * b[j + 1]) * inv;
        }
    }
    f[1] = b[0]; f[2] = b[1]; f[3] = b[2]; f[4] = b[3];
}

__global__ void wprep_kernel(const float* __restrict__ wb1, const float* __restrict__ ws1,
                             const float* __restrict__ wb2, const float* __restrict__ ws2) {
    int q = blockIdx.x * 256 + threadIdx.x;
    if (q < 1920) {
        int o = q & 31, kk = q >> 5;
        int ii = kk / 5, t = kk - ii * 5;
        g_W1[kk * 32 + o] = (t == 0) ? wb1[o * 12 + ii] : ws1[(o * 12 + ii) * 4 + (t - 1)];
    }
    int q2 = q - 1920;
    if (q2 >= 0 && q2 < 40960) {
        int o = q2 & 63, kk = q2 >> 6;
        int ii = kk / 5, t = kk - ii * 5;
        g_W2[kk * 64 + o] = (t == 0) ? wb2[o * 128 + ii] : ws2[(o * 128 + ii) * 4 + (t - 1)];
    }
}

__global__ void feat1_kernel(const float* __restrict__ x) {
    int i = blockIdx.x * 256 + threadIdx.x;
    if (i >= 3145728) return;
    float f[5]; feats5(x[i], f);
    g_F1a[i] = f[0];
    g_F1b[i] = make_float4(f[1], f[2], f[3], f[4]);
}

// conv1 GEMM: M=984064, N=32, K=60 (2 chunks of 30), f32x2 + fused BN partials
__global__ __launch_bounds__(256) void conv1_gemm() {
    __shared__ __align__(16) float As[30][256];   // reused as 4096-float stat buffer
    __shared__ __align__(16) float Bs[30][32];
    __shared__ int ipb[256];
    const int tid = threadIdx.x;
    const int m0 = blockIdx.x * 256;
    const int px = tid & 63, oy = tid >> 6;
    {
        int m = m0 + tid;
        int bb = m / 961, r = m - bb * 961;
        int y = r / 31, xx = r - y * 31;
        ipb[tid] = ((bb * 3) * 32 + y) * 32 + xx;
    }
    unsigned long long acc2[4][4];
#pragma unroll
    for (int a = 0; a < 4; a++)
#pragma unroll
        for (int p = 0; p < 4; p++) acc2[a][p] = 0ull;

    for (int chunk = 0; chunk < 2; chunk++) {
        __syncthreads();
        for (int q = tid; q < 960; q += 256) {
            int o = q & 31, kk = q >> 5;
            Bs[kk][o] = g_W1[(chunk * 30 + kk) * 32 + o];
        }
        for (int q = tid; q < 1536; q += 256) {
            int pos = q & 255, ii = q >> 8;
            int i = chunk * 6 + ii;
            int c = i >> 2, j = i & 3;
            int pix = ipb[pos] + c * 1024 + ((j & 2) << 4) + (j & 1);
            float f0 = g_F1a[pix];
            float4 f4 = g_F1b[pix];
            As[ii * 5 + 0][pos] = f0;
            As[ii * 5 + 1][pos] = f4.x;
            As[ii * 5 + 2][pos] = f4.y;
            As[ii * 5 + 3][pos] = f4.z;
            As[ii * 5 + 4][pos] = f4.w;
        }
        __syncthreads();
#pragma unroll 5
        for (int k = 0; k < 30; k++) {
            float4 av = *(const float4*)&As[k][px * 4];
            ulonglong2 b01 = *(const ulonglong2*)&Bs[k][oy * 8];
            ulonglong2 b23 = *(const ulonglong2*)&Bs[k][oy * 8 + 4];
            float aa[4] = {av.x, av.y, av.z, av.w};
#pragma unroll
            for (int a = 0; a < 4; a++) {
                unsigned long long a2 = pack2(aa[a]);
                fma2(acc2[a][0], a2, b01.x);
                fma2(acc2[a][1], a2, b01.y);
                fma2(acc2[a][2], a2, b23.x);
                fma2(acc2[a][3], a2, b23.y);
            }
        }
    }
    // store outputs (padded rows) + local per-channel stats over 4 positions
    float ls[8], lss[8];
#pragma unroll
    for (int c = 0; c < 8; c++) { ls[c] = 0.f; lss[c] = 0.f; }
#pragma unroll
    for (int a = 0; a < 4; a++) {
        int m = m0 + px * 4 + a;
        int bb = m / 961, r = m - bb * 961;
        int y = r / 31, xx = r - y * 31;
#pragma unroll
        for (int p = 0; p < 4; p++) {
            float2 v = u2f(acc2[a][p]);
            g_h1[((bb * 32 + oy * 8 + 2 * p + 0) * 31 + y) * 32 + xx] = v.x;
            g_h1[((bb * 32 + oy * 8 + 2 * p + 1) * 31 + y) * 32 + xx] = v.y;
            ls[2 * p]     += v.x; lss[2 * p]     += v.x * v.x;
            ls[2 * p + 1] += v.y; lss[2 * p + 1] += v.y * v.y;
        }
    }
    __syncthreads();
    float* sm = &As[0][0];                       // [0..2047] sums, [2048..4095] sumsq
#pragma unroll
    for (int c = 0; c < 8; c++) {
        sm[(oy * 8 + c) * 64 + px] = ls[c];
        sm[2048 + (oy * 8 + c) * 64 + px] = lss[c];
    }
    __syncthreads();
    if (tid < 64) {
        int c = tid & 31;
        const float* base = sm + (tid >> 5) * 2048 + c * 64;
        float s = 0.f;
        for (int i = 0; i < 64; i++) s += base[i];
        g_part1[(c * 3844 + blockIdx.x) * 2 + (tid >> 5)] = s;
    }
}

__global__ void finalize1_kernel(const float* __restrict__ gam, const float* __restrict__ bet) {
    __shared__ float rs[256], rq[256];
    int c = blockIdx.x;
    float s = 0.f, ss = 0.f;
    for (int i = threadIdx.x; i < 3844; i += 256) {
        s  += g_part1[(c * 3844 + i) * 2 + 0];
        ss += g_part1[(c * 3844 + i) * 2 + 1];
    }
    rs[threadIdx.x] = s; rq[threadIdx.x] = ss; __syncthreads();
    for (int st = 128; st; st >>= 1) {
        if (threadIdx.x < st) { rs[threadIdx.x] += rs[threadIdx.x + st]; rq[threadIdx.x] += rq[threadIdx.x + st]; }
        __syncthreads();
    }
    if (threadIdx.x == 0) {
        float mean = rs[0] / 984064.f;
        float var  = rq[0] / 984064.f - mean * mean;
        float sc   = gam[c] * rsqrtf(var + EPSBN);
        g_bn1p[2 * c + 0] = sc;
        g_bn1p[2 * c + 1] = bet[c] - mean * sc;
    }
}

// bn1 + relu + maxpool + conv2 feature generation
__global__ void pool1feat_kernel() {
    int idx = blockIdx.x * 256 + threadIdx.x;
    if (idx >= 7372800) return;
    int xo = idx % 15; int t1 = idx / 15;
    int yo = t1 % 15;  int t2 = t1 / 15;
    int c  = t2 & 31;  int b  = t2 >> 5;
    float sc = g_bn1p[2 * c], sh = g_bn1p[2 * c + 1];
    const float* p = g_h1 + ((b * 32 + c) * 31 + 2 * yo) * 32 + 2 * xo;
    float2 r0 = *(const float2*)p;
    float2 r1 = *(const float2*)(p + 32);
    float m = fmaxf(fmaxf(r0.x, r0.y), fmaxf(r1.x, r1.y));
    float v = fmaxf(fmaf(m, sc, sh), 0.f);
    float f[5]; feats5(v, f);
    g_F2a[idx] = f[0];
    g_F2b[idx] = make_float4(f[1], f[2], f[3], f[4]);
}

// conv2 GEMM: M=200704, N=64, K=640 (16 chunks of 40), f32x2 + fused BN partials
__global__ __launch_bounds__(256) void conv2_gemm() {
    __shared__ __align__(16) float As[40][128];   // 5120 floats, reused for stats
    __shared__ __align__(16) float Bs[40][64];
    __shared__ int ipb[128];
    const int tid = threadIdx.x;
    const int m0 = blockIdx.x * 128;
    const int px = tid & 31, oy = tid >> 5;
    if (tid < 128) {
        int m = m0 + tid;
        int bb = m / 196, r = m - bb * 196;
        int y = r / 14, xx = r - y * 14;
        ipb[tid] = ((bb * 32) * 15 + y) * 15 + xx;
    }
    unsigned long long acc2[4][4];
#pragma unroll
    for (int a = 0; a < 4; a++)
#pragma unroll
        for (int p = 0; p < 4; p++) acc2[a][p] = 0ull;

    for (int chunk = 0; chunk < 16; chunk++) {
        __syncthreads();
        for (int q = tid; q < 2560; q += 256) {
            int o = q & 63, kk = q >> 6;
            Bs[kk][o] = g_W2[(chunk * 40 + kk) * 64 + o];
        }
        for (int q = tid; q < 1024; q += 256) {
            int pos = q & 127, ii = q >> 7;
            int i = chunk * 8 + ii;
            int c = i >> 2, j = i & 3;
            int pix = ipb[pos] + c * 225 + (j >> 1) * 15 + (j & 1);
            float f0 = g_F2a[pix];
            float4 f4 = g_F2b[pix];
            As[ii * 5 + 0][pos] = f0;
            As[ii * 5 + 1][pos] = f4.x;
            As[ii * 5 + 2][pos] = f4.y;
            As[ii * 5 + 3][pos] = f4.z;
            As[ii * 5 + 4][pos] = f4.w;
        }
        __syncthreads();
#pragma unroll 5
        for (int k = 0; k < 40; k++) {
            float4 av = *(const float4*)&As[k][px * 4];
            ulonglong2 b01 = *(const ulonglong2*)&Bs[k][oy * 8];
            ulonglong2 b23 = *(const ulonglong2*)&Bs[k][oy * 8 + 4];
            float aa[4] = {av.x, av.y, av.z, av.w};
#pragma unroll
            for (int a = 0; a < 4; a++) {
                unsigned long long a2 = pack2(aa[a]);
                fma2(acc2[a][0], a2, b01.x);
                fma2(acc2[a][1], a2, b01.y);
                fma2(acc2[a][2], a2, b23.x);
                fma2(acc2[a][3], a2, b23.y);
            }
        }
    }
    float ls[8], lss[8];
#pragma unroll
    for (int c = 0; c < 8; c++) { ls[c] = 0.f; lss[c] = 0.f; }
#pragma unroll
    for (int a = 0; a < 4; a++) {
        int m = m0 + px * 4 + a;
        int bb = m / 196, r = m - bb * 196;
        int y = r / 14, xx = r - y * 14;
#pragma unroll
        for (int p = 0; p < 4; p++) {
            float2 v = u2f(acc2[a][p]);
            g_h2[((bb * 64 + oy * 8 + 2 * p + 0) * 14 + y) * 16 + xx] = v.x;
            g_h2[((bb * 64 + oy * 8 + 2 * p + 1) * 14 + y) * 16 + xx] = v.y;
            ls[2 * p]     += v.x; lss[2 * p]     += v.x * v.x;
            ls[2 * p + 1] += v.y; lss[2 * p + 1] += v.y * v.y;
        }
    }
    __syncthreads();
    float* sm = &As[0][0];                       // [0..2047] sums, [2048..4095] sumsq
#pragma unroll
    for (int c = 0; c < 8; c++) {
        sm[(oy * 8 + c) * 32 + px] = ls[c];
        sm[2048 + (oy * 8 + c) * 32 + px] = lss[c];
    }
    __syncthreads();
    if (tid < 128) {
        int c = tid & 63;
        const float* base = sm + (tid >> 6) * 2048 + c * 32;
        float s = 0.f;
        for (int i = 0; i < 32; i++) s += base[i];
        g_part2[(c * 1568 + blockIdx.x) * 2 + (tid >> 6)] = s;
    }
}

__global__ void finalize2_kernel(const float* __restrict__ gam, const float* __restrict__ bet) {
    __shared__ float rs[256], rq[256];
    int c = blockIdx.x;
    float s = 0.f, ss = 0.f;
    for (int i = threadIdx.x; i < 1568; i += 256) {
        s  += g_part2[(c * 1568 + i) * 2 + 0];
        ss += g_part2[(c * 1568 + i) * 2 + 1];
    }
    rs[threadIdx.x] = s; rq[threadIdx.x] = ss; __syncthreads();
    for (int st = 128; st; st >>= 1) {
        if (threadIdx.x < st) { rs[threadIdx.x] += rs[threadIdx.x + st]; rq[threadIdx.x] += rq[threadIdx.x + st]; }
        __syncthreads();
    }
    if (threadIdx.x == 0) {
        float mean = rs[0] / 200704.f;
        float var  = rq[0] / 200704.f - mean * mean;
        float sc   = gam[c] * rsqrtf(var + EPSBN);
        g_bn2p[2 * c + 0] = sc;
        g_bn2p[2 * c + 1] = bet[c] - mean * sc;
    }
}

// bn2 + relu + maxpool -> flat [1024,3136]
__global__ void pool2_kernel() {
    int idx = blockIdx.x * 256 + threadIdx.x;
    if (idx >= 3211264) return;
    int xo = idx % 7; int t1 = idx / 7;
    int yo = t1 % 7;  int t2 = t1 / 7;
    int c  = t2 & 63;  int b  = t2 >> 6;
    float sc = g_bn2p[2 * c], sh = g_bn2p[2 * c + 1];
    const float* p = g_h2 + ((b * 64 + c) * 14 + 2 * yo) * 16 + 2 * xo;
    float2 r0 = *(const float2*)p;
    float2 r1 = *(const float2*)(p + 16);
    float m = fmaxf(fmaxf(r0.x, r0.y), fmaxf(r1.x, r1.y));
    g_p2[idx] = fmaxf(fmaf(m, sc, sh), 0.f);
}

// fc1: [1024,3136]x[64,3136]^T, k-split 8, 64-row tiles, f32x2
__global__ __launch_bounds__(256) void fc1_kernel(const float* __restrict__ w) {
    __shared__ __align__(16) float Xs[56][64];
    __shared__ __align__(16) float Ws[56][64];
    const int tid = threadIdx.x;
    const int b0 = blockIdx.x * 64;
    const int ks = blockIdx.y;
    const int o0 = (tid & 15) * 4, r0 = (tid >> 4) * 4;
    unsigned long long acc2[4][2];
#pragma unroll
    for (int a = 0; a < 4; a++) { acc2[a][0] = 0ull; acc2[a][1] = 0ull; }
    for (int cc = 0; cc < 7; cc++) {
        int k0 = ks * 392 + cc * 56;
        __syncthreads();
        for (int q = tid; q < 3584; q += 256) {
            int k = q / 64, rr = q & 63;
            Xs[k][rr] = g_p2[(b0 + rr) * 3136 + k0 + k];
            Ws[k][rr] = w[rr * 3136 + k0 + k];
        }
        __syncthreads();
#pragma unroll 8
        for (int k = 0; k < 56; k++) {
            float4 xv = *(const float4*)&Xs[k][r0];
            ulonglong2 wv = *(const ulonglong2*)&Ws[k][o0];
            float aa[4] = {xv.x, xv.y, xv.z, xv.w};
#pragma unroll
            for (int a = 0; a < 4; a++) {
                unsigned long long a2 = pack2(aa[a]);
                fma2(acc2[a][0], a2, wv.x);
                fma2(acc2[a][1], a2, wv.y);
            }
        }
    }
#pragma unroll
    for (int a = 0; a < 4; a++) {
        float2 v0 = u2f(acc2[a][0]);
        float2 v1 = u2f(acc2[a][1]);
        float* dst = g_fc1p + ks * 65536 + (b0 + r0 + a) * 64 + o0;
        dst[0] = v0.x; dst[1] = v0.y; dst[2] = v1.x; dst[3] = v1.y;
    }
}

__global__ void bn3_kernel(const float* __restrict__ fc1b,
                           const float* __restrict__ gam, const float* __restrict__ bet) {
    __shared__ float rs[256], rq[256];
    int c = blockIdx.x;
    float bias = fc1b[c];
    float s = 0.f, ss = 0.f;
    for (int b = threadIdx.x; b < 1024; b += 256) {
        float v = bias;
#pragma unroll
        for (int k = 0; k < 8; k++) v += g_fc1p[k * 65536 + b * 64 + c];
        g_a1[b * 64 + c] = v;
        s += v; ss += v * v;
    }
    rs[threadIdx.x] = s; rq[threadIdx.x] = ss; __syncthreads();
    for (int st = 128; st; st >>= 1) {
        if (threadIdx.x < st) { rs[threadIdx.x] += rs[threadIdx.x + st]; rq[threadIdx.x] += rq[threadIdx.x + st]; }
        __syncthreads();
    }
    if (threadIdx.x == 0) {
        float mean = rs[0] / 1024.f;
        float var  = rq[0] / 1024.f - mean * mean;
        float sc   = gam[c] * rsqrtf(var + EPSBN);
        g_bn3p[2 * c + 0] = sc;
        g_bn3p[2 * c + 1] = bet[c] - mean * sc;
    }
}

__global__ void final_kernel(const float* __restrict__ w2, const float* __restrict__ b2,
                             float* __restrict__ out) {
    __shared__ float hm[64];
    int b = blockIdx.x, tid = threadIdx.x;
    float v = g_a1[b * 64 + tid];
    hm[tid] = fmaxf(fmaf(v, g_bn3p[2 * tid], g_bn3p[2 * tid + 1]), 0.f);
    __syncthreads();
    if (tid < 10) {
        float acc = b2[tid];
#pragma unroll
        for (int k = 0; k < 64; k++) acc = fmaf(hm[k], w2[tid * 64 + k], acc);
        out[b * 10 + tid] = acc;
    }
}

extern "C" void kernel_launch(void* const* d_in, const int* in_sizes, int n_in,
                              void* d_out, int out_size) {
    const float* x    = (const float*)d_in[0];
    const float* bw1  = (const float*)d_in[1];
    const float* sw1  = (const float*)d_in[2];
    const float* bn1g = (const float*)d_in[3];
    const float* bn1b = (const float*)d_in[4];
    const float* bw2  = (const float*)d_in[5];
    const float* sw2  = (const float*)d_in[6];
    const float* bn2g = (const float*)d_in[7];
    const float* bn2b = (const float*)d_in[8];
    const float* fc1w = (const float*)d_in[9];
    const float* fc1b = (const float*)d_in[10];
    const float* bn3g = (const float*)d_in[11];
    const float* bn3b = (const float*)d_in[12];
    const float* fc2w = (const float*)d_in[13];
    const float* fc2b = (const float*)d_in[14];
    float* out = (float*)d_out;

    wprep_kernel<<<168, 256>>>(bw1, sw1, bw2, sw2);
    feat1_kernel<<<12288, 256>>>(x);
    conv1_gemm<<<3844, 256>>>();
    finalize1_kernel<<<32, 256>>>(bn1g, bn1b);
    pool1feat_kernel<<<28800, 256>>>();
    conv2_gemm<<<1568, 256>>>();
    finalize2_kernel<<<64, 256>>>(bn2g, bn2b);
    pool2_kernel<<<12544, 256>>>();
    fc1_kernel<<<dim3(16, 8), 256>>>(fc1w);
    bn3_kernel<<<64, 256>>>(fc1b, bn3g, bn3b);
    final_kernel<<<1024, 64>>>(fc2w, fc2b, out);
}

// round 5
// speedup vs baseline: 1.4435x; 1.4435x over previous
#include <cuda_runtime.h>

#define EPSBN 1e-5f

// ---------------- device scratch ----------------
__device__ float  g_F1a[3145728];
__device__ float4 g_F1b[3145728];
__device__ float  g_h1[31588352];          // [1024,32,964] (961 used, 3 pad = always 0)
__device__ float  g_part1[32*64*2];
__device__ float  g_bn1p[64];
__device__ float  g_F2a[7372800];          // [1024,32,15,15]
__device__ float4 g_F2b[7372800];
__device__ float  g_h2[12845056];          // [1024,64,196] (196*4 = 16B-aligned rows)
__device__ float  g_part2[64*16*2];
__device__ float  g_bn2p[128];
__device__ float  g_p2[3211264];           // [1024,3136]
__device__ float  g_fc1p[8*65536];
__device__ float  g_a1[65536];
__device__ float  g_bn3p[128];
__device__ float  g_W1[60*32];
__device__ float  g_W2[640*64];

// ---------------- f32x2 packed math ----------------
__device__ __forceinline__ void fma2(unsigned long long &d, unsigned long long a, unsigned long long b) {
    asm("fma.rn.f32x2 %0, %1, %2, %3;" : "=l"(d) : "l"(a), "l"(b), "l"(d));
}
__device__ __forceinline__ unsigned long long pack2(float v) {
    unsigned long long r;
    asm("mov.b64 %0, {%1, %1};" : "=l"(r) : "r"(__float_as_uint(v)));
    return r;
}
__device__ __forceinline__ float2 u2f(unsigned long long u) {
    float2 f;
    f.x = __uint_as_float((unsigned)u);
    f.y = __uint_as_float((unsigned)(u >> 32));
    return f;
}

// silu + 4 cubic B-spline bases on knots {-7,-5,...,7}
__device__ __forceinline__ void feats5(float v, float f[5]) {
    f[0] = v / (1.f + __expf(-v));
    float b[7];
#pragma unroll
    for (int j = 0; j < 7; j++) {
        float gj = 2.f * j - 7.f;
        b[j] = (v >= gj && v < gj + 2.f) ? 1.f : 0.f;
    }
#pragma unroll
    for (int p = 1; p <= 3; p++) {
        float inv = 1.f / (2.f * p);
#pragma unroll
        for (int j = 0; j < 7 - p; j++) {
            float gj = 2.f * j - 7.f;
            b[j] = ((v - gj) * b[j] + (gj + 2.f * (p + 1) - v) * b[j + 1]) * inv;
        }
    }
    f[1] = b[0]; f[2] = b[1]; f[3] = b[2]; f[4] = b[3];
}

__global__ void wprep_kernel(const float* __restrict__ wb1, const float* __restrict__ ws1,
                             const float* __restrict__ wb2, const float* __restrict__ ws2) {
    int q = blockIdx.x * 256 + threadIdx.x;
    if (q < 1920) {
        int o = q & 31, kk = q >> 5;
        int ii = kk / 5, t = kk - ii * 5;
        g_W1[kk * 32 + o] = (t == 0) ? wb1[o * 12 + ii] : ws1[(o * 12 + ii) * 4 + (t - 1)];
    }
    int q2 = q - 1920;
    if (q2 >= 0 && q2 < 40960) {
        int o = q2 & 63, kk = q2 >> 6;
        int ii = kk / 5, t = kk - ii * 5;
        g_W2[kk * 64 + o] = (t == 0) ? wb2[o * 128 + ii] : ws2[(o * 128 + ii) * 4 + (t - 1)];
    }
}

__global__ void feat1_kernel(const float* __restrict__ x) {
    int i = blockIdx.x * 256 + threadIdx.x;
    if (i >= 3145728) return;
    float f[5]; feats5(x[i], f);
    g_F1a[i] = f[0];
    g_F1b[i] = make_float4(f[1], f[2], f[3], f[4]);
}

// conv1 GEMM: M=984064, N=32, K=60 (2 chunks of 30), f32x2 inner loop
__global__ __launch_bounds__(256) void conv1_gemm() {
    __shared__ __align__(16) float As[30][256];
    __shared__ __align__(16) float Bs[30][32];
    __shared__ int ipb[256];
    const int tid = threadIdx.x;
    const int m0 = blockIdx.x * 256;
    const int px = tid & 63, oy = tid >> 6;
    {
        int m = m0 + tid;
        int bb = m / 961, r = m - bb * 961;
        int y = r / 31, xx = r - y * 31;
        ipb[tid] = ((bb * 3) * 32 + y) * 32 + xx;
    }
    unsigned long long acc2[4][4];
#pragma unroll
    for (int a = 0; a < 4; a++)
#pragma unroll
        for (int p = 0; p < 4; p++) acc2[a][p] = 0ull;

    for (int chunk = 0; chunk < 2; chunk++) {
        __syncthreads();
        for (int q = tid; q < 960; q += 256) {
            int o = q & 31, kk = q >> 5;
            Bs[kk][o] = g_W1[(chunk * 30 + kk) * 32 + o];
        }
        for (int q = tid; q < 1536; q += 256) {
            int pos = q & 255, ii = q >> 8;
            int i = chunk * 6 + ii;
            int c = i >> 2, j = i & 3;
            int pix = ipb[pos] + c * 1024 + ((j & 2) << 4) + (j & 1);
            float f0 = g_F1a[pix];
            float4 f4 = g_F1b[pix];
            As[ii * 5 + 0][pos] = f0;
            As[ii * 5 + 1][pos] = f4.x;
            As[ii * 5 + 2][pos] = f4.y;
            As[ii * 5 + 3][pos] = f4.z;
            As[ii * 5 + 4][pos] = f4.w;
        }
        __syncthreads();
#pragma unroll 5
        for (int k = 0; k < 30; k++) {
            float4 av = *(const float4*)&As[k][px * 4];
            ulonglong2 b01 = *(const ulonglong2*)&Bs[k][oy * 8];
            ulonglong2 b23 = *(const ulonglong2*)&Bs[k][oy * 8 + 4];
            float aa[4] = {av.x, av.y, av.z, av.w};
#pragma unroll
            for (int a = 0; a < 4; a++) {
                unsigned long long a2 = pack2(aa[a]);
                fma2(acc2[a][0], a2, b01.x);
                fma2(acc2[a][1], a2, b01.y);
                fma2(acc2[a][2], a2, b23.x);
                fma2(acc2[a][3], a2, b23.y);
            }
        }
    }
#pragma unroll
    for (int a = 0; a < 4; a++) {
        int m = m0 + px * 4 + a;
        int bb = m / 961, r = m - bb * 961;
#pragma unroll
        for (int p = 0; p < 4; p++) {
            float2 v = u2f(acc2[a][p]);
            g_h1[(bb * 32 + oy * 8 + 2 * p + 0) * 964 + r] = v.x;
            g_h1[(bb * 32 + oy * 8 + 2 * p + 1) * 964 + r] = v.y;
        }
    }
}

// per-channel sum/sumsq over padded rows (pad floats are always 0 -> no effect)
__global__ void reduce1_kernel() {
    __shared__ float rs[256], rq[256];
    int c = blockIdx.y, b0 = blockIdx.x * 16;
    float s = 0.f, ss = 0.f;
    for (int b = b0; b < b0 + 16; b++) {
        const float4* p = (const float4*)(g_h1 + (b * 32 + c) * 964);
        for (int i = threadIdx.x; i < 241; i += 256) {
            float4 v = p[i];
            s  += (v.x + v.y) + (v.z + v.w);
            ss += (v.x * v.x + v.y * v.y) + (v.z * v.z + v.w * v.w);
        }
    }
    rs[threadIdx.x] = s; rq[threadIdx.x] = ss; __syncthreads();
    for (int st = 128; st; st >>= 1) {
        if (threadIdx.x < st) { rs[threadIdx.x] += rs[threadIdx.x + st]; rq[threadIdx.x] += rq[threadIdx.x + st]; }
        __syncthreads();
    }
    if (threadIdx.x == 0) {
        g_part1[(c * 64 + blockIdx.x) * 2 + 0] = rs[0];
        g_part1[(c * 64 + blockIdx.x) * 2 + 1] = rq[0];
    }
}

__global__ void reduce2_kernel() {
    __shared__ float rs[256], rq[256];
    int c = blockIdx.y, b0 = blockIdx.x * 64;
    float s = 0.f, ss = 0.f;
    for (int b = b0; b < b0 + 64; b++) {
        const float4* p = (const float4*)(g_h2 + (b * 64 + c) * 196);
        for (int i = threadIdx.x; i < 49; i += 256) {
            float4 v = p[i];
            s  += (v.x + v.y) + (v.z + v.w);
            ss += (v.x * v.x + v.y * v.y) + (v.z * v.z + v.w * v.w);
        }
    }
    rs[threadIdx.x] = s; rq[threadIdx.x] = ss; __syncthreads();
    for (int st = 128; st; st >>= 1) {
        if (threadIdx.x < st) { rs[threadIdx.x] += rs[threadIdx.x + st]; rq[threadIdx.x] += rq[threadIdx.x + st]; }
        __syncthreads();
    }
    if (threadIdx.x == 0) {
        g_part2[(c * 16 + blockIdx.x) * 2 + 0] = rs[0];
        g_part2[(c * 16 + blockIdx.x) * 2 + 1] = rq[0];
    }
}

__global__ void finalize_bn(int which, const float* __restrict__ gam, const float* __restrict__ bet) {
    int c = blockIdx.x;
    const float* part; float* out2; int nparts; float invc;
    if (which == 0) { part = g_part1; out2 = g_bn1p; nparts = 64; invc = 1.f / 984064.f; }
    else            { part = g_part2; out2 = g_bn2p; nparts = 16; invc = 1.f / 200704.f; }
    float s = 0.f, ss = 0.f;
    for (int i = threadIdx.x; i < nparts; i += 32) {
        s  += part[(c * nparts + i) * 2 + 0];
        ss += part[(c * nparts + i) * 2 + 1];
    }
#pragma unroll
    for (int off = 16; off; off >>= 1) {
        s  += __shfl_down_sync(0xffffffffu, s, off);
        ss += __shfl_down_sync(0xffffffffu, ss, off);
    }
    if (threadIdx.x == 0) {
        float mean = s * invc;
        float var  = ss * invc - mean * mean;
        float sc   = gam[c] * rsqrtf(var + EPSBN);
        out2[2 * c + 0] = sc;
        out2[2 * c + 1] = bet[c] - mean * sc;
    }
}

// bn1 + relu + maxpool + conv2 feature generation
__global__ void pool1feat_kernel() {
    int idx = blockIdx.x * 256 + threadIdx.x;
    if (idx >= 7372800) return;
    int xo = idx % 15; int t1 = idx / 15;
    int yo = t1 % 15;  int t2 = t1 / 15;
    int c  = t2 & 31;  int b  = t2 >> 5;
    float sc = g_bn1p[2 * c], sh = g_bn1p[2 * c + 1];
    const float* p = g_h1 + (b * 32 + c) * 964 + (2 * yo) * 31 + 2 * xo;
    float m = fmaxf(fmaxf(p[0], p[1]), fmaxf(p[31], p[32]));
    float v = fmaxf(fmaf(m, sc, sh), 0.f);
    float f[5]; feats5(v, f);
    g_F2a[idx] = f[0];
    g_F2b[idx] = make_float4(f[1], f[2], f[3], f[4]);
}

// conv2 GEMM: M=200704, N=64, K=640 (16 chunks of 40), f32x2 inner loop
__global__ __launch_bounds__(256) void conv2_gemm() {
    __shared__ __align__(16) float As[40][128];
    __shared__ __align__(16) float Bs[40][64];
    __shared__ int ipb[128];
    const int tid = threadIdx.x;
    const int m0 = blockIdx.x * 128;
    const int px = tid & 31, oy = tid >> 5;
    if (tid < 128) {
        int m = m0 + tid;
        int bb = m / 196, r = m - bb * 196;
        int y = r / 14, xx = r - y * 14;
        ipb[tid] = ((bb * 32) * 15 + y) * 15 + xx;
    }
    unsigned long long acc2[4][4];
#pragma unroll
    for (int a = 0; a < 4; a++)
#pragma unroll
        for (int p = 0; p < 4; p++) acc2[a][p] = 0ull;

    for (int chunk = 0; chunk < 16; chunk++) {
        __syncthreads();
        for (int q = tid; q < 2560; q += 256) {
            int o = q & 63, kk = q >> 6;
            Bs[kk][o] = g_W2[(chunk * 40 + kk) * 64 + o];
        }
        for (int q = tid; q < 1024; q += 256) {
            int pos = q & 127, ii = q >> 7;
            int i = chunk * 8 + ii;
            int c = i >> 2, j = i & 3;
            int pix = ipb[pos] + c * 225 + (j >> 1) * 15 + (j & 1);
            float f0 = g_F2a[pix];
            float4 f4 = g_F2b[pix];
            As[ii * 5 + 0][pos] = f0;
            As[ii * 5 + 1][pos] = f4.x;
            As[ii * 5 + 2][pos] = f4.y;
            As[ii * 5 + 3][pos] = f4.z;
            As[ii * 5 + 4][pos] = f4.w;
        }
        __syncthreads();
#pragma unroll 5
        for (int k = 0; k < 40; k++) {
            float4 av = *(const float4*)&As[k][px * 4];
            ulonglong2 b01 = *(const ulonglong2*)&Bs[k][oy * 8];
            ulonglong2 b23 = *(const ulonglong2*)&Bs[k][oy * 8 + 4];
            float aa[4] = {av.x, av.y, av.z, av.w};
#pragma unroll
            for (int a = 0; a < 4; a++) {
                unsigned long long a2 = pack2(aa[a]);
                fma2(acc2[a][0], a2, b01.x);
                fma2(acc2[a][1], a2, b01.y);
                fma2(acc2[a][2], a2, b23.x);
                fma2(acc2[a][3], a2, b23.y);
            }
        }
    }
#pragma unroll
    for (int a = 0; a < 4; a++) {
        int m = m0 + px * 4 + a;
        int bb = m / 196, r = m - bb * 196;
#pragma unroll
        for (int p = 0; p < 4; p++) {
            float2 v = u2f(acc2[a][p]);
            g_h2[(bb * 64 + oy * 8 + 2 * p + 0) * 196 + r] = v.x;
            g_h2[(bb * 64 + oy * 8 + 2 * p + 1) * 196 + r] = v.y;
        }
    }
}

// bn2 + relu + maxpool -> flat [1024,3136]
__global__ void pool2_kernel() {
    int idx = blockIdx.x * 256 + threadIdx.x;
    if (idx >= 3211264) return;
    int xo = idx % 7; int t1 = idx / 7;
    int yo = t1 % 7;  int t2 = t1 / 7;
    int c  = t2 & 63;  int b  = t2 >> 6;
    float sc = g_bn2p[2 * c], sh = g_bn2p[2 * c + 1];
    const float* p = g_h2 + (b * 64 + c) * 196 + (2 * yo) * 14 + 2 * xo;
    float m = fmaxf(fmaxf(p[0], p[1]), fmaxf(p[14], p[15]));
    g_p2[idx] = fmaxf(fmaf(m, sc, sh), 0.f);
}

// fc1: [1024,3136]x[64,3136]^T, k-split 8, 64-row tiles, f32x2
__global__ __launch_bounds__(256) void fc1_kernel(const float* __restrict__ w) {
    __shared__ __align__(16) float Xs[56][64];
    __shared__ __align__(16) float Ws[56][64];
    const int tid = threadIdx.x;
    const int b0 = blockIdx.x * 64;
    const int ks = blockIdx.y;
    const int o0 = (tid & 15) * 4, r0 = (tid >> 4) * 4;
    unsigned long long acc2[4][2];
#pragma unroll
    for (int a = 0; a < 4; a++) { acc2[a][0] = 0ull; acc2[a][1] = 0ull; }
    for (int cc = 0; cc < 7; cc++) {
        int k0 = ks * 392 + cc * 56;
        __syncthreads();
        for (int q = tid; q < 3584; q += 256) {
            int k = q / 64, rr = q & 63;
            Xs[k][rr] = g_p2[(b0 + rr) * 3136 + k0 + k];
            Ws[k][rr] = w[rr * 3136 + k0 + k];
        }
        __syncthreads();
#pragma unroll 8
        for (int k = 0; k < 56; k++) {
            float4 xv = *(const float4*)&Xs[k][r0];
            ulonglong2 wv = *(const ulonglong2*)&Ws[k][o0];
            float aa[4] = {xv.x, xv.y, xv.z, xv.w};
#pragma unroll
            for (int a = 0; a < 4; a++) {
                unsigned long long a2 = pack2(aa[a]);
                fma2(acc2[a][0], a2, wv.x);
                fma2(acc2[a][1], a2, wv.y);
            }
        }
    }
#pragma unroll
    for (int a = 0; a < 4; a++) {
        float2 v0 = u2f(acc2[a][0]);
        float2 v1 = u2f(acc2[a][1]);
        float* dst = g_fc1p + ks * 65536 + (b0 + r0 + a) * 64 + o0;
        dst[0] = v0.x; dst[1] = v0.y; dst[2] = v1.x; dst[3] = v1.y;
    }
}

__global__ void bn3_kernel(const float* __restrict__ fc1b,
                           const float* __restrict__ gam, const float* __restrict__ bet) {
    __shared__ float rs[256], rq[256];
    int c = blockIdx.x;
    float bias = fc1b[c];
    float s = 0.f, ss = 0.f;
    for (int b = threadIdx.x; b < 1024; b += 256) {
        float v = bias;
#pragma unroll
        for (int k = 0; k < 8; k++) v += g_fc1p[k * 65536 + b * 64 + c];
        g_a1[b * 64 + c] = v;
        s += v; ss += v * v;
    }
    rs[threadIdx.x] = s; rq[threadIdx.x] = ss; __syncthreads();
    for (int st = 128; st; st >>= 1) {
        if (threadIdx.x < st) { rs[threadIdx.x] += rs[threadIdx.x + st]; rq[threadIdx.x] += rq[threadIdx.x + st]; }
        __syncthreads();
    }
    if (threadIdx.x == 0) {
        float mean = rs[0] / 1024.f;
        float var  = rq[0] / 1024.f - mean * mean;
        float sc   = gam[c] * rsqrtf(var + EPSBN);
        g_bn3p[2 * c + 0] = sc;
        g_bn3p[2 * c + 1] = bet[c] - mean * sc;
    }
}

__global__ void final_kernel(const float* __restrict__ w2, const float* __restrict__ b2,
                             float* __restrict__ out) {
    __shared__ float hm[64];
    int b = blockIdx.x, tid = threadIdx.x;
    float v = g_a1[b * 64 + tid];
    hm[tid] = fmaxf(fmaf(v, g_bn3p[2 * tid], g_bn3p[2 * tid + 1]), 0.f);
    __syncthreads();
    if (tid < 10) {
        float acc = b2[tid];
#pragma unroll
        for (int k = 0; k < 64; k++) acc = fmaf(hm[k], w2[tid * 64 + k], acc);
        out[b * 10 + tid] = acc;
    }
}

extern "C" void kernel_launch(void* const* d_in, const int* in_sizes, int n_in,
                              void* d_out, int out_size) {
    const float* x    = (const float*)d_in[0];
    const float* bw1  = (const float*)d_in[1];
    const float* sw1  = (const float*)d_in[2];
    const float* bn1g = (const float*)d_in[3];
    const float* bn1b = (const float*)d_in[4];
    const float* bw2  = (const float*)d_in[5];
    const float* sw2  = (const float*)d_in[6];
    const float* bn2g = (const float*)d_in[7];
    const float* bn2b = (const float*)d_in[8];
    const float* fc1w = (const float*)d_in[9];
    const float* fc1b = (const float*)d_in[10];
    const float* bn3g = (const float*)d_in[11];
    const float* bn3b = (const float*)d_in[12];
    const float* fc2w = (const float*)d_in[13];
    const float* fc2b = (const float*)d_in[14];
    float* out = (float*)d_out;

    wprep_kernel<<<168, 256>>>(bw1, sw1, bw2, sw2);
    feat1_kernel<<<12288, 256>>>(x);
    conv1_gemm<<<3844, 256>>>();
    reduce1_kernel<<<dim3(64, 32), 256>>>();
    finalize_bn<<<32, 32>>>(0, bn1g, bn1b);
    pool1feat_kernel<<<28800, 256>>>();
    conv2_gemm<<<1568, 256>>>();
    reduce2_kernel<<<dim3(16, 64), 256>>>();
    finalize_bn<<<64, 32>>>(1, bn2g, bn2b);
    pool2_kernel<<<12544, 256>>>();
    fc1_kernel<<<dim3(16, 8), 256>>>(fc1w);
    bn3_kernel<<<64, 256>>>(fc1b, bn3g, bn3b);
    final_kernel<<<1024, 64>>>(fc2w, fc2b, out);
}

// round 7
// speedup vs baseline: 1.7232x; 1.1938x over previous
#include <cuda_runtime.h>
#include <cuda_fp16.h>
#include <stdint.h>

#define EPSBN 1e-5f

// ---------------- device scratch ----------------
__device__ float  g_F1a[3145728];
__device__ float4 g_F1b[3145728];
__device__ float  g_h1[31588352];          // [1024,32,964]
__device__ float  g_part1[32*64*2];
__device__ float  g_bn1p[64];
__device__ float  g_F2a[7372800];          // [1024,32,15,15]
__device__ float4 g_F2b[7372800];
__device__ float  g_h2[12845056];          // [1024,64,196]
__device__ float  g_part2[64*16*2];
__device__ float  g_bn2p[128];
__device__ float  g_p2[3211264];           // [1024,3136]
__device__ float  g_fc1p[8*65536];
__device__ float  g_a1[65536];
__device__ float  g_bn3p[128];
__device__ float  g_W1[60*32];
__device__ uint2  g_Bf0[12288];            // conv2 B fragments, fp16-hi: [chunk][ks][n8t][lane]
__device__ uint2  g_Bf1[12288];            // fp16-lo

// ---------------- f32x2 packed math ----------------
__device__ __forceinline__ void fma2(unsigned long long &d, unsigned long long a, unsigned long long b) {
    asm("fma.rn.f32x2 %0, %1, %2, %3;" : "=l"(d) : "l"(a), "l"(b), "l"(d));
}
__device__ __forceinline__ unsigned long long pack2(float v) {
    unsigned long long r;
    asm("mov.b64 %0, {%1, %1};" : "=l"(r) : "r"(__float_as_uint(v)));
    return r;
}
__device__ __forceinline__ float2 u2f(unsigned long long u) {
    float2 f;
    f.x = __uint_as_float((unsigned)u);
    f.y = __uint_as_float((unsigned)(u >> 32));
    return f;
}

// ---------------- warp mma m16n8k16 fp16 -> f32 ----------------
__device__ __forceinline__ void mma16816(float* d, const uint32_t* a, uint2 b) {
    asm volatile("mma.sync.aligned.m16n8k16.row.col.f32.f16.f16.f32 "
        "{%0,%1,%2,%3}, {%4,%5,%6,%7}, {%8,%9}, {%0,%1,%2,%3};"
        : "+f"(d[0]), "+f"(d[1]), "+f"(d[2]), "+f"(d[3])
        : "r"(a[0]), "r"(a[1]), "r"(a[2]), "r"(a[3]), "r"(b.x), "r"(b.y));
}

// silu + 4 cubic B-spline bases on knots {-7,-5,...,7}
__device__ __forceinline__ void feats5(float v, float f[5]) {
    f[0] = v / (1.f + __expf(-v));
    float b[7];
#pragma unroll
    for (int j = 0; j < 7; j++) {
        float gj = 2.f * j - 7.f;
        b[j] = (v >= gj && v < gj + 2.f) ? 1.f : 0.f;
    }
#pragma unroll
    for (int p = 1; p <= 3; p++) {
        float inv = 1.f / (2.f * p);
#pragma unroll
        for (int j = 0; j < 7 - p; j++) {
            float gj = 2.f * j - 7.f;
            b[j] = ((v - gj) * b[j] + (gj + 2.f * (p + 1) - v) * b[j + 1]) * inv;
        }
    }
    f[1] = b[0]; f[2] = b[1]; f[3] = b[2]; f[4] = b[3];
}

__global__ void wprep_kernel(const float* __restrict__ wb1, const float* __restrict__ ws1) {
    int q = blockIdx.x * 256 + threadIdx.x;
    if (q < 1920) {
        int o = q & 31, kk = q >> 5;
        int ii = kk / 5, t = kk - ii * 5;
        g_W1[kk * 32 + o] = (t == 0) ? wb1[o * 12 + ii] : ws1[(o * 12 + ii) * 4 + (t - 1)];
    }
}

// conv2 weights -> per-lane mma B fragments, fp16 hi/lo split
// frag mapping (m16n8k16 col-major B): b0 = {B[k0][n], B[k0+1][n]}, b1 = {B[k0+8][n], B[k0+9][n]},
// k0 = ks*16 + (lane%4)*2, n = n8t*8 + lane/4
__global__ void wprep2_kernel(const float* __restrict__ wb2, const float* __restrict__ ws2) {
    int q = blockIdx.x * 256 + threadIdx.x;
    if (q >= 12288) return;
    int lane = q & 31; int r = q >> 5;
    int n8t = r & 7; r >>= 3;
    int ks = r % 3; int chunk = r / 3;
    int gid = lane >> 2, tig = lane & 3;
    int n = n8t * 8 + gid;
    uint32_t h[2], l[2];
#pragma unroll
    for (int reg = 0; reg < 2; reg++) {
        uint32_t ph = 0, pl = 0;
#pragma unroll
        for (int e = 0; e < 2; e++) {
            int kk = ks * 16 + tig * 2 + reg * 8 + e;
            float w = 0.f;
            if (kk < 40) {
                int kg = chunk * 40 + kk;
                int i = kg / 5, t = kg - i * 5;
                w = (t == 0) ? wb2[n * 128 + i] : ws2[(n * 128 + i) * 4 + (t - 1)];
            }
            half hh = __float2half_rn(w);
            half hl = __float2half_rn(w - __half2float(hh));
            ph |= (uint32_t)__half_as_ushort(hh) << (16 * e);
            pl |= (uint32_t)__half_as_ushort(hl) << (16 * e);
        }
        h[reg] = ph; l[reg] = pl;
    }
    g_Bf0[q] = make_uint2(h[0], h[1]);
    g_Bf1[q] = make_uint2(l[0], l[1]);
}

__global__ void feat1_kernel(const float* __restrict__ x) {
    int i = blockIdx.x * 256 + threadIdx.x;
    if (i >= 3145728) return;
    float f[5]; feats5(x[i], f);
    g_F1a[i] = f[0];
    g_F1b[i] = make_float4(f[1], f[2], f[3], f[4]);
}

// conv1 GEMM: M=984064, N=32, K=60 (2 chunks of 30), f32x2 inner loop
__global__ __launch_bounds__(256) void conv1_gemm() {
    __shared__ __align__(16) float As[30][256];
    __shared__ __align__(16) float Bs[30][32];
    __shared__ int ipb[256];
    const int tid = threadIdx.x;
    const int m0 = blockIdx.x * 256;
    const int px = tid & 63, oy = tid >> 6;
    {
        int m = m0 + tid;
        int bb = m / 961, r = m - bb * 961;
        int y = r / 31, xx = r - y * 31;
        ipb[tid] = ((bb * 3) * 32 + y) * 32 + xx;
    }
    unsigned long long acc2[4][4];
#pragma unroll
    for (int a = 0; a < 4; a++)
#pragma unroll
        for (int p = 0; p < 4; p++) acc2[a][p] = 0ull;

    for (int chunk = 0; chunk < 2; chunk++) {
        __syncthreads();
        for (int q = tid; q < 960; q += 256) {
            int o = q & 31, kk = q >> 5;
            Bs[kk][o] = g_W1[(chunk * 30 + kk) * 32 + o];
        }
        for (int q = tid; q < 1536; q += 256) {
            int pos = q & 255, ii = q >> 8;
            int i = chunk * 6 + ii;
            int c = i >> 2, j = i & 3;
            int pix = ipb[pos] + c * 1024 + ((j & 2) << 4) + (j & 1);
            float f0 = g_F1a[pix];
            float4 f4 = g_F1b[pix];
            As[ii * 5 + 0][pos] = f0;
            As[ii * 5 + 1][pos] = f4.x;
            As[ii * 5 + 2][pos] = f4.y;
            As[ii * 5 + 3][pos] = f4.z;
            As[ii * 5 + 4][pos] = f4.w;
        }
        __syncthreads();
#pragma unroll 5
        for (int k = 0; k < 30; k++) {
            float4 av = *(const float4*)&As[k][px * 4];
            ulonglong2 b01 = *(const ulonglong2*)&Bs[k][oy * 8];
            ulonglong2 b23 = *(const ulonglong2*)&Bs[k][oy * 8 + 4];
            float aa[4] = {av.x, av.y, av.z, av.w};
#pragma unroll
            for (int a = 0; a < 4; a++) {
                unsigned long long a2 = pack2(aa[a]);
                fma2(acc2[a][0], a2, b01.x);
                fma2(acc2[a][1], a2, b01.y);
                fma2(acc2[a][2], a2, b23.x);
                fma2(acc2[a][3], a2, b23.y);
            }
        }
    }
#pragma unroll
    for (int a = 0; a < 4; a++) {
        int m = m0 + px * 4 + a;
        int bb = m / 961, r = m - bb * 961;
#pragma unroll
        for (int p = 0; p < 4; p++) {
            float2 v = u2f(acc2[a][p]);
            g_h1[(bb * 32 + oy * 8 + 2 * p + 0) * 964 + r] = v.x;
            g_h1[(bb * 32 + oy * 8 + 2 * p + 1) * 964 + r] = v.y;
        }
    }
}

__global__ void reduce1_kernel() {
    __shared__ float rs[256], rq[256];
    int c = blockIdx.y, b0 = blockIdx.x * 16;
    float s = 0.f, ss = 0.f;
    for (int b = b0; b < b0 + 16; b++) {
        const float4* p = (const float4*)(g_h1 + (b * 32 + c) * 964);
        for (int i = threadIdx.x; i < 241; i += 256) {
            float4 v = p[i];
            s  += (v.x + v.y) + (v.z + v.w);
            ss += (v.x * v.x + v.y * v.y) + (v.z * v.z + v.w * v.w);
        }
    }
    rs[threadIdx.x] = s; rq[threadIdx.x] = ss; __syncthreads();
    for (int st = 128; st; st >>= 1) {
        if (threadIdx.x < st) { rs[threadIdx.x] += rs[threadIdx.x + st]; rq[threadIdx.x] += rq[threadIdx.x + st]; }
        __syncthreads();
    }
    if (threadIdx.x == 0) {
        g_part1[(c * 64 + blockIdx.x) * 2 + 0] = rs[0];
        g_part1[(c * 64 + blockIdx.x) * 2 + 1] = rq[0];
    }
}

__global__ void reduce2_kernel() {
    __shared__ float rs[256], rq[256];
    int c = blockIdx.y, b0 = blockIdx.x * 64;
    float s = 0.f, ss = 0.f;
    for (int b = b0; b < b0 + 64; b++) {
        const float4* p = (const float4*)(g_h2 + (b * 64 + c) * 196);
        for (int i = threadIdx.x; i < 49; i += 256) {
            float4 v = p[i];
            s  += (v.x + v.y) + (v.z + v.w);
            ss += (v.x * v.x + v.y * v.y) + (v.z * v.z + v.w * v.w);
        }
    }
    rs[threadIdx.x] = s; rq[threadIdx.x] = ss; __syncthreads();
    for (int st = 128; st; st >>= 1) {
        if (threadIdx.x < st) { rs[threadIdx.x] += rs[threadIdx.x + st]; rq[threadIdx.x] += rq[threadIdx.x + st]; }
        __syncthreads();
    }
    if (threadIdx.x == 0) {
        g_part2[(c * 16 + blockIdx.x) * 2 + 0] = rs[0];
        g_part2[(c * 16 + blockIdx.x) * 2 + 1] = rq[0];
    }
}

__global__ void finalize_bn(int which, const float* __restrict__ gam, const float* __restrict__ bet) {
    int c = blockIdx.x;
    const float* part; float* out2; int nparts; float invc;
    if (which == 0) { part = g_part1; out2 = g_bn1p; nparts = 64; invc = 1.f / 984064.f; }
    else            { part = g_part2; out2 = g_bn2p; nparts = 16; invc = 1.f / 200704.f; }
    float s = 0.f, ss = 0.f;
    for (int i = threadIdx.x; i < nparts; i += 32) {
        s  += part[(c * nparts + i) * 2 + 0];
        ss += part[(c * nparts + i) * 2 + 1];
    }
#pragma unroll
    for (int off = 16; off; off >>= 1) {
        s  += __shfl_down_sync(0xffffffffu, s, off);
        ss += __shfl_down_sync(0xffffffffu, ss, off);
    }
    if (threadIdx.x == 0) {
        float mean = s * invc;
        float var  = ss * invc - mean * mean;
        float sc   = gam[c] * rsqrtf(var + EPSBN);
        out2[2 * c + 0] = sc;
        out2[2 * c + 1] = bet[c] - mean * sc;
    }
}

__global__ void pool1feat_kernel() {
    int idx = blockIdx.x * 256 + threadIdx.x;
    if (idx >= 7372800) return;
    int xo = idx % 15; int t1 = idx / 15;
    int yo = t1 % 15;  int t2 = t1 / 15;
    int c  = t2 & 31;  int b  = t2 >> 5;
    float sc = g_bn1p[2 * c], sh = g_bn1p[2 * c + 1];
    const float* p = g_h1 + (b * 32 + c) * 964 + (2 * yo) * 31 + 2 * xo;
    float m = fmaxf(fmaxf(p[0], p[1]), fmaxf(p[31], p[32]));
    float v = fmaxf(fmaf(m, sc, sh), 0.f);
    float f[5]; feats5(v, f);
    g_F2a[idx] = f[0];
    g_F2b[idx] = make_float4(f[1], f[2], f[3], f[4]);
}

// conv2 via warp mma: M=128/block x N=64, K=16 chunks x 48 (40 real), fp16x3 split
__global__ __launch_bounds__(256) void conv2_mma() {
    __shared__ __align__(16) half A0[128 * 56];
    __shared__ __align__(16) half A1[128 * 56];
    __shared__ int ipb[128];
    const int tid = threadIdx.x;
    const int m0 = blockIdx.x * 128;
    const int warp = tid >> 5, lane = tid & 31;
    const int wm = warp >> 1, wn = warp & 1;
    const int gid = lane >> 2, tig = lane & 3;

    if (tid < 128) {
        int m = m0 + tid;
        int bb = m / 196, r = m - bb * 196;
        int y = r / 14, xx = r - y * 14;
        ipb[tid] = ((bb * 32) * 15 + y) * 15 + xx;
    }
    {   // zero A tiles once; gather only writes cols 0..39, pad cols 40..55 stay 0
        uint4 z = make_uint4(0, 0, 0, 0);
        for (int q = tid; q < 896; q += 256) { ((uint4*)A0)[q] = z; ((uint4*)A1)[q] = z; }
    }

    float d[2][4][4];
#pragma unroll
    for (int mh = 0; mh < 2; mh++)
#pragma unroll
        for (int j = 0; j < 4; j++)
#pragma unroll
            for (int e = 0; e < 4; e++) d[mh][j][e] = 0.f;

    for (int chunk = 0; chunk < 16; chunk++) {
        __syncthreads();
        for (int q = tid; q < 1024; q += 256) {
            int pos = q & 127, ii = q >> 7;
            int i = chunk * 8 + ii;
            int c = i >> 2, j = i & 3;
            int pix = ipb[pos] + c * 225 + (j >> 1) * 15 + (j & 1);
            float f0 = g_F2a[pix];
            float4 f4 = g_F2b[pix];
            float f[5] = {f0, f4.x, f4.y, f4.z, f4.w};
            int base = pos * 56 + ii * 5;
#pragma unroll
            for (int t = 0; t < 5; t++) {
                half h = __float2half_rn(f[t]);
                A0[base + t] = h;
                A1[base + t] = __float2half_rn(f[t] - __half2float(h));
            }
        }
        __syncthreads();
#pragma unroll
        for (int ks = 0; ks < 3; ks++) {
            uint32_t ah[2][4], al[2][4];
            int kw = ks * 8 + tig;   // b32 col index: (ks*16 + tig*2)/2
#pragma unroll
            for (int mh = 0; mh < 2; mh++) {
                int rlo = wm * 32 + mh * 16 + gid;
                const uint32_t* p0l = (const uint32_t*)(A0 + rlo * 56);
                const uint32_t* p0h = (const uint32_t*)(A0 + (rlo + 8) * 56);
                const uint32_t* p1l = (const uint32_t*)(A1 + rlo * 56);
                const uint32_t* p1h = (const uint32_t*)(A1 + (rlo + 8) * 56);
                ah[mh][0] = p0l[kw]; ah[mh][1] = p0h[kw]; ah[mh][2] = p0l[kw + 4]; ah[mh][3] = p0h[kw + 4];
                al[mh][0] = p1l[kw]; al[mh][1] = p1h[kw]; al[mh][2] = p1l[kw + 4]; al[mh][3] = p1h[kw + 4];
            }
#pragma unroll
            for (int j = 0; j < 4; j++) {
                int idx = ((chunk * 3 + ks) * 8 + wn * 4 + j) * 32 + lane;
                uint2 bh = g_Bf0[idx];
                uint2 bl = g_Bf1[idx];
#pragma unroll
                for (int mh = 0; mh < 2; mh++) {
                    mma16816(d[mh][j], ah[mh], bh);
                    mma16816(d[mh][j], ah[mh], bl);
                    mma16816(d[mh][j], al[mh], bh);
                }
            }
        }
    }
    // epilogue: write D
#pragma unroll
    for (int mh = 0; mh < 2; mh++) {
        int mlo = m0 + wm * 32 + mh * 16 + gid;
        int bb0 = mlo / 196, rr0 = mlo - bb0 * 196;
        int mhi = mlo + 8;
        int bb1 = mhi / 196, rr1 = mhi - bb1 * 196;
#pragma unroll
        for (int j = 0; j < 4; j++) {
            int n = (wn * 4 + j) * 8 + tig * 2;
            g_h2[(bb0 * 64 + n) * 196 + rr0]     = d[mh][j][0];
            g_h2[(bb0 * 64 + n + 1) * 196 + rr0] = d[mh][j][1];
            g_h2[(bb1 * 64 + n) * 196 + rr1]     = d[mh][j][2];
            g_h2[(bb1 * 64 + n + 1) * 196 + rr1] = d[mh][j][3];
        }
    }
}

__global__ void pool2_kernel() {
    int idx = blockIdx.x * 256 + threadIdx.x;
    if (idx >= 3211264) return;
    int xo = idx % 7; int t1 = idx / 7;
    int yo = t1 % 7;  int t2 = t1 / 7;
    int c  = t2 & 63;  int b  = t2 >> 6;
    float sc = g_bn2p[2 * c], sh = g_bn2p[2 * c + 1];
    const float* p = g_h2 + (b * 64 + c) * 196 + (2 * yo) * 14 + 2 * xo;
    float m = fmaxf(fmaxf(p[0], p[1]), fmaxf(p[14], p[15]));
    g_p2[idx] = fmaxf(fmaf(m, sc, sh), 0.f);
}

__global__ __launch_bounds__(256) void fc1_kernel(const float* __restrict__ w) {
    __shared__ __align__(16) float Xs[56][64];
    __shared__ __align__(16) float Ws[56][64];
    const int tid = threadIdx.x;
    const int b0 = blockIdx.x * 64;
    const int ks = blockIdx.y;
    const int o0 = (tid & 15) * 4, r0 = (tid >> 4) * 4;
    unsigned long long acc2[4][2];
#pragma unroll
    for (int a = 0; a < 4; a++) { acc2[a][0] = 0ull; acc2[a][1] = 0ull; }
    for (int cc = 0; cc < 7; cc++) {
        int k0 = ks * 392 + cc * 56;
        __syncthreads();
        for (int q = tid; q < 3584; q += 256) {
            int k = q / 64, rr = q & 63;
            Xs[k][rr] = g_p2[(b0 + rr) * 3136 + k0 + k];
            Ws[k][rr] = w[rr * 3136 + k0 + k];
        }
        __syncthreads();
#pragma unroll 8
        for (int k = 0; k < 56; k++) {
            float4 xv = *(const float4*)&Xs[k][r0];
            ulonglong2 wv = *(const ulonglong2*)&Ws[k][o0];
            float aa[4] = {xv.x, xv.y, xv.z, xv.w};
#pragma unroll
            for (int a = 0; a < 4; a++) {
                unsigned long long a2 = pack2(aa[a]);
                fma2(acc2[a][0], a2, wv.x);
                fma2(acc2[a][1], a2, wv.y);
            }
        }
    }
#pragma unroll
    for (int a = 0; a < 4; a++) {
        float2 v0 = u2f(acc2[a][0]);
        float2 v1 = u2f(acc2[a][1]);
        float* dst = g_fc1p + ks * 65536 + (b0 + r0 + a) * 64 + o0;
        dst[0] = v0.x; dst[1] = v0.y; dst[2] = v1.x; dst[3] = v1.y;
    }
}

__global__ void bn3_kernel(const float* __restrict__ fc1b,
                           const float* __restrict__ gam, const float* __restrict__ bet) {
    __shared__ float rs[256], rq[256];
    int c = blockIdx.x;
    float bias = fc1b[c];
    float s = 0.f, ss = 0.f;
    for (int b = threadIdx.x; b < 1024; b += 256) {
        float v = bias;
#pragma unroll
        for (int k = 0; k < 8; k++) v += g_fc1p[k * 65536 + b * 64 + c];
        g_a1[b * 64 + c] = v;
        s += v; ss += v * v;
    }
    rs[threadIdx.x] = s; rq[threadIdx.x] = ss; __syncthreads();
    for (int st = 128; st; st >>= 1) {
        if (threadIdx.x < st) { rs[threadIdx.x] += rs[threadIdx.x + st]; rq[threadIdx.x] += rq[threadIdx.x + st]; }
        __syncthreads();
    }
    if (threadIdx.x == 0) {
        float mean = rs[0] / 1024.f;
        float var  = rq[0] / 1024.f - mean * mean;
        float sc   = gam[c] * rsqrtf(var + EPSBN);
        g_bn3p[2 * c + 0] = sc;
        g_bn3p[2 * c + 1] = bet[c] - mean * sc;
    }
}

__global__ void final_kernel(const float* __restrict__ w2, const float* __restrict__ b2,
                             float* __restrict__ out) {
    __shared__ float hm[64];
    int b = blockIdx.x, tid = threadIdx.x;
    float v = g_a1[b * 64 + tid];
    hm[tid] = fmaxf(fmaf(v, g_bn3p[2 * tid], g_bn3p[2 * tid + 1]), 0.f);
    __syncthreads();
    if (tid < 10) {
        float acc = b2[tid];
#pragma unroll
        for (int k = 0; k < 64; k++) acc = fmaf(hm[k], w2[tid * 64 + k], acc);
        out[b * 10 + tid] = acc;
    }
}

extern "C" void kernel_launch(void* const* d_in, const int* in_sizes, int n_in,
                              void* d_out, int out_size) {
    const float* x    = (const float*)d_in[0];
    const float* bw1  = (const float*)d_in[1];
    const float* sw1  = (const float*)d_in[2];
    const float* bn1g = (const float*)d_in[3];
    const float* bn1b = (const float*)d_in[4];
    const float* bw2  = (const float*)d_in[5];
    const float* sw2  = (const float*)d_in[6];
    const float* bn2g = (const float*)d_in[7];
    const float* bn2b = (const float*)d_in[8];
    const float* fc1w = (const float*)d_in[9];
    const float* fc1b = (const float*)d_in[10];
    const float* bn3g = (const float*)d_in[11];
    const float* bn3b = (const float*)d_in[12];
    const float* fc2w = (const float*)d_in[13];
    const float* fc2b = (const float*)d_in[14];
    float* out = (float*)d_out;

    wprep_kernel<<<8, 256>>>(bw1, sw1);
    wprep2_kernel<<<48, 256>>>(bw2, sw2);
    feat1_kernel<<<12288, 256>>>(x);
    conv1_gemm<<<3844, 256>>>();
    reduce1_kernel<<<dim3(64, 32), 256>>>();
    finalize_bn<<<32, 32>>>(0, bn1g, bn1b);
    pool1feat_kernel<<<28800, 256>>>();
    conv2_mma<<<1568, 256>>>();
    reduce2_kernel<<<dim3(16, 64), 256>>>();
    finalize_bn<<<64, 32>>>(1, bn2g, bn2b);
    pool2_kernel<<<12544, 256>>>();
    fc1_kernel<<<dim3(16, 8), 256>>>(fc1w);
    bn3_kernel<<<64, 256>>>(fc1b, bn3g, bn3b);
    final_kernel<<<1024, 64>>>(fc2w, fc2b, out);
}

// round 8
// speedup vs baseline: 1.7850x; 1.0359x over previous
#include <cuda_runtime.h>
#include <cuda_fp16.h>
#include <stdint.h>

#define EPSBN 1e-5f

// ---------------- device scratch ----------------
__device__ float  g_F1a[3145728];
__device__ float4 g_F1b[3145728];
__device__ float  g_h1[31588352];          // [1024,32,964]
__device__ float  g_part1[32*64*2];
__device__ float  g_bn1p[64];
__device__ float  g_F2a[7372800];          // [1024,32,15,15]
__device__ float4 g_F2b[7372800];
__device__ float  g_h2[12845056];          // [1024,64,196]
__device__ float  g_part2[64*16*2];
__device__ float  g_bn2p[128];
__device__ float  g_p2[3211264];           // [1024,3136]
__device__ float  g_fc1p[8*65536];
__device__ float  g_a1[65536];
__device__ float  g_bn3p[128];
__device__ uint2  g_B1f0[512];             // conv1 B fragments fp16-hi: [ks][n8t][lane]
__device__ uint2  g_B1f1[512];             // fp16-lo
__device__ uint2  g_Bf0[12288];            // conv2 B fragments fp16-hi
__device__ uint2  g_Bf1[12288];            // fp16-lo

// ---------------- f32x2 packed math ----------------
__device__ __forceinline__ void fma2(unsigned long long &d, unsigned long long a, unsigned long long b) {
    asm("fma.rn.f32x2 %0, %1, %2, %3;" : "=l"(d) : "l"(a), "l"(b), "l"(d));
}
__device__ __forceinline__ unsigned long long pack2(float v) {
    unsigned long long r;
    asm("mov.b64 %0, {%1, %1};" : "=l"(r) : "r"(__float_as_uint(v)));
    return r;
}
__device__ __forceinline__ float2 u2f(unsigned long long u) {
    float2 f;
    f.x = __uint_as_float((unsigned)u);
    f.y = __uint_as_float((unsigned)(u >> 32));
    return f;
}

// ---------------- warp mma m16n8k16 fp16 -> f32 ----------------
__device__ __forceinline__ void mma16816(float* d, const uint32_t* a, uint2 b) {
    asm volatile("mma.sync.aligned.m16n8k16.row.col.f32.f16.f16.f32 "
        "{%0,%1,%2,%3}, {%4,%5,%6,%7}, {%8,%9}, {%0,%1,%2,%3};"
        : "+f"(d[0]), "+f"(d[1]), "+f"(d[2]), "+f"(d[3])
        : "r"(a[0]), "r"(a[1]), "r"(a[2]), "r"(a[3]), "r"(b.x), "r"(b.y));
}

// silu + 4 cubic B-spline bases on knots {-7,-5,...,7}
__device__ __forceinline__ void feats5(float v, float f[5]) {
    f[0] = v / (1.f + __expf(-v));
    float b[7];
#pragma unroll
    for (int j = 0; j < 7; j++) {
        float gj = 2.f * j - 7.f;
        b[j] = (v >= gj && v < gj + 2.f) ? 1.f : 0.f;
    }
#pragma unroll
    for (int p = 1; p <= 3; p++) {
        float inv = 1.f / (2.f * p);
#pragma unroll
        for (int j = 0; j < 7 - p; j++) {
            float gj = 2.f * j - 7.f;
            b[j] = ((v - gj) * b[j] + (gj + 2.f * (p + 1) - v) * b[j + 1]) * inv;
        }
    }
    f[1] = b[0]; f[2] = b[1]; f[3] = b[2]; f[4] = b[3];
}

// conv1 weights -> per-lane mma B fragments (K=60 padded to 64)
__global__ void wprep1_kernel(const float* __restrict__ wb1, const float* __restrict__ ws1) {
    int q = blockIdx.x * 256 + threadIdx.x;
    if (q >= 512) return;
    int lane = q & 31; int r = q >> 5;
    int n8t = r & 3; int ks = r >> 2;
    int gid = lane >> 2, tig = lane & 3;
    int n = n8t * 8 + gid;
    uint32_t h[2], l[2];
#pragma unroll
    for (int reg = 0; reg < 2; reg++) {
        uint32_t ph = 0, pl = 0;
#pragma unroll
        for (int e = 0; e < 2; e++) {
            int kk = ks * 16 + tig * 2 + reg * 8 + e;
            float w = 0.f;
            if (kk < 60) {
                int i = kk / 5, t = kk - i * 5;
                w = (t == 0) ? wb1[n * 12 + i] : ws1[(n * 12 + i) * 4 + (t - 1)];
            }
            half hh = __float2half_rn(w);
            half hl = __float2half_rn(w - __half2float(hh));
            ph |= (uint32_t)__half_as_ushort(hh) << (16 * e);
            pl |= (uint32_t)__half_as_ushort(hl) << (16 * e);
        }
        h[reg] = ph; l[reg] = pl;
    }
    g_B1f0[q] = make_uint2(h[0], h[1]);
    g_B1f1[q] = make_uint2(l[0], l[1]);
}

// conv2 weights -> per-lane mma B fragments
__global__ void wprep2_kernel(const float* __restrict__ wb2, const float* __restrict__ ws2) {
    int q = blockIdx.x * 256 + threadIdx.x;
    if (q >= 12288) return;
    int lane = q & 31; int r = q >> 5;
    int n8t = r & 7; r >>= 3;
    int ks = r % 3; int chunk = r / 3;
    int gid = lane >> 2, tig = lane & 3;
    int n = n8t * 8 + gid;
    uint32_t h[2], l[2];
#pragma unroll
    for (int reg = 0; reg < 2; reg++) {
        uint32_t ph = 0, pl = 0;
#pragma unroll
        for (int e = 0; e < 2; e++) {
            int kk = ks * 16 + tig * 2 + reg * 8 + e;
            float w = 0.f;
            if (kk < 40) {
                int kg = chunk * 40 + kk;
                int i = kg / 5, t = kg - i * 5;
                w = (t == 0) ? wb2[n * 128 + i] : ws2[(n * 128 + i) * 4 + (t - 1)];
            }
            half hh = __float2half_rn(w);
            half hl = __float2half_rn(w - __half2float(hh));
            ph |= (uint32_t)__half_as_ushort(hh) << (16 * e);
            pl |= (uint32_t)__half_as_ushort(hl) << (16 * e);
        }
        h[reg] = ph; l[reg] = pl;
    }
    g_Bf0[q] = make_uint2(h[0], h[1]);
    g_Bf1[q] = make_uint2(l[0], l[1]);
}

__global__ void feat1_kernel(const float* __restrict__ x) {
    int i = blockIdx.x * 256 + threadIdx.x;
    if (i >= 3145728) return;
    float f[5]; feats5(x[i], f);
    g_F1a[i] = f[0];
    g_F1b[i] = make_float4(f[1], f[2], f[3], f[4]);
}

// conv1 via warp mma: M=128/block x N=32, K=60 (1 chunk of 64), fp16x3 split
__global__ __launch_bounds__(256) void conv1_mma() {
    __shared__ __align__(16) half A0[128 * 72];
    __shared__ __align__(16) half A1[128 * 72];
    __shared__ int ipb[128];
    const int tid = threadIdx.x;
    const int m0 = blockIdx.x * 128;
    const int warp = tid >> 5, lane = tid & 31;
    const int wm = warp >> 1, wn = warp & 1;
    const int gid = lane >> 2, tig = lane & 3;

    if (tid < 128) {
        int m = m0 + tid;
        int bb = m / 961, r = m - bb * 961;
        int y = r / 31, xx = r - y * 31;
        ipb[tid] = ((bb * 3) * 32 + y) * 32 + xx;
    }
    {
        uint4 z = make_uint4(0, 0, 0, 0);
        for (int q = tid; q < 1152; q += 256) { ((uint4*)A0)[q] = z; ((uint4*)A1)[q] = z; }
    }
    __syncthreads();
    for (int q = tid; q < 1536; q += 256) {
        int pos = q & 127, ii = q >> 7;
        int c = ii >> 2, j = ii & 3;
        int pix = ipb[pos] + c * 1024 + ((j & 2) << 4) + (j & 1);
        float f0 = g_F1a[pix];
        float4 f4 = g_F1b[pix];
        float f[5] = {f0, f4.x, f4.y, f4.z, f4.w};
        int base = pos * 72 + ii * 5;
#pragma unroll
        for (int t = 0; t < 5; t++) {
            half h = __float2half_rn(f[t]);
            A0[base + t] = h;
            A1[base + t] = __float2half_rn(f[t] - __half2float(h));
        }
    }
    __syncthreads();

    float d[2][2][4];
#pragma unroll
    for (int mh = 0; mh < 2; mh++)
#pragma unroll
        for (int j = 0; j < 2; j++)
#pragma unroll
            for (int e = 0; e < 4; e++) d[mh][j][e] = 0.f;

#pragma unroll
    for (int ks = 0; ks < 4; ks++) {
        uint32_t ah[2][4], al[2][4];
        int kw = ks * 8 + tig;
#pragma unroll
        for (int mh = 0; mh < 2; mh++) {
            int rlo = wm * 32 + mh * 16 + gid;
            const uint32_t* p0l = (const uint32_t*)(A0 + rlo * 72);
            const uint32_t* p0h = (const uint32_t*)(A0 + (rlo + 8) * 72);
            const uint32_t* p1l = (const uint32_t*)(A1 + rlo * 72);
            const uint32_t* p1h = (const uint32_t*)(A1 + (rlo + 8) * 72);
            ah[mh][0] = p0l[kw]; ah[mh][1] = p0h[kw]; ah[mh][2] = p0l[kw + 4]; ah[mh][3] = p0h[kw + 4];
            al[mh][0] = p1l[kw]; al[mh][1] = p1h[kw]; al[mh][2] = p1l[kw + 4]; al[mh][3] = p1h[kw + 4];
        }
#pragma unroll
        for (int j = 0; j < 2; j++) {
            int idx = (ks * 4 + wn * 2 + j) * 32 + lane;
            uint2 bh = g_B1f0[idx];
            uint2 bl = g_B1f1[idx];
#pragma unroll
            for (int mh = 0; mh < 2; mh++) {
                mma16816(d[mh][j], ah[mh], bh);
                mma16816(d[mh][j], ah[mh], bl);
                mma16816(d[mh][j], al[mh], bh);
            }
        }
    }
#pragma unroll
    for (int mh = 0; mh < 2; mh++) {
        int mlo = m0 + wm * 32 + mh * 16 + gid;
        int bb0 = mlo / 961, rr0 = mlo - bb0 * 961;
        int mhi = mlo + 8;
        int bb1 = mhi / 961, rr1 = mhi - bb1 * 961;
#pragma unroll
        for (int j = 0; j < 2; j++) {
            int n = (wn * 2 + j) * 8 + tig * 2;
            g_h1[(bb0 * 32 + n) * 964 + rr0]     = d[mh][j][0];
            g_h1[(bb0 * 32 + n + 1) * 964 + rr0] = d[mh][j][1];
            g_h1[(bb1 * 32 + n) * 964 + rr1]     = d[mh][j][2];
            g_h1[(bb1 * 32 + n + 1) * 964 + rr1] = d[mh][j][3];
        }
    }
}

__global__ void reduce1_kernel() {
    __shared__ float rs[256], rq[256];
    int c = blockIdx.y, b0 = blockIdx.x * 16;
    float s = 0.f, ss = 0.f;
    for (int b = b0; b < b0 + 16; b++) {
        const float4* p = (const float4*)(g_h1 + (b * 32 + c) * 964);
        for (int i = threadIdx.x; i < 241; i += 256) {
            float4 v = p[i];
            s  += (v.x + v.y) + (v.z + v.w);
            ss += (v.x * v.x + v.y * v.y) + (v.z * v.z + v.w * v.w);
        }
    }
    rs[threadIdx.x] = s; rq[threadIdx.x] = ss; __syncthreads();
    for (int st = 128; st; st >>= 1) {
        if (threadIdx.x < st) { rs[threadIdx.x] += rs[threadIdx.x + st]; rq[threadIdx.x] += rq[threadIdx.x + st]; }
        __syncthreads();
    }
    if (threadIdx.x == 0) {
        g_part1[(c * 64 + blockIdx.x) * 2 + 0] = rs[0];
        g_part1[(c * 64 + blockIdx.x) * 2 + 1] = rq[0];
    }
}

__global__ void reduce2_kernel() {
    __shared__ float rs[256], rq[256];
    int c = blockIdx.y, b0 = blockIdx.x * 64;
    float s = 0.f, ss = 0.f;
    for (int b = b0; b < b0 + 64; b++) {
        const float4* p = (const float4*)(g_h2 + (b * 64 + c) * 196);
        for (int i = threadIdx.x; i < 49; i += 256) {
            float4 v = p[i];
            s  += (v.x + v.y) + (v.z + v.w);
            ss += (v.x * v.x + v.y * v.y) + (v.z * v.z + v.w * v.w);
        }
    }
    rs[threadIdx.x] = s; rq[threadIdx.x] = ss; __syncthreads();
    for (int st = 128; st; st >>= 1) {
        if (threadIdx.x < st) { rs[threadIdx.x] += rs[threadIdx.x + st]; rq[threadIdx.x] += rq[threadIdx.x + st]; }
        __syncthreads();
    }
    if (threadIdx.x == 0) {
        g_part2[(c * 16 + blockIdx.x) * 2 + 0] = rs[0];
        g_part2[(c * 16 + blockIdx.x) * 2 + 1] = rq[0];
    }
}

__global__ void finalize_bn(int which, const float* __restrict__ gam, const float* __restrict__ bet) {
    int c = blockIdx.x;
    const float* part; float* out2; int nparts; float invc;
    if (which == 0) { part = g_part1; out2 = g_bn1p; nparts = 64; invc = 1.f / 984064.f; }
    else            { part = g_part2; out2 = g_bn2p; nparts = 16; invc = 1.f / 200704.f; }
    float s = 0.f, ss = 0.f;
    for (int i = threadIdx.x; i < nparts; i += 32) {
        s  += part[(c * nparts + i) * 2 + 0];
        ss += part[(c * nparts + i) * 2 + 1];
    }
#pragma unroll
    for (int off = 16; off; off >>= 1) {
        s  += __shfl_down_sync(0xffffffffu, s, off);
        ss += __shfl_down_sync(0xffffffffu, ss, off);
    }
    if (threadIdx.x == 0) {
        float mean = s * invc;
        float var  = ss * invc - mean * mean;
        float sc   = gam[c] * rsqrtf(var + EPSBN);
        out2[2 * c + 0] = sc;
        out2[2 * c + 1] = bet[c] - mean * sc;
    }
}

__global__ void pool1feat_kernel() {
    int idx = blockIdx.x * 256 + threadIdx.x;
    if (idx >= 7372800) return;
    int xo = idx % 15; int t1 = idx / 15;
    int yo = t1 % 15;  int t2 = t1 / 15;
    int c  = t2 & 31;  int b  = t2 >> 5;
    float sc = g_bn1p[2 * c], sh = g_bn1p[2 * c + 1];
    const float* p = g_h1 + (b * 32 + c) * 964 + (2 * yo) * 31 + 2 * xo;
    float m = fmaxf(fmaxf(p[0], p[1]), fmaxf(p[31], p[32]));
    float v = fmaxf(fmaf(m, sc, sh), 0.f);
    float f[5]; feats5(v, f);
    g_F2a[idx] = f[0];
    g_F2b[idx] = make_float4(f[1], f[2], f[3], f[4]);
}

// conv2 via warp mma: M=128/block x N=64, K=16 chunks x 48 (40 real), fp16x3 split
__global__ __launch_bounds__(256) void conv2_mma() {
    __shared__ __align__(16) half A0[128 * 56];
    __shared__ __align__(16) half A1[128 * 56];
    __shared__ int ipb[128];
    const int tid = threadIdx.x;
    const int m0 = blockIdx.x * 128;
    const int warp = tid >> 5, lane = tid & 31;
    const int wm = warp >> 1, wn = warp & 1;
    const int gid = lane >> 2, tig = lane & 3;

    if (tid < 128) {
        int m = m0 + tid;
        int bb = m / 196, r = m - bb * 196;
        int y = r / 14, xx = r - y * 14;
        ipb[tid] = ((bb * 32) * 15 + y) * 15 + xx;
    }
    {
        uint4 z = make_uint4(0, 0, 0, 0);
        for (int q = tid; q < 896; q += 256) { ((uint4*)A0)[q] = z; ((uint4*)A1)[q] = z; }
    }

    float d[2][4][4];
#pragma unroll
    for (int mh = 0; mh < 2; mh++)
#pragma unroll
        for (int j = 0; j < 4; j++)
#pragma unroll
            for (int e = 0; e < 4; e++) d[mh][j][e] = 0.f;

    for (int chunk = 0; chunk < 16; chunk++) {
        __syncthreads();
        for (int q = tid; q < 1024; q += 256) {
            int pos = q & 127, ii = q >> 7;
            int i = chunk * 8 + ii;
            int c = i >> 2, j = i & 3;
            int pix = ipb[pos] + c * 225 + (j >> 1) * 15 + (j & 1);
            float f0 = g_F2a[pix];
            float4 f4 = g_F2b[pix];
            float f[5] = {f0, f4.x, f4.y, f4.z, f4.w};
            int base = pos * 56 + ii * 5;
#pragma unroll
            for (int t = 0; t < 5; t++) {
                half h = __float2half_rn(f[t]);
                A0[base + t] = h;
                A1[base + t] = __float2half_rn(f[t] - __half2float(h));
            }
        }
        __syncthreads();
#pragma unroll
        for (int ks = 0; ks < 3; ks++) {
            uint32_t ah[2][4], al[2][4];
            int kw = ks * 8 + tig;
#pragma unroll
            for (int mh = 0; mh < 2; mh++) {
                int rlo = wm * 32 + mh * 16 + gid;
                const uint32_t* p0l = (const uint32_t*)(A0 + rlo * 56);
                const uint32_t* p0h = (const uint32_t*)(A0 + (rlo + 8) * 56);
                const uint32_t* p1l = (const uint32_t*)(A1 + rlo * 56);
                const uint32_t* p1h = (const uint32_t*)(A1 + (rlo + 8) * 56);
                ah[mh][0] = p0l[kw]; ah[mh][1] = p0h[kw]; ah[mh][2] = p0l[kw + 4]; ah[mh][3] = p0h[kw + 4];
                al[mh][0] = p1l[kw]; al[mh][1] = p1h[kw]; al[mh][2] = p1l[kw + 4]; al[mh][3] = p1h[kw + 4];
            }
#pragma unroll
            for (int j = 0; j < 4; j++) {
                int idx = ((chunk * 3 + ks) * 8 + wn * 4 + j) * 32 + lane;
                uint2 bh = g_Bf0[idx];
                uint2 bl = g_Bf1[idx];
#pragma unroll
                for (int mh = 0; mh < 2; mh++) {
                    mma16816(d[mh][j], ah[mh], bh);
                    mma16816(d[mh][j], ah[mh], bl);
                    mma16816(d[mh][j], al[mh], bh);
                }
            }
        }
    }
#pragma unroll
    for (int mh = 0; mh < 2; mh++) {
        int mlo = m0 + wm * 32 + mh * 16 + gid;
        int bb0 = mlo / 196, rr0 = mlo - bb0 * 196;
        int mhi = mlo + 8;
        int bb1 = mhi / 196, rr1 = mhi - bb1 * 196;
#pragma unroll
        for (int j = 0; j < 4; j++) {
            int n = (wn * 4 + j) * 8 + tig * 2;
            g_h2[(bb0 * 64 + n) * 196 + rr0]     = d[mh][j][0];
            g_h2[(bb0 * 64 + n + 1) * 196 + rr0] = d[mh][j][1];
            g_h2[(bb1 * 64 + n) * 196 + rr1]     = d[mh][j][2];
            g_h2[(bb1 * 64 + n + 1) * 196 + rr1] = d[mh][j][3];
        }
    }
}

__global__ void pool2_kernel() {
    int idx = blockIdx.x * 256 + threadIdx.x;
    if (idx >= 3211264) return;
    int xo = idx % 7; int t1 = idx / 7;
    int yo = t1 % 7;  int t2 = t1 / 7;
    int c  = t2 & 63;  int b  = t2 >> 6;
    float sc = g_bn2p[2 * c], sh = g_bn2p[2 * c + 1];
    const float* p = g_h2 + (b * 64 + c) * 196 + (2 * yo) * 14 + 2 * xo;
    float m = fmaxf(fmaxf(p[0], p[1]), fmaxf(p[14], p[15]));
    g_p2[idx] = fmaxf(fmaf(m, sc, sh), 0.f);
}

__global__ __launch_bounds__(256) void fc1_kernel(const float* __restrict__ w) {
    __shared__ __align__(16) float Xs[56][64];
    __shared__ __align__(16) float Ws[56][64];
    const int tid = threadIdx.x;
    const int b0 = blockIdx.x * 64;
    const int ks = blockIdx.y;
    const int o0 = (tid & 15) * 4, r0 = (tid >> 4) * 4;
    unsigned long long acc2[4][2];
#pragma unroll
    for (int a = 0; a < 4; a++) { acc2[a][0] = 0ull; acc2[a][1] = 0ull; }
    for (int cc = 0; cc < 7; cc++) {
        int k0 = ks * 392 + cc * 56;
        __syncthreads();
        for (int q = tid; q < 3584; q += 256) {
            int k = q / 64, rr = q & 63;
            Xs[k][rr] = g_p2[(b0 + rr) * 3136 + k0 + k];
            Ws[k][rr] = w[rr * 3136 + k0 + k];
        }
        __syncthreads();
#pragma unroll 8
        for (int k = 0; k < 56; k++) {
            float4 xv = *(const float4*)&Xs[k][r0];
            ulonglong2 wv = *(const ulonglong2*)&Ws[k][o0];
            float aa[4] = {xv.x, xv.y, xv.z, xv.w};
#pragma unroll
            for (int a = 0; a < 4; a++) {
                unsigned long long a2 = pack2(aa[a]);
                fma2(acc2[a][0], a2, wv.x);
                fma2(acc2[a][1], a2, wv.y);
            }
        }
    }
#pragma unroll
    for (int a = 0; a < 4; a++) {
        float2 v0 = u2f(acc2[a][0]);
        float2 v1 = u2f(acc2[a][1]);
        float* dst = g_fc1p + ks * 65536 + (b0 + r0 + a) * 64 + o0;
        dst[0] = v0.x; dst[1] = v0.y; dst[2] = v1.x; dst[3] = v1.y;
    }
}

__global__ void bn3_kernel(const float* __restrict__ fc1b,
                           const float* __restrict__ gam, const float* __restrict__ bet) {
    __shared__ float rs[256], rq[256];
    int c = blockIdx.x;
    float bias = fc1b[c];
    float s = 0.f, ss = 0.f;
    for (int b = threadIdx.x; b < 1024; b += 256) {
        float v = bias;
#pragma unroll
        for (int k = 0; k < 8; k++) v += g_fc1p[k * 65536 + b * 64 + c];
        g_a1[b * 64 + c] = v;
        s += v; ss += v * v;
    }
    rs[threadIdx.x] = s; rq[threadIdx.x] = ss; __syncthreads();
    for (int st = 128; st; st >>= 1) {
        if (threadIdx.x < st) { rs[threadIdx.x] += rs[threadIdx.x + st]; rq[threadIdx.x] += rq[threadIdx.x + st]; }
        __syncthreads();
    }
    if (threadIdx.x == 0) {
        float mean = rs[0] / 1024.f;
        float var  = rq[0] / 1024.f - mean * mean;
        float sc   = gam[c] * rsqrtf(var + EPSBN);
        g_bn3p[2 * c + 0] = sc;
        g_bn3p[2 * c + 1] = bet[c] - mean * sc;
    }
}

__global__ void final_kernel(const float* __restrict__ w2, const float* __restrict__ b2,
                             float* __restrict__ out) {
    __shared__ float hm[64];
    int b = blockIdx.x, tid = threadIdx.x;
    float v = g_a1[b * 64 + tid];
    hm[tid] = fmaxf(fmaf(v, g_bn3p[2 * tid], g_bn3p[2 * tid + 1]), 0.f);
    __syncthreads();
    if (tid < 10) {
        float acc = b2[tid];
#pragma unroll
        for (int k = 0; k < 64; k++) acc = fmaf(hm[k], w2[tid * 64 + k], acc);
        out[b * 10 + tid] = acc;
    }
}

extern "C" void kernel_launch(void* const* d_in, const int* in_sizes, int n_in,
                              void* d_out, int out_size) {
    const float* x    = (const float*)d_in[0];
    const float* bw1  = (const float*)d_in[1];
    const float* sw1  = (const float*)d_in[2];
    const float* bn1g = (const float*)d_in[3];
    const float* bn1b = (const float*)d_in[4];
    const float* bw2  = (const float*)d_in[5];
    const float* sw2  = (const float*)d_in[6];
    const float* bn2g = (const float*)d_in[7];
    const float* bn2b = (const float*)d_in[8];
    const float* fc1w = (const float*)d_in[9];
    const float* fc1b = (const float*)d_in[10];
    const float* bn3g = (const float*)d_in[11];
    const float* bn3b = (const float*)d_in[12];
    const float* fc2w = (const float*)d_in[13];
    const float* fc2b = (const float*)d_in[14];
    float* out = (float*)d_out;

    wprep1_kernel<<<2, 256>>>(bw1, sw1);
    wprep2_kernel<<<48, 256>>>(bw2, sw2);
    feat1_kernel<<<12288, 256>>>(x);
    conv1_mma<<<7688, 256>>>();
    reduce1_kernel<<<dim3(64, 32), 256>>>();
    finalize_bn<<<32, 32>>>(0, bn1g, bn1b);
    pool1feat_kernel<<<28800, 256>>>();
    conv2_mma<<<1568, 256>>>();
    reduce2_kernel<<<dim3(16, 64), 256>>>();
    finalize_bn<<<64, 32>>>(1, bn2g, bn2b);
    pool2_kernel<<<12544, 256>>>();
    fc1_kernel<<<dim3(16, 8), 256>>>(fc1w);
    bn3_kernel<<<64, 256>>>(fc1b, bn3g, bn3b);
    final_kernel<<<1024, 64>>>(fc2w, fc2b, out);
}

// round 9
// speedup vs baseline: 1.8426x; 1.0322x over previous
#include <cuda_runtime.h>
#include <cuda_fp16.h>
#include <stdint.h>

#define EPSBN 1e-5f

// ---------------- device scratch ----------------
__device__ float  g_h1[31588352];          // [1024,32,964]
__device__ float  g_part1[32*64*2];
__device__ float  g_bn1p[64];
__device__ float  g_p1[7372800];           // pooled1 [1024,32,15,15]
__device__ float  g_h2[12845056];          // [1024,64,196]
__device__ float  g_part2[64*16*2];
__device__ float  g_bn2p[128];
__device__ float  g_p2[3211264];           // [1024,3136]
__device__ float  g_fc1p[8*65536];
__device__ float  g_a1[65536];
__device__ float  g_bn3p[128];
__device__ uint2  g_B1f0[512];             // conv1 B fragments fp16-hi
__device__ uint2  g_B1f1[512];             // fp16-lo
__device__ uint2  g_Bf0[12288];            // conv2 B fragments fp16-hi
__device__ uint2  g_Bf1[12288];            // fp16-lo

// ---------------- f32x2 packed math ----------------
__device__ __forceinline__ void fma2(unsigned long long &d, unsigned long long a, unsigned long long b) {
    asm("fma.rn.f32x2 %0, %1, %2, %3;" : "=l"(d) : "l"(a), "l"(b), "l"(d));
}
__device__ __forceinline__ unsigned long long pack2(float v) {
    unsigned long long r;
    asm("mov.b64 %0, {%1, %1};" : "=l"(r) : "r"(__float_as_uint(v)));
    return r;
}
__device__ __forceinline__ float2 u2f(unsigned long long u) {
    float2 f;
    f.x = __uint_as_float((unsigned)u);
    f.y = __uint_as_float((unsigned)(u >> 32));
    return f;
}

// ---------------- warp mma m16n8k16 fp16 -> f32 ----------------
__device__ __forceinline__ void mma16816(float* d, const uint32_t* a, uint2 b) {
    asm volatile("mma.sync.aligned.m16n8k16.row.col.f32.f16.f16.f32 "
        "{%0,%1,%2,%3}, {%4,%5,%6,%7}, {%8,%9}, {%0,%1,%2,%3};"
        : "+f"(d[0]), "+f"(d[1]), "+f"(d[2]), "+f"(d[3])
        : "r"(a[0]), "r"(a[1]), "r"(a[2]), "r"(a[3]), "r"(b.x), "r"(b.y));
}

// silu + 4 cubic B-spline bases on knots {-7,-5,...,7}
__device__ __forceinline__ void feats5(float v, float f[5]) {
    f[0] = v / (1.f + __expf(-v));
    float b[7];
#pragma unroll
    for (int j = 0; j < 7; j++) {
        float gj = 2.f * j - 7.f;
        b[j] = (v >= gj && v < gj + 2.f) ? 1.f : 0.f;
    }
#pragma unroll
    for (int p = 1; p <= 3; p++) {
        float inv = 1.f / (2.f * p);
#pragma unroll
        for (int j = 0; j < 7 - p; j++) {
            float gj = 2.f * j - 7.f;
            b[j] = ((v - gj) * b[j] + (gj + 2.f * (p + 1) - v) * b[j + 1]) * inv;
        }
    }
    f[1] = b[0]; f[2] = b[1]; f[3] = b[2]; f[4] = b[3];
}

// conv1 weights -> per-lane mma B fragments (K=60 padded to 64)
__global__ void wprep1_kernel(const float* __restrict__ wb1, const float* __restrict__ ws1) {
    int q = blockIdx.x * 256 + threadIdx.x;
    if (q >= 512) return;
    int lane = q & 31; int r = q >> 5;
    int n8t = r & 3; int ks = r >> 2;
    int gid = lane >> 2, tig = lane & 3;
    int n = n8t * 8 + gid;
    uint32_t h[2], l[2];
#pragma unroll
    for (int reg = 0; reg < 2; reg++) {
        uint32_t ph = 0, pl = 0;
#pragma unroll
        for (int e = 0; e < 2; e++) {
            int kk = ks * 16 + tig * 2 + reg * 8 + e;
            float w = 0.f;
            if (kk < 60) {
                int i = kk / 5, t = kk - i * 5;
                w = (t == 0) ? wb1[n * 12 + i] : ws1[(n * 12 + i) * 4 + (t - 1)];
            }
            half hh = __float2half_rn(w);
            half hl = __float2half_rn(w - __half2float(hh));
            ph |= (uint32_t)__half_as_ushort(hh) << (16 * e);
            pl |= (uint32_t)__half_as_ushort(hl) << (16 * e);
        }
        h[reg] = ph; l[reg] = pl;
    }
    g_B1f0[q] = make_uint2(h[0], h[1]);
    g_B1f1[q] = make_uint2(l[0], l[1]);
}

// conv2 weights -> per-lane mma B fragments
__global__ void wprep2_kernel(const float* __restrict__ wb2, const float* __restrict__ ws2) {
    int q = blockIdx.x * 256 + threadIdx.x;
    if (q >= 12288) return;
    int lane = q & 31; int r = q >> 5;
    int n8t = r & 7; r >>= 3;
    int ks = r % 3; int chunk = r / 3;
    int gid = lane >> 2, tig = lane & 3;
    int n = n8t * 8 + gid;
    uint32_t h[2], l[2];
#pragma unroll
    for (int reg = 0; reg < 2; reg++) {
        uint32_t ph = 0, pl = 0;
#pragma unroll
        for (int e = 0; e < 2; e++) {
            int kk = ks * 16 + tig * 2 + reg * 8 + e;
            float w = 0.f;
            if (kk < 40) {
                int kg = chunk * 40 + kk;
                int i = kg / 5, t = kg - i * 5;
                w = (t == 0) ? wb2[n * 128 + i] : ws2[(n * 128 + i) * 4 + (t - 1)];
            }
            half hh = __float2half_rn(w);
            half hl = __float2half_rn(w - __half2float(hh));
            ph |= (uint32_t)__half_as_ushort(hh) << (16 * e);
            pl |= (uint32_t)__half_as_ushort(hl) << (16 * e);
        }
        h[reg] = ph; l[reg] = pl;
    }
    g_Bf0[q] = make_uint2(h[0], h[1]);
    g_Bf1[q] = make_uint2(l[0], l[1]);
}

// conv1 via warp mma: M=128/block x N=32, K=60 (1 chunk of 64), fp16x3 split
// A tile row stride 66 halves (33 b32, odd -> conflict-free STS.16 and LDS.32)
__global__ __launch_bounds__(256) void conv1_mma(const float* __restrict__ x) {
    __shared__ __align__(16) half A0[128 * 66];
    __shared__ __align__(16) half A1[128 * 66];
    __shared__ int ipb[128];
    const int tid = threadIdx.x;
    const int m0 = blockIdx.x * 128;
    const int warp = tid >> 5, lane = tid & 31;
    const int wm = warp >> 1, wn = warp & 1;
    const int gid = lane >> 2, tig = lane & 3;

    if (tid < 128) {
        int m = m0 + tid;
        int bb = m / 961, r = m - bb * 961;
        int y = r / 31, xx = r - y * 31;
        ipb[tid] = ((bb * 3) * 32 + y) * 32 + xx;
    }
    if (tid < 256) {   // zero pad cols 60..63 per row on one tile each
        int pos = tid & 127, tile = tid >> 7;
        uint32_t* dst = tile ? (uint32_t*)A1 : (uint32_t*)A0;
        dst[33 * pos + 30] = 0u;
        dst[33 * pos + 31] = 0u;
    }
    __syncthreads();
    for (int q = tid; q < 1536; q += 256) {
        int pos = q & 127, ii = q >> 7;
        int c = ii >> 2, j = ii & 3;
        int pix = ipb[pos] + c * 1024 + ((j & 2) << 4) + (j & 1);
        float f[5]; feats5(x[pix], f);
        int base = pos * 66 + ii * 5;
#pragma unroll
        for (int t = 0; t < 5; t++) {
            half h = __float2half_rn(f[t]);
            A0[base + t] = h;
            A1[base + t] = __float2half_rn(f[t] - __half2float(h));
        }
    }
    __syncthreads();

    float d[2][2][4];
#pragma unroll
    for (int mh = 0; mh < 2; mh++)
#pragma unroll
        for (int j = 0; j < 2; j++)
#pragma unroll
            for (int e = 0; e < 4; e++) d[mh][j][e] = 0.f;

#pragma unroll
    for (int ks = 0; ks < 4; ks++) {
        uint32_t ah[2][4], al[2][4];
        int kw = ks * 8 + tig;
#pragma unroll
        for (int mh = 0; mh < 2; mh++) {
            int rlo = wm * 32 + mh * 16 + gid;
            const uint32_t* p0l = (const uint32_t*)(A0 + rlo * 66);
            const uint32_t* p0h = (const uint32_t*)(A0 + (rlo + 8) * 66);
            const uint32_t* p1l = (const uint32_t*)(A1 + rlo * 66);
            const uint32_t* p1h = (const uint32_t*)(A1 + (rlo + 8) * 66);
            ah[mh][0] = p0l[kw]; ah[mh][1] = p0h[kw]; ah[mh][2] = p0l[kw + 4]; ah[mh][3] = p0h[kw + 4];
            al[mh][0] = p1l[kw]; al[mh][1] = p1h[kw]; al[mh][2] = p1l[kw + 4]; al[mh][3] = p1h[kw + 4];
        }
#pragma unroll
        for (int j = 0; j < 2; j++) {
            int idx = (ks * 4 + wn * 2 + j) * 32 + lane;
            uint2 bh = g_B1f0[idx];
            uint2 bl = g_B1f1[idx];
#pragma unroll
            for (int mh = 0; mh < 2; mh++) {
                mma16816(d[mh][j], ah[mh], bh);
                mma16816(d[mh][j], ah[mh], bl);
                mma16816(d[mh][j], al[mh], bh);
            }
        }
    }
#pragma unroll
    for (int mh = 0; mh < 2; mh++) {
        int mlo = m0 + wm * 32 + mh * 16 + gid;
        int bb0 = mlo / 961, rr0 = mlo - bb0 * 961;
        int mhi = mlo + 8;
        int bb1 = mhi / 961, rr1 = mhi - bb1 * 961;
#pragma unroll
        for (int j = 0; j < 2; j++) {
            int n = (wn * 2 + j) * 8 + tig * 2;
            g_h1[(bb0 * 32 + n) * 964 + rr0]     = d[mh][j][0];
            g_h1[(bb0 * 32 + n + 1) * 964 + rr0] = d[mh][j][1];
            g_h1[(bb1 * 32 + n) * 964 + rr1]     = d[mh][j][2];
            g_h1[(bb1 * 32 + n + 1) * 964 + rr1] = d[mh][j][3];
        }
    }
}

__global__ void reduce1_kernel() {
    __shared__ float rs[256], rq[256];
    int c = blockIdx.y, b0 = blockIdx.x * 16;
    float s = 0.f, ss = 0.f;
    for (int b = b0; b < b0 + 16; b++) {
        const float4* p = (const float4*)(g_h1 + (b * 32 + c) * 964);
        for (int i = threadIdx.x; i < 241; i += 256) {
            float4 v = p[i];
            s  += (v.x + v.y) + (v.z + v.w);
            ss += (v.x * v.x + v.y * v.y) + (v.z * v.z + v.w * v.w);
        }
    }
    rs[threadIdx.x] = s; rq[threadIdx.x] = ss; __syncthreads();
    for (int st = 128; st; st >>= 1) {
        if (threadIdx.x < st) { rs[threadIdx.x] += rs[threadIdx.x + st]; rq[threadIdx.x] += rq[threadIdx.x + st]; }
        __syncthreads();
    }
    if (threadIdx.x == 0) {
        g_part1[(c * 64 + blockIdx.x) * 2 + 0] = rs[0];
        g_part1[(c * 64 + blockIdx.x) * 2 + 1] = rq[0];
    }
}

__global__ void reduce2_kernel() {
    __shared__ float rs[256], rq[256];
    int c = blockIdx.y, b0 = blockIdx.x * 64;
    float s = 0.f, ss = 0.f;
    for (int b = b0; b < b0 + 64; b++) {
        const float4* p = (const float4*)(g_h2 + (b * 64 + c) * 196);
        for (int i = threadIdx.x; i < 49; i += 256) {
            float4 v = p[i];
            s  += (v.x + v.y) + (v.z + v.w);
            ss += (v.x * v.x + v.y * v.y) + (v.z * v.z + v.w * v.w);
        }
    }
    rs[threadIdx.x] = s; rq[threadIdx.x] = ss; __syncthreads();
    for (int st = 128; st; st >>= 1) {
        if (threadIdx.x < st) { rs[threadIdx.x] += rs[threadIdx.x + st]; rq[threadIdx.x] += rq[threadIdx.x + st]; }
        __syncthreads();
    }
    if (threadIdx.x == 0) {
        g_part2[(c * 16 + blockIdx.x) * 2 + 0] = rs[0];
        g_part2[(c * 16 + blockIdx.x) * 2 + 1] = rq[0];
    }
}

__global__ void finalize_bn(int which, const float* __restrict__ gam, const float* __restrict__ bet) {
    int c = blockIdx.x;
    const float* part; float* out2; int nparts; float invc;
    if (which == 0) { part = g_part1; out2 = g_bn1p; nparts = 64; invc = 1.f / 984064.f; }
    else            { part = g_part2; out2 = g_bn2p; nparts = 16; invc = 1.f / 200704.f; }
    float s = 0.f, ss = 0.f;
    for (int i = threadIdx.x; i < nparts; i += 32) {
        s  += part[(c * nparts + i) * 2 + 0];
        ss += part[(c * nparts + i) * 2 + 1];
    }
#pragma unroll
    for (int off = 16; off; off >>= 1) {
        s  += __shfl_down_sync(0xffffffffu, s, off);
        ss += __shfl_down_sync(0xffffffffu, ss, off);
    }
    if (threadIdx.x == 0) {
        float mean = s * invc;
        float var  = ss * invc - mean * mean;
        float sc   = gam[c] * rsqrtf(var + EPSBN);
        out2[2 * c + 0] = sc;
        out2[2 * c + 1] = bet[c] - mean * sc;
    }
}

// bn1 + relu + maxpool -> compact pooled image
__global__ void pool1_kernel() {
    int idx = blockIdx.x * 256 + threadIdx.x;
    if (idx >= 7372800) return;
    int xo = idx % 15; int t1 = idx / 15;
    int yo = t1 % 15;  int t2 = t1 / 15;
    int c  = t2 & 31;  int b  = t2 >> 5;
    float sc = g_bn1p[2 * c], sh = g_bn1p[2 * c + 1];
    const float* p = g_h1 + (b * 32 + c) * 964 + (2 * yo) * 31 + 2 * xo;
    float m = fmaxf(fmaxf(p[0], p[1]), fmaxf(p[31], p[32]));
    g_p1[idx] = fmaxf(fmaf(m, sc, sh), 0.f);
}

// conv2 via warp mma: M=128/block x N=64, K=16 chunks x 48 (40 real), fp16x3 split
// A tile row stride 50 halves (25 b32, odd -> conflict-free)
__global__ __launch_bounds__(256) void conv2_mma() {
    __shared__ __align__(16) half A0[128 * 50];
    __shared__ __align__(16) half A1[128 * 50];
    __shared__ int ipb[128];
    const int tid = threadIdx.x;
    const int m0 = blockIdx.x * 128;
    const int warp = tid >> 5, lane = tid & 31;
    const int wm = warp >> 1, wn = warp & 1;
    const int gid = lane >> 2, tig = lane & 3;

    if (tid < 128) {
        int m = m0 + tid;
        int bb = m / 196, r = m - bb * 196;
        int y = r / 14, xx = r - y * 14;
        ipb[tid] = ((bb * 32) * 15 + y) * 15 + xx;
    }
    if (tid < 256) {   // zero pad cols 40..47 per row on one tile each
        int pos = tid & 127, tile = tid >> 7;
        uint32_t* dst = tile ? (uint32_t*)A1 : (uint32_t*)A0;
        int base = 25 * pos + 20;
        dst[base] = 0u; dst[base + 1] = 0u; dst[base + 2] = 0u; dst[base + 3] = 0u;
    }

    float d[2][4][4];
#pragma unroll
    for (int mh = 0; mh < 2; mh++)
#pragma unroll
        for (int j = 0; j < 4; j++)
#pragma unroll
            for (int e = 0; e < 4; e++) d[mh][j][e] = 0.f;

    for (int chunk = 0; chunk < 16; chunk++) {
        __syncthreads();
        for (int q = tid; q < 1024; q += 256) {
            int pos = q & 127, ii = q >> 7;
            int i = chunk * 8 + ii;
            int c = i >> 2, j = i & 3;
            int pix = ipb[pos] + c * 225 + (j >> 1) * 15 + (j & 1);
            float f[5]; feats5(g_p1[pix], f);
            int base = pos * 50 + ii * 5;
#pragma unroll
            for (int t = 0; t < 5; t++) {
                half h = __float2half_rn(f[t]);
                A0[base + t] = h;
                A1[base + t] = __float2half_rn(f[t] - __half2float(h));
            }
        }
        __syncthreads();
#pragma unroll
        for (int ks = 0; ks < 3; ks++) {
            uint32_t ah[2][4], al[2][4];
            int kw = ks * 8 + tig;
#pragma unroll
            for (int mh = 0; mh < 2; mh++) {
                int rlo = wm * 32 + mh * 16 + gid;
                const uint32_t* p0l = (const uint32_t*)(A0 + rlo * 50);
                const uint32_t* p0h = (const uint32_t*)(A0 + (rlo + 8) * 50);
                const uint32_t* p1l = (const uint32_t*)(A1 + rlo * 50);
                const uint32_t* p1h = (const uint32_t*)(A1 + (rlo + 8) * 50);
                ah[mh][0] = p0l[kw]; ah[mh][1] = p0h[kw]; ah[mh][2] = p0l[kw + 4]; ah[mh][3] = p0h[kw + 4];
                al[mh][0] = p1l[kw]; al[mh][1] = p1h[kw]; al[mh][2] = p1l[kw + 4]; al[mh][3] = p1h[kw + 4];
            }
#pragma unroll
            for (int j = 0; j < 4; j++) {
                int idx = ((chunk * 3 + ks) * 8 + wn * 4 + j) * 32 + lane;
                uint2 bh = g_Bf0[idx];
                uint2 bl = g_Bf1[idx];
#pragma unroll
                for (int mh = 0; mh < 2; mh++) {
                    mma16816(d[mh][j], ah[mh], bh);
                    mma16816(d[mh][j], ah[mh], bl);
                    mma16816(d[mh][j], al[mh], bh);
                }
            }
        }
    }
#pragma unroll
    for (int mh = 0; mh < 2; mh++) {
        int mlo = m0 + wm * 32 + mh * 16 + gid;
        int bb0 = mlo / 196, rr0 = mlo - bb0 * 196;
        int mhi = mlo + 8;
        int bb1 = mhi / 196, rr1 = mhi - bb1 * 196;
#pragma unroll
        for (int j = 0; j < 4; j++) {
            int n = (wn * 4 + j) * 8 + tig * 2;
            g_h2[(bb0 * 64 + n) * 196 + rr0]     = d[mh][j][0];
            g_h2[(bb0 * 64 + n + 1) * 196 + rr0] = d[mh][j][1];
            g_h2[(bb1 * 64 + n) * 196 + rr1]     = d[mh][j][2];
            g_h2[(bb1 * 64 + n + 1) * 196 + rr1] = d[mh][j][3];
        }
    }
}

__global__ void pool2_kernel() {
    int idx = blockIdx.x * 256 + threadIdx.x;
    if (idx >= 3211264) return;
    int xo = idx % 7; int t1 = idx / 7;
    int yo = t1 % 7;  int t2 = t1 / 7;
    int c  = t2 & 63;  int b  = t2 >> 6;
    float sc = g_bn2p[2 * c], sh = g_bn2p[2 * c + 1];
    const float* p = g_h2 + (b * 64 + c) * 196 + (2 * yo) * 14 + 2 * xo;
    float m = fmaxf(fmaxf(p[0], p[1]), fmaxf(p[14], p[15]));
    g_p2[idx] = fmaxf(fmaf(m, sc, sh), 0.f);
}

__global__ __launch_bounds__(256) void fc1_kernel(const float* __restrict__ w) {
    __shared__ __align__(16) float Xs[56][64];
    __shared__ __align__(16) float Ws[56][64];
    const int tid = threadIdx.x;
    const int b0 = blockIdx.x * 64;
    const int ks = blockIdx.y;
    const int o0 = (tid & 15) * 4, r0 = (tid >> 4) * 4;
    unsigned long long acc2[4][2];
#pragma unroll
    for (int a = 0; a < 4; a++) { acc2[a][0] = 0ull; acc2[a][1] = 0ull; }
    for (int cc = 0; cc < 7; cc++) {
        int k0 = ks * 392 + cc * 56;
        __syncthreads();
        for (int q = tid; q < 3584; q += 256) {
            int k = q / 64, rr = q & 63;
            Xs[k][rr] = g_p2[(b0 + rr) * 3136 + k0 + k];
            Ws[k][rr] = w[rr * 3136 + k0 + k];
        }
        __syncthreads();
#pragma unroll 8
        for (int k = 0; k < 56; k++) {
            float4 xv = *(const float4*)&Xs[k][r0];
            ulonglong2 wv = *(const ulonglong2*)&Ws[k][o0];
            float aa[4] = {xv.x, xv.y, xv.z, xv.w};
#pragma unroll
            for (int a = 0; a < 4; a++) {
                unsigned long long a2 = pack2(aa[a]);
                fma2(acc2[a][0], a2, wv.x);
                fma2(acc2[a][1], a2, wv.y);
            }
        }
    }
#pragma unroll
    for (int a = 0; a < 4; a++) {
        float2 v0 = u2f(acc2[a][0]);
        float2 v1 = u2f(acc2[a][1]);
        float* dst = g_fc1p + ks * 65536 + (b0 + r0 + a) * 64 + o0;
        dst[0] = v0.x; dst[1] = v0.y; dst[2] = v1.x; dst[3] = v1.y;
    }
}

__global__ void bn3_kernel(const float* __restrict__ fc1b,
                           const float* __restrict__ gam, const float* __restrict__ bet) {
    __shared__ float rs[256], rq[256];
    int c = blockIdx.x;
    float bias = fc1b[c];
    float s = 0.f, ss = 0.f;
    for (int b = threadIdx.x; b < 1024; b += 256) {
        float v = bias;
#pragma unroll
        for (int k = 0; k < 8; k++) v += g_fc1p[k * 65536 + b * 64 + c];
        g_a1[b * 64 + c] = v;
        s += v; ss += v * v;
    }
    rs[threadIdx.x] = s; rq[threadIdx.x] = ss; __syncthreads();
    for (int st = 128; st; st >>= 1) {
        if (threadIdx.x < st) { rs[threadIdx.x] += rs[threadIdx.x + st]; rq[threadIdx.x] += rq[threadIdx.x + st]; }
        __syncthreads();
    }
    if (threadIdx.x == 0) {
        float mean = rs[0] / 1024.f;
        float var  = rq[0] / 1024.f - mean * mean;
        float sc   = gam[c] * rsqrtf(var + EPSBN);
        g_bn3p[2 * c + 0] = sc;
        g_bn3p[2 * c + 1] = bet[c] - mean * sc;
    }
}

__global__ void final_kernel(const float* __restrict__ w2, const float* __restrict__ b2,
                             float* __restrict__ out) {
    __shared__ float hm[64];
    int b = blockIdx.x, tid = threadIdx.x;
    float v = g_a1[b * 64 + tid];
    hm[tid] = fmaxf(fmaf(v, g_bn3p[2 * tid], g_bn3p[2 * tid + 1]), 0.f);
    __syncthreads();
    if (tid < 10) {
        float acc = b2[tid];
#pragma unroll
        for (int k = 0; k < 64; k++) acc = fmaf(hm[k], w2[tid * 64 + k], acc);
        out[b * 10 + tid] = acc;
    }
}

extern "C" void kernel_launch(void* const* d_in, const int* in_sizes, int n_in,
                              void* d_out, int out_size) {
    const float* x    = (const float*)d_in[0];
    const float* bw1  = (const float*)d_in[1];
    const float* sw1  = (const float*)d_in[2];
    const float* bn1g = (const float*)d_in[3];
    const float* bn1b = (const float*)d_in[4];
    const float* bw2  = (const float*)d_in[5];
    const float* sw2  = (const float*)d_in[6];
    const float* bn2g = (const float*)d_in[7];
    const float* bn2b = (const float*)d_in[8];
    const float* fc1w = (const float*)d_in[9];
    const float* fc1b = (const float*)d_in[10];
    const float* bn3g = (const float*)d_in[11];
    const float* bn3b = (const float*)d_in[12];
    const float* fc2w = (const float*)d_in[13];
    const float* fc2b = (const float*)d_in[14];
    float* out = (float*)d_out;

    wprep1_kernel<<<2, 256>>>(bw1, sw1);
    wprep2_kernel<<<48, 256>>>(bw2, sw2);
    conv1_mma<<<7688, 256>>>(x);
    reduce1_kernel<<<dim3(64, 32), 256>>>();
    finalize_bn<<<32, 32>>>(0, bn1g, bn1b);
    pool1_kernel<<<28800, 256>>>();
    conv2_mma<<<1568, 256>>>();
    reduce2_kernel<<<dim3(16, 64), 256>>>();
    finalize_bn<<<64, 32>>>(1, bn2g, bn2b);
    pool2_kernel<<<12544, 256>>>();
    fc1_kernel<<<dim3(16, 8), 256>>>(fc1w);
    bn3_kernel<<<64, 256>>>(fc1b, bn3g, bn3b);
    final_kernel<<<1024, 64>>>(fc2w, fc2b, out);
}

// round 10
// speedup vs baseline: 1.8569x; 1.0078x over previous
#include <cuda_runtime.h>
#include <cuda_fp16.h>
#include <stdint.h>

#define EPSBN 1e-5f
#define NB1 7688
#define NB2 1568

// ---------------- device scratch ----------------
__device__ float  g_h1[31588352];          // [1024,32,964]
__device__ float  g_part1[32*NB1*2];
__device__ float  g_bn1p[64];
__device__ float  g_p1[7372800];           // pooled1 [1024,32,15,15]
__device__ float  g_h2[12845056];          // [1024,64,196]
__device__ float  g_part2[64*NB2*2];
__device__ float  g_bn2p[128];
__device__ float  g_p2[3211264];           // [1024,3136]
__device__ float  g_fc1p[16*65536];
__device__ float  g_a1[65536];
__device__ float  g_bn3p[128];
__device__ uint2  g_B1f0[512];
__device__ uint2  g_B1f1[512];
__device__ uint2  g_Bf0[12288];
__device__ uint2  g_Bf1[12288];

// ---------------- f32x2 packed math ----------------
__device__ __forceinline__ void fma2(unsigned long long &d, unsigned long long a, unsigned long long b) {
    asm("fma.rn.f32x2 %0, %1, %2, %3;" : "=l"(d) : "l"(a), "l"(b), "l"(d));
}
__device__ __forceinline__ unsigned long long pack2(float v) {
    unsigned long long r;
    asm("mov.b64 %0, {%1, %1};" : "=l"(r) : "r"(__float_as_uint(v)));
    return r;
}
__device__ __forceinline__ float2 u2f(unsigned long long u) {
    float2 f;
    f.x = __uint_as_float((unsigned)u);
    f.y = __uint_as_float((unsigned)(u >> 32));
    return f;
}

// ---------------- warp mma m16n8k16 fp16 -> f32 ----------------
__device__ __forceinline__ void mma16816(float* d, const uint32_t* a, uint2 b) {
    asm volatile("mma.sync.aligned.m16n8k16.row.col.f32.f16.f16.f32 "
        "{%0,%1,%2,%3}, {%4,%5,%6,%7}, {%8,%9}, {%0,%1,%2,%3};"
        : "+f"(d[0]), "+f"(d[1]), "+f"(d[2]), "+f"(d[3])
        : "r"(a[0]), "r"(a[1]), "r"(a[2]), "r"(a[3]), "r"(b.x), "r"(b.y));
}

// silu + 4 cubic B-spline bases on knots {-7,-5,...,7}
__device__ __forceinline__ void feats5(float v, float f[5]) {
    f[0] = v / (1.f + __expf(-v));
    float b[7];
#pragma unroll
    for (int j = 0; j < 7; j++) {
        float gj = 2.f * j - 7.f;
        b[j] = (v >= gj && v < gj + 2.f) ? 1.f : 0.f;
    }
#pragma unroll
    for (int p = 1; p <= 3; p++) {
        float inv = 1.f / (2.f * p);
#pragma unroll
        for (int j = 0; j < 7 - p; j++) {
            float gj = 2.f * j - 7.f;
            b[j] = ((v - gj) * b[j] + (gj + 2.f * (p + 1) - v) * b[j + 1]) * inv;
        }
    }
    f[1] = b[0]; f[2] = b[1]; f[3] = b[2]; f[4] = b[3];
}

__global__ void wprep1_kernel(const float* __restrict__ wb1, const float* __restrict__ ws1) {
    int q = blockIdx.x * 256 + threadIdx.x;
    if (q >= 512) return;
    int lane = q & 31; int r = q >> 5;
    int n8t = r & 3; int ks = r >> 2;
    int gid = lane >> 2, tig = lane & 3;
    int n = n8t * 8 + gid;
    uint32_t h[2], l[2];
#pragma unroll
    for (int reg = 0; reg < 2; reg++) {
        uint32_t ph = 0, pl = 0;
#pragma unroll
        for (int e = 0; e < 2; e++) {
            int kk = ks * 16 + tig * 2 + reg * 8 + e;
            float w = 0.f;
            if (kk < 60) {
                int i = kk / 5, t = kk - i * 5;
                w = (t == 0) ? wb1[n * 12 + i] : ws1[(n * 12 + i) * 4 + (t - 1)];
            }
            half hh = __float2half_rn(w);
            half hl = __float2half_rn(w - __half2float(hh));
            ph |= (uint32_t)__half_as_ushort(hh) << (16 * e);
            pl |= (uint32_t)__half_as_ushort(hl) << (16 * e);
        }
        h[reg] = ph; l[reg] = pl;
    }
    g_B1f0[q] = make_uint2(h[0], h[1]);
    g_B1f1[q] = make_uint2(l[0], l[1]);
}

__global__ void wprep2_kernel(const float* __restrict__ wb2, const float* __restrict__ ws2) {
    int q = blockIdx.x * 256 + threadIdx.x;
    if (q >= 12288) return;
    int lane = q & 31; int r = q >> 5;
    int n8t = r & 7; r >>= 3;
    int ks = r % 3; int chunk = r / 3;
    int gid = lane >> 2, tig = lane & 3;
    int n = n8t * 8 + gid;
    uint32_t h[2], l[2];
#pragma unroll
    for (int reg = 0; reg < 2; reg++) {
        uint32_t ph = 0, pl = 0;
#pragma unroll
        for (int e = 0; e < 2; e++) {
            int kk = ks * 16 + tig * 2 + reg * 8 + e;
            float w = 0.f;
            if (kk < 40) {
                int kg = chunk * 40 + kk;
                int i = kg / 5, t = kg - i * 5;
                w = (t == 0) ? wb2[n * 128 + i] : ws2[(n * 128 + i) * 4 + (t - 1)];
            }
            half hh = __float2half_rn(w);
            half hl = __float2half_rn(w - __half2float(hh));
            ph |= (uint32_t)__half_as_ushort(hh) << (16 * e);
            pl |= (uint32_t)__half_as_ushort(hl) << (16 * e);
        }
        h[reg] = ph; l[reg] = pl;
    }
    g_Bf0[q] = make_uint2(h[0], h[1]);
    g_Bf1[q] = make_uint2(l[0], l[1]);
}

// conv1 via warp mma + fused BN partials
__global__ __launch_bounds__(256) void conv1_mma(const float* __restrict__ x) {
    __shared__ __align__(16) half A0[128 * 66];
    __shared__ __align__(16) half A1[128 * 66];
    __shared__ int ipb[128];
    __shared__ float sstat[8][16][2];
    const int tid = threadIdx.x;
    const int m0 = blockIdx.x * 128;
    const int warp = tid >> 5, lane = tid & 31;
    const int wm = warp >> 1, wn = warp & 1;
    const int gid = lane >> 2, tig = lane & 3;

    if (tid < 128) {
        int m = m0 + tid;
        int bb = m / 961, r = m - bb * 961;
        int y = r / 31, xx = r - y * 31;
        ipb[tid] = ((bb * 3) * 32 + y) * 32 + xx;
    }
    {
        int pos = tid & 127, tile = tid >> 7;
        uint32_t* dst = tile ? (uint32_t*)A1 : (uint32_t*)A0;
        dst[33 * pos + 30] = 0u;
        dst[33 * pos + 31] = 0u;
    }
    __syncthreads();
    for (int q = tid; q < 1536; q += 256) {
        int pos = q & 127, ii = q >> 7;
        int c = ii >> 2, j = ii & 3;
        int pix = ipb[pos] + c * 1024 + ((j & 2) << 4) + (j & 1);
        float f[5]; feats5(x[pix], f);
        int base = pos * 66 + ii * 5;
#pragma unroll
        for (int t = 0; t < 5; t++) {
            half h = __float2half_rn(f[t]);
            A0[base + t] = h;
            A1[base + t] = __float2half_rn(f[t] - __half2float(h));
        }
    }
    __syncthreads();

    float d[2][2][4];
#pragma unroll
    for (int mh = 0; mh < 2; mh++)
#pragma unroll
        for (int j = 0; j < 2; j++)
#pragma unroll
            for (int e = 0; e < 4; e++) d[mh][j][e] = 0.f;

#pragma unroll
    for (int ks = 0; ks < 4; ks++) {
        uint32_t ah[2][4], al[2][4];
        int kw = ks * 8 + tig;
#pragma unroll
        for (int mh = 0; mh < 2; mh++) {
            int rlo = wm * 32 + mh * 16 + gid;
            const uint32_t* p0l = (const uint32_t*)(A0 + rlo * 66);
            const uint32_t* p0h = (const uint32_t*)(A0 + (rlo + 8) * 66);
            const uint32_t* p1l = (const uint32_t*)(A1 + rlo * 66);
            const uint32_t* p1h = (const uint32_t*)(A1 + (rlo + 8) * 66);
            ah[mh][0] = p0l[kw]; ah[mh][1] = p0h[kw]; ah[mh][2] = p0l[kw + 4]; ah[mh][3] = p0h[kw + 4];
            al[mh][0] = p1l[kw]; al[mh][1] = p1h[kw]; al[mh][2] = p1l[kw + 4]; al[mh][3] = p1h[kw + 4];
        }
#pragma unroll
        for (int j = 0; j < 2; j++) {
            int idx = (ks * 4 + wn * 2 + j) * 32 + lane;
            uint2 bh = g_B1f0[idx];
            uint2 bl = g_B1f1[idx];
#pragma unroll
            for (int mh = 0; mh < 2; mh++) {
                mma16816(d[mh][j], ah[mh], bh);
                mma16816(d[mh][j], ah[mh], bl);
                mma16816(d[mh][j], al[mh], bh);
            }
        }
    }
#pragma unroll
    for (int mh = 0; mh < 2; mh++) {
        int mlo = m0 + wm * 32 + mh * 16 + gid;
        int bb0 = mlo / 961, rr0 = mlo - bb0 * 961;
        int mhi = mlo + 8;
        int bb1 = mhi / 961, rr1 = mhi - bb1 * 961;
#pragma unroll
        for (int j = 0; j < 2; j++) {
            int n = (wn * 2 + j) * 8 + tig * 2;
            g_h1[(bb0 * 32 + n) * 964 + rr0]     = d[mh][j][0];
            g_h1[(bb0 * 32 + n + 1) * 964 + rr0] = d[mh][j][1];
            g_h1[(bb1 * 32 + n) * 964 + rr1]     = d[mh][j][2];
            g_h1[(bb1 * 32 + n + 1) * 964 + rr1] = d[mh][j][3];
        }
    }
    // fused BN partials: shuffle-reduce across gid, combine warps in smem
#pragma unroll
    for (int j = 0; j < 2; j++)
#pragma unroll
        for (int par = 0; par < 2; par++) {
            float a0 = d[0][j][par], a1 = d[0][j][par + 2];
            float a2 = d[1][j][par], a3 = d[1][j][par + 2];
            float s = (a0 + a1) + (a2 + a3);
            float q = (a0 * a0 + a1 * a1) + (a2 * a2 + a3 * a3);
#pragma unroll
            for (int off = 4; off < 32; off <<= 1) {
                s += __shfl_xor_sync(0xffffffffu, s, off);
                q += __shfl_xor_sync(0xffffffffu, q, off);
            }
            if (gid == 0) {
                int local = j * 8 + tig * 2 + par;
                sstat[warp][local][0] = s;
                sstat[warp][local][1] = q;
            }
        }
    __syncthreads();
    if (tid < 64) {
        int wn2 = tid >> 5, local = (tid >> 1) & 15, stat = tid & 1;
        float s = sstat[wn2][local][stat] + sstat[wn2 + 2][local][stat]
                + sstat[wn2 + 4][local][stat] + sstat[wn2 + 6][local][stat];
        int c = wn2 * 16 + local;
        g_part1[(c * NB1 + blockIdx.x) * 2 + stat] = s;
    }
}

__global__ void finalize_bn(int which, const float* __restrict__ gam, const float* __restrict__ bet) {
    __shared__ float rs[256], rq[256];
    int c = blockIdx.x;
    const float* part; float* out2; int nparts; float invc;
    if (which == 0) { part = g_part1; out2 = g_bn1p; nparts = NB1; invc = 1.f / 984064.f; }
    else            { part = g_part2; out2 = g_bn2p; nparts = NB2; invc = 1.f / 200704.f; }
    float s = 0.f, ss = 0.f;
    for (int i = threadIdx.x; i < nparts; i += 256) {
        s  += part[(c * nparts + i) * 2 + 0];
        ss += part[(c * nparts + i) * 2 + 1];
    }
    rs[threadIdx.x] = s; rq[threadIdx.x] = ss; __syncthreads();
    for (int st = 128; st; st >>= 1) {
        if (threadIdx.x < st) { rs[threadIdx.x] += rs[threadIdx.x + st]; rq[threadIdx.x] += rq[threadIdx.x + st]; }
        __syncthreads();
    }
    if (threadIdx.x == 0) {
        float mean = rs[0] * invc;
        float var  = rq[0] * invc - mean * mean;
        float sc   = gam[c] * rsqrtf(var + EPSBN);
        out2[2 * c + 0] = sc;
        out2[2 * c + 1] = bet[c] - mean * sc;
    }
}

__global__ void pool1_kernel() {
    int idx = blockIdx.x * 256 + threadIdx.x;
    if (idx >= 7372800) return;
    int xo = idx % 15; int t1 = idx / 15;
    int yo = t1 % 15;  int t2 = t1 / 15;
    int c  = t2 & 31;  int b  = t2 >> 5;
    float sc = g_bn1p[2 * c], sh = g_bn1p[2 * c + 1];
    const float* p = g_h1 + (b * 32 + c) * 964 + (2 * yo) * 31 + 2 * xo;
    float m = fmaxf(fmaxf(p[0], p[1]), fmaxf(p[31], p[32]));
    g_p1[idx] = fmaxf(fmaf(m, sc, sh), 0.f);
}

// conv2 via warp mma + fused BN partials
__global__ __launch_bounds__(256) void conv2_mma() {
    __shared__ __align__(16) half A0[128 * 50];
    __shared__ __align__(16) half A1[128 * 50];
    __shared__ int ipb[128];
    __shared__ float sstat[8][32][2];
    const int tid = threadIdx.x;
    const int m0 = blockIdx.x * 128;
    const int warp = tid >> 5, lane = tid & 31;
    const int wm = warp >> 1, wn = warp & 1;
    const int gid = lane >> 2, tig = lane & 3;

    if (tid < 128) {
        int m = m0 + tid;
        int bb = m / 196, r = m - bb * 196;
        int y = r / 14, xx = r - y * 14;
        ipb[tid] = ((bb * 32) * 15 + y) * 15 + xx;
    }
    {
        int pos = tid & 127, tile = tid >> 7;
        uint32_t* dst = tile ? (uint32_t*)A1 : (uint32_t*)A0;
        int base = 25 * pos + 20;
        dst[base] = 0u; dst[base + 1] = 0u; dst[base + 2] = 0u; dst[base + 3] = 0u;
    }

    float d[2][4][4];
#pragma unroll
    for (int mh = 0; mh < 2; mh++)
#pragma unroll
        for (int j = 0; j < 4; j++)
#pragma unroll
            for (int e = 0; e < 4; e++) d[mh][j][e] = 0.f;

    for (int chunk = 0; chunk < 16; chunk++) {
        __syncthreads();
        for (int q = tid; q < 1024; q += 256) {
            int pos = q & 127, ii = q >> 7;
            int i = chunk * 8 + ii;
            int c = i >> 2, j = i & 3;
            int pix = ipb[pos] + c * 225 + (j >> 1) * 15 + (j & 1);
            float f[5]; feats5(g_p1[pix], f);
            int base = pos * 50 + ii * 5;
#pragma unroll
            for (int t = 0; t < 5; t++) {
                half h = __float2half_rn(f[t]);
                A0[base + t] = h;
                A1[base + t] = __float2half_rn(f[t] - __half2float(h));
            }
        }
        __syncthreads();
#pragma unroll
        for (int ks = 0; ks < 3; ks++) {
            uint32_t ah[2][4], al[2][4];
            int kw = ks * 8 + tig;
#pragma unroll
            for (int mh = 0; mh < 2; mh++) {
                int rlo = wm * 32 + mh * 16 + gid;
                const uint32_t* p0l = (const uint32_t*)(A0 + rlo * 50);
                const uint32_t* p0h = (const uint32_t*)(A0 + (rlo + 8) * 50);
                const uint32_t* p1l = (const uint32_t*)(A1 + rlo * 50);
                const uint32_t* p1h = (const uint32_t*)(A1 + (rlo + 8) * 50);
                ah[mh][0] = p0l[kw]; ah[mh][1] = p0h[kw]; ah[mh][2] = p0l[kw + 4]; ah[mh][3] = p0h[kw + 4];
                al[mh][0] = p1l[kw]; al[mh][1] = p1h[kw]; al[mh][2] = p1l[kw + 4]; al[mh][3] = p1h[kw + 4];
            }
#pragma unroll
            for (int j = 0; j < 4; j++) {
                int idx = ((chunk * 3 + ks) * 8 + wn * 4 + j) * 32 + lane;
                uint2 bh = g_Bf0[idx];
                uint2 bl = g_Bf1[idx];
#pragma unroll
                for (int mh = 0; mh < 2; mh++) {
                    mma16816(d[mh][j], ah[mh], bh);
                    mma16816(d[mh][j], ah[mh], bl);
                    mma16816(d[mh][j], al[mh], bh);
                }
            }
        }
    }
#pragma unroll
    for (int mh = 0; mh < 2; mh++) {
        int mlo = m0 + wm * 32 + mh * 16 + gid;
        int bb0 = mlo / 196, rr0 = mlo - bb0 * 196;
        int mhi = mlo + 8;
        int bb1 = mhi / 196, rr1 = mhi - bb1 * 196;
#pragma unroll
        for (int j = 0; j < 4; j++) {
            int n = (wn * 4 + j) * 8 + tig * 2;
            g_h2[(bb0 * 64 + n) * 196 + rr0]     = d[mh][j][0];
            g_h2[(bb0 * 64 + n + 1) * 196 + rr0] = d[mh][j][1];
            g_h2[(bb1 * 64 + n) * 196 + rr1]     = d[mh][j][2];
            g_h2[(bb1 * 64 + n + 1) * 196 + rr1] = d[mh][j][3];
        }
    }
    // fused BN partials
#pragma unroll
    for (int j = 0; j < 4; j++)
#pragma unroll
        for (int par = 0; par < 2; par++) {
            float a0 = d[0][j][par], a1 = d[0][j][par + 2];
            float a2 = d[1][j][par], a3 = d[1][j][par + 2];
            float s = (a0 + a1) + (a2 + a3);
            float q = (a0 * a0 + a1 * a1) + (a2 * a2 + a3 * a3);
#pragma unroll
            for (int off = 4; off < 32; off <<= 1) {
                s += __shfl_xor_sync(0xffffffffu, s, off);
                q += __shfl_xor_sync(0xffffffffu, q, off);
            }
            if (gid == 0) {
                int local = j * 8 + tig * 2 + par;
                sstat[warp][local][0] = s;
                sstat[warp][local][1] = q;
            }
        }
    __syncthreads();
    if (tid < 128) {
        int wn2 = tid >> 6, local = (tid >> 1) & 31, stat = tid & 1;
        float s = sstat[wn2][local][stat] + sstat[wn2 + 2][local][stat]
                + sstat[wn2 + 4][local][stat] + sstat[wn2 + 6][local][stat];
        int c = wn2 * 32 + local;
        g_part2[(c * NB2 + blockIdx.x) * 2 + stat] = s;
    }
}

__global__ void pool2_kernel() {
    int idx = blockIdx.x * 256 + threadIdx.x;
    if (idx >= 3211264) return;
    int xo = idx % 7; int t1 = idx / 7;
    int yo = t1 % 7;  int t2 = t1 / 7;
    int c  = t2 & 63;  int b  = t2 >> 6;
    float sc = g_bn2p[2 * c], sh = g_bn2p[2 * c + 1];
    const float* p = g_h2 + (b * 64 + c) * 196 + (2 * yo) * 14 + 2 * xo;
    float m = fmaxf(fmaxf(p[0], p[1]), fmaxf(p[14], p[15]));
    g_p2[idx] = fmaxf(fmaf(m, sc, sh), 0.f);
}

// fc1: k-split 16 (196 k each, 4 chunks of 49)
__global__ __launch_bounds__(256) void fc1_kernel(const float* __restrict__ w) {
    __shared__ __align__(16) float Xs[49][64];
    __shared__ __align__(16) float Ws[49][64];
    const int tid = threadIdx.x;
    const int b0 = blockIdx.x * 64;
    const int ks = blockIdx.y;
    const int o0 = (tid & 15) * 4, r0 = (tid >> 4) * 4;
    unsigned long long acc2[4][2];
#pragma unroll
    for (int a = 0; a < 4; a++) { acc2[a][0] = 0ull; acc2[a][1] = 0ull; }
    for (int cc = 0; cc < 4; cc++) {
        int k0 = ks * 196 + cc * 49;
        __syncthreads();
        for (int q = tid; q < 3136; q += 256) {
            int k = q >> 6, rr = q & 63;
            Xs[k][rr] = g_p2[(b0 + rr) * 3136 + k0 + k];
            Ws[k][rr] = w[rr * 3136 + k0 + k];
        }
        __syncthreads();
#pragma unroll 7
        for (int k = 0; k < 49; k++) {
            float4 xv = *(const float4*)&Xs[k][r0];
            ulonglong2 wv = *(const ulonglong2*)&Ws[k][o0];
            float aa[4] = {xv.x, xv.y, xv.z, xv.w};
#pragma unroll
            for (int a = 0; a < 4; a++) {
                unsigned long long a2 = pack2(aa[a]);
                fma2(acc2[a][0], a2, wv.x);
                fma2(acc2[a][1], a2, wv.y);
            }
        }
    }
#pragma unroll
    for (int a = 0; a < 4; a++) {
        float2 v0 = u2f(acc2[a][0]);
        float2 v1 = u2f(acc2[a][1]);
        float* dst = g_fc1p + ks * 65536 + (b0 + r0 + a) * 64 + o0;
        dst[0] = v0.x; dst[1] = v0.y; dst[2] = v1.x; dst[3] = v1.y;
    }
}

__global__ void bn3_kernel(const float* __restrict__ fc1b,
                           const float* __restrict__ gam, const float* __restrict__ bet) {
    __shared__ float rs[256], rq[256];
    int c = blockIdx.x;
    float bias = fc1b[c];
    float s = 0.f, ss = 0.f;
    for (int b = threadIdx.x; b < 1024; b += 256) {
        float v = bias;
#pragma unroll
        for (int k = 0; k < 16; k++) v += g_fc1p[k * 65536 + b * 64 + c];
        g_a1[b * 64 + c] = v;
        s += v; ss += v * v;
    }
    rs[threadIdx.x] = s; rq[threadIdx.x] = ss; __syncthreads();
    for (int st = 128; st; st >>= 1) {
        if (threadIdx.x < st) { rs[threadIdx.x] += rs[threadIdx.x + st]; rq[threadIdx.x] += rq[threadIdx.x + st]; }
        __syncthreads();
    }
    if (threadIdx.x == 0) {
        float mean = rs[0] / 1024.f;
        float var  = rq[0] / 1024.f - mean * mean;
        float sc   = gam[c] * rsqrtf(var + EPSBN);
        g_bn3p[2 * c + 0] = sc;
        g_bn3p[2 * c + 1] = bet[c] - mean * sc;
    }
}

__global__ void final_kernel(const float* __restrict__ w2, const float* __restrict__ b2,
                             float* __restrict__ out) {
    __shared__ float hm[64];
    int b = blockIdx.x, tid = threadIdx.x;
    float v = g_a1[b * 64 + tid];
    hm[tid] = fmaxf(fmaf(v, g_bn3p[2 * tid], g_bn3p[2 * tid + 1]), 0.f);
    __syncthreads();
    if (tid < 10) {
        float acc = b2[tid];
#pragma unroll
        for (int k = 0; k < 64; k++) acc = fmaf(hm[k], w2[tid * 64 + k], acc);
        out[b * 10 + tid] = acc;
    }
}

extern "C" void kernel_launch(void* const* d_in, const int* in_sizes, int n_in,
                              void* d_out, int out_size) {
    const float* x    = (const float*)d_in[0];
    const float* bw1  = (const float*)d_in[1];
    const float* sw1  = (const float*)d_in[2];
    const float* bn1g = (const float*)d_in[3];
    const float* bn1b = (const float*)d_in[4];
    const float* bw2  = (const float*)d_in[5];
    const float* sw2  = (const float*)d_in[6];
    const float* bn2g = (const float*)d_in[7];
    const float* bn2b = (const float*)d_in[8];
    const float* fc1w = (const float*)d_in[9];
    const float* fc1b = (const float*)d_in[10];
    const float* bn3g = (const float*)d_in[11];
    const float* bn3b = (const float*)d_in[12];
    const float* fc2w = (const float*)d_in[13];
    const float* fc2b = (const float*)d_in[14];
    float* out = (float*)d_out;

    wprep1_kernel<<<2, 256>>>(bw1, sw1);
    wprep2_kernel<<<48, 256>>>(bw2, sw2);
    conv1_mma<<<NB1, 256>>>(x);
    finalize_bn<<<32, 256>>>(0, bn1g, bn1b);
    pool1_kernel<<<28800, 256>>>();
    conv2_mma<<<NB2, 256>>>();
    finalize_bn<<<64, 256>>>(1, bn2g, bn2b);
    pool2_kernel<<<12544, 256>>>();
    fc1_kernel<<<dim3(16, 16), 256>>>(fc1w);
    bn3_kernel<<<64, 256>>>(fc1b, bn3g, bn3b);
    final_kernel<<<1024, 64>>>(fc2w, fc2b, out);
}

// round 11
// speedup vs baseline: 1.9223x; 1.0352x over previous
#include <cuda_runtime.h>
#include <cuda_fp16.h>
#include <stdint.h>

#define EPSBN 1e-5f
#define NB1 7688
#define NB2 1568

// ---------------- device scratch ----------------
__device__ float  g_h1[32505856];          // [1024,32,31,32] rows padded
__device__ float  g_part1[32*NB1*2];
__device__ float  g_bn1p[64];
__device__ float  g_p1[7372800];           // pooled1 [1024,32,15,15]
__device__ float  g_h2[14680064];          // [1024,64,14,16] rows padded
__device__ float  g_part2[64*NB2*2];
__device__ float  g_bn2p[128];
__device__ float  g_p2[3211264];           // [1024,3136]
__device__ float  g_fc1p[16*65536];
__device__ float  g_a1[65536];
__device__ float  g_bn3p[128];
__device__ uint2  g_B1f0[640];             // conv1 B frags (5 ksteps)
__device__ uint2  g_B1f1[640];
__device__ uint2  g_Bf0[12288];
__device__ uint2  g_Bf1[12288];

// ---------------- f32x2 packed math ----------------
__device__ __forceinline__ void fma2(unsigned long long &d, unsigned long long a, unsigned long long b) {
    asm("fma.rn.f32x2 %0, %1, %2, %3;" : "=l"(d) : "l"(a), "l"(b), "l"(d));
}
__device__ __forceinline__ unsigned long long pack2(float v) {
    unsigned long long r;
    asm("mov.b64 %0, {%1, %1};" : "=l"(r) : "r"(__float_as_uint(v)));
    return r;
}
__device__ __forceinline__ float2 u2f(unsigned long long u) {
    float2 f;
    f.x = __uint_as_float((unsigned)u);
    f.y = __uint_as_float((unsigned)(u >> 32));
    return f;
}

__device__ __forceinline__ void mma16816(float* d, const uint32_t* a, uint2 b) {
    asm volatile("mma.sync.aligned.m16n8k16.row.col.f32.f16.f16.f32 "
        "{%0,%1,%2,%3}, {%4,%5,%6,%7}, {%8,%9}, {%0,%1,%2,%3};"
        : "+f"(d[0]), "+f"(d[1]), "+f"(d[2]), "+f"(d[3])
        : "r"(a[0]), "r"(a[1]), "r"(a[2]), "r"(a[3]), "r"(b.x), "r"(b.y));
}

__device__ __forceinline__ uint32_t packh(float a, float b) {
    half ha = __float2half_rn(a), hb = __float2half_rn(b);
    return (uint32_t)__half_as_ushort(ha) | ((uint32_t)__half_as_ushort(hb) << 16);
}

// silu + 4 cubic B-spline bases on knots {-7,-5,...,7}
__device__ __forceinline__ void feats5(float v, float f[5]) {
    f[0] = v / (1.f + __expf(-v));
    float b[7];
#pragma unroll
    for (int j = 0; j < 7; j++) {
        float gj = 2.f * j - 7.f;
        b[j] = (v >= gj && v < gj + 2.f) ? 1.f : 0.f;
    }
#pragma unroll
    for (int p = 1; p <= 3; p++) {
        float inv = 1.f / (2.f * p);
#pragma unroll
        for (int j = 0; j < 7 - p; j++) {
            float gj = 2.f * j - 7.f;
            b[j] = ((v - gj) * b[j] + (gj + 2.f * (p + 1) - v) * b[j + 1]) * inv;
        }
    }
    f[1] = b[0]; f[2] = b[1]; f[3] = b[2]; f[4] = b[3];
}

// conv1 weights, K mapped kk = i*6 + t (t<5), K=80 (5 ksteps), pad zero
__global__ void wprep1_kernel(const float* __restrict__ wb1, const float* __restrict__ ws1) {
    int q = blockIdx.x * 256 + threadIdx.x;
    if (q >= 640) return;
    int lane = q & 31; int r = q >> 5;
    int n8t = r & 3; int ks = r >> 2;   // ks 0..4
    int gid = lane >> 2, tig = lane & 3;
    int n = n8t * 8 + gid;
    uint32_t h[2], l[2];
#pragma unroll
    for (int reg = 0; reg < 2; reg++) {
        uint32_t ph = 0, pl = 0;
#pragma unroll
        for (int e = 0; e < 2; e++) {
            int kk = ks * 16 + tig * 2 + reg * 8 + e;
            int i = kk / 6, t = kk - i * 6;
            float w = 0.f;
            if (t < 5 && i < 12)
                w = (t == 0) ? wb1[n * 12 + i] : ws1[(n * 12 + i) * 4 + (t - 1)];
            half hh = __float2half_rn(w);
            half hl = __float2half_rn(w - __half2float(hh));
            ph |= (uint32_t)__half_as_ushort(hh) << (16 * e);
            pl |= (uint32_t)__half_as_ushort(hl) << (16 * e);
        }
        h[reg] = ph; l[reg] = pl;
    }
    g_B1f0[q] = make_uint2(h[0], h[1]);
    g_B1f1[q] = make_uint2(l[0], l[1]);
}

// conv2 weights, K mapped kk = i_local*6 + t (t<5), 48 cols = 3 ksteps
__global__ void wprep2_kernel(const float* __restrict__ wb2, const float* __restrict__ ws2) {
    int q = blockIdx.x * 256 + threadIdx.x;
    if (q >= 12288) return;
    int lane = q & 31; int r = q >> 5;
    int n8t = r & 7; r >>= 3;
    int ks = r % 3; int chunk = r / 3;
    int gid = lane >> 2, tig = lane & 3;
    int n = n8t * 8 + gid;
    uint32_t h[2], l[2];
#pragma unroll
    for (int reg = 0; reg < 2; reg++) {
        uint32_t ph = 0, pl = 0;
#pragma unroll
        for (int e = 0; e < 2; e++) {
            int kk = ks * 16 + tig * 2 + reg * 8 + e;    // 0..47
            int il = kk / 6, t = kk - il * 6;
            float w = 0.f;
            if (t < 5) {
                int i = chunk * 8 + il;
                w = (t == 0) ? wb2[n * 128 + i] : ws2[(n * 128 + i) * 4 + (t - 1)];
            }
            half hh = __float2half_rn(w);
            half hl = __float2half_rn(w - __half2float(hh));
            ph |= (uint32_t)__half_as_ushort(hh) << (16 * e);
            pl |= (uint32_t)__half_as_ushort(hl) << (16 * e);
        }
        h[reg] = ph; l[reg] = pl;
    }
    g_Bf0[q] = make_uint2(h[0], h[1]);
    g_Bf1[q] = make_uint2(l[0], l[1]);
}

// conv1 via warp mma + fused BN partials; A row stride 41 b32 (82 halves)
__global__ __launch_bounds__(256) void conv1_mma(const float* __restrict__ x) {
    __shared__ __align__(16) uint32_t A0[128 * 41];
    __shared__ __align__(16) uint32_t A1[128 * 41];
    __shared__ int ipb[128];
    __shared__ float sstat[8][16][2];
    const int tid = threadIdx.x;
    const int m0 = blockIdx.x * 128;
    const int warp = tid >> 5, lane = tid & 31;
    const int wm = warp >> 1, wn = warp & 1;
    const int gid = lane >> 2, tig = lane & 3;

    if (tid < 128) {
        int m = m0 + tid;
        int bb = m / 961, r = m - bb * 961;
        int y = r / 31, xx = r - y * 31;
        ipb[tid] = ((bb * 3) * 32 + y) * 32 + xx;
    }
    {   // zero pad cols 72..79 (b32 36..39) per row per tile
        int pos = tid & 127;
        uint32_t* dst = (tid >> 7) ? A1 : A0;
        int base = pos * 41 + 36;
        dst[base] = 0u; dst[base + 1] = 0u; dst[base + 2] = 0u; dst[base + 3] = 0u;
    }
    __syncthreads();
    for (int q = tid; q < 1536; q += 256) {
        int pos = q & 127, ii = q >> 7;
        int c = ii >> 2, j = ii & 3;
        int pix = ipb[pos] + c * 1024 + ((j & 2) << 4) + (j & 1);
        float f[5]; feats5(x[pix], f);
        float r0 = f[0] - __half2float(__float2half_rn(f[0]));
        float r1 = f[1] - __half2float(__float2half_rn(f[1]));
        float r2 = f[2] - __half2float(__float2half_rn(f[2]));
        float r3 = f[3] - __half2float(__float2half_rn(f[3]));
        float r4 = f[4] - __half2float(__float2half_rn(f[4]));
        int base = pos * 41 + ii * 3;
        A0[base + 0] = packh(f[0], f[1]);
        A0[base + 1] = packh(f[2], f[3]);
        A0[base + 2] = packh(f[4], 0.f);
        A1[base + 0] = packh(r0, r1);
        A1[base + 1] = packh(r2, r3);
        A1[base + 2] = packh(r4, 0.f);
    }
    __syncthreads();

    float d[2][2][4];
#pragma unroll
    for (int mh = 0; mh < 2; mh++)
#pragma unroll
        for (int j = 0; j < 2; j++)
#pragma unroll
            for (int e = 0; e < 4; e++) d[mh][j][e] = 0.f;

#pragma unroll
    for (int ks = 0; ks < 5; ks++) {
        uint32_t ah[2][4], al[2][4];
        int kw = ks * 8 + tig;
#pragma unroll
        for (int mh = 0; mh < 2; mh++) {
            int rlo = wm * 32 + mh * 16 + gid;
            const uint32_t* p0l = A0 + rlo * 41;
            const uint32_t* p0h = A0 + (rlo + 8) * 41;
            const uint32_t* p1l = A1 + rlo * 41;
            const uint32_t* p1h = A1 + (rlo + 8) * 41;
            ah[mh][0] = p0l[kw]; ah[mh][1] = p0h[kw]; ah[mh][2] = p0l[kw + 4]; ah[mh][3] = p0h[kw + 4];
            al[mh][0] = p1l[kw]; al[mh][1] = p1h[kw]; al[mh][2] = p1l[kw + 4]; al[mh][3] = p1h[kw + 4];
        }
#pragma unroll
        for (int j = 0; j < 2; j++) {
            int idx = (ks * 4 + wn * 2 + j) * 32 + lane;
            uint2 bh = g_B1f0[idx];
            uint2 bl = g_B1f1[idx];
#pragma unroll
            for (int mh = 0; mh < 2; mh++) {
                mma16816(d[mh][j], ah[mh], bh);
                mma16816(d[mh][j], ah[mh], bl);
                mma16816(d[mh][j], al[mh], bh);
            }
        }
    }
#pragma unroll
    for (int mh = 0; mh < 2; mh++) {
        int mlo = m0 + wm * 32 + mh * 16 + gid;
        int bb0 = mlo / 961, rr0 = mlo - bb0 * 961;
        int y0 = rr0 / 31, x0 = rr0 - y0 * 31;
        int mhi = mlo + 8;
        int bb1 = mhi / 961, rr1 = mhi - bb1 * 961;
        int y1 = rr1 / 31, x1 = rr1 - y1 * 31;
#pragma unroll
        for (int j = 0; j < 2; j++) {
            int n = (wn * 2 + j) * 8 + tig * 2;
            g_h1[(bb0 * 32 + n) * 992 + y0 * 32 + x0]     = d[mh][j][0];
            g_h1[(bb0 * 32 + n + 1) * 992 + y0 * 32 + x0] = d[mh][j][1];
            g_h1[(bb1 * 32 + n) * 992 + y1 * 32 + x1]     = d[mh][j][2];
            g_h1[(bb1 * 32 + n + 1) * 992 + y1 * 32 + x1] = d[mh][j][3];
        }
    }
#pragma unroll
    for (int j = 0; j < 2; j++)
#pragma unroll
        for (int par = 0; par < 2; par++) {
            float a0 = d[0][j][par], a1 = d[0][j][par + 2];
            float a2 = d[1][j][par], a3 = d[1][j][par + 2];
            float s = (a0 + a1) + (a2 + a3);
            float q = (a0 * a0 + a1 * a1) + (a2 * a2 + a3 * a3);
#pragma unroll
            for (int off = 4; off < 32; off <<= 1) {
                s += __shfl_xor_sync(0xffffffffu, s, off);
                q += __shfl_xor_sync(0xffffffffu, q, off);
            }
            if (gid == 0) {
                int local = j * 8 + tig * 2 + par;
                sstat[warp][local][0] = s;
                sstat[warp][local][1] = q;
            }
        }
    __syncthreads();
    if (tid < 64) {
        int wn2 = tid >> 5, local = (tid >> 1) & 15, stat = tid & 1;
        float s = sstat[wn2][local][stat] + sstat[wn2 + 2][local][stat]
                + sstat[wn2 + 4][local][stat] + sstat[wn2 + 6][local][stat];
        int c = wn2 * 16 + local;
        g_part1[(c * NB1 + blockIdx.x) * 2 + stat] = s;
    }
}

__global__ void finalize_bn(int which, const float* __restrict__ gam, const float* __restrict__ bet) {
    __shared__ float rs[256], rq[256];
    int c = blockIdx.x;
    const float* part; float* out2; int nparts; float invc;
    if (which == 0) { part = g_part1; out2 = g_bn1p; nparts = NB1; invc = 1.f / 984064.f; }
    else            { part = g_part2; out2 = g_bn2p; nparts = NB2; invc = 1.f / 200704.f; }
    float s = 0.f, ss = 0.f;
    for (int i = threadIdx.x; i < nparts; i += 256) {
        s  += part[(c * nparts + i) * 2 + 0];
        ss += part[(c * nparts + i) * 2 + 1];
    }
    rs[threadIdx.x] = s; rq[threadIdx.x] = ss; __syncthreads();
    for (int st = 128; st; st >>= 1) {
        if (threadIdx.x < st) { rs[threadIdx.x] += rs[threadIdx.x + st]; rq[threadIdx.x] += rq[threadIdx.x + st]; }
        __syncthreads();
    }
    if (threadIdx.x == 0) {
        float mean = rs[0] * invc;
        float var  = rq[0] * invc - mean * mean;
        float sc   = gam[c] * rsqrtf(var + EPSBN);
        out2[2 * c + 0] = sc;
        out2[2 * c + 1] = bet[c] - mean * sc;
    }
}

__global__ void pool1_kernel() {
    int idx = blockIdx.x * 256 + threadIdx.x;
    if (idx >= 7372800) return;
    int xo = idx % 15; int t1 = idx / 15;
    int yo = t1 % 15;  int t2 = t1 / 15;
    int c  = t2 & 31;  int b  = t2 >> 5;
    float sc = g_bn1p[2 * c], sh = g_bn1p[2 * c + 1];
    const float* p = g_h1 + (b * 32 + c) * 992 + (2 * yo) * 32 + 2 * xo;
    float2 r0 = *(const float2*)p;
    float2 r1 = *(const float2*)(p + 32);
    float m = fmaxf(fmaxf(r0.x, r0.y), fmaxf(r1.x, r1.y));
    g_p1[idx] = fmaxf(fmaf(m, sc, sh), 0.f);
}

// conv2 via warp mma + fused BN partials; A row stride 25 b32 (50 halves)
__global__ __launch_bounds__(256) void conv2_mma() {
    __shared__ __align__(16) uint32_t A0[128 * 25];
    __shared__ __align__(16) uint32_t A1[128 * 25];
    __shared__ int ipb[128];
    __shared__ float sstat[8][32][2];
    const int tid = threadIdx.x;
    const int m0 = blockIdx.x * 128;
    const int warp = tid >> 5, lane = tid & 31;
    const int wm = warp >> 1, wn = warp & 1;
    const int gid = lane >> 2, tig = lane & 3;

    if (tid < 128) {
        int m = m0 + tid;
        int bb = m / 196, r = m - bb * 196;
        int y = r / 14, xx = r - y * 14;
        ipb[tid] = ((bb * 32) * 15 + y) * 15 + xx;
    }

    float d[2][4][4];
#pragma unroll
    for (int mh = 0; mh < 2; mh++)
#pragma unroll
        for (int j = 0; j < 4; j++)
#pragma unroll
            for (int e = 0; e < 4; e++) d[mh][j][e] = 0.f;

    for (int chunk = 0; chunk < 16; chunk++) {
        __syncthreads();
        for (int q = tid; q < 1024; q += 256) {
            int pos = q & 127, ii = q >> 7;
            int i = chunk * 8 + ii;
            int c = i >> 2, j = i & 3;
            int pix = ipb[pos] + c * 225 + (j >> 1) * 15 + (j & 1);
            float f[5]; feats5(g_p1[pix], f);
            float r0 = f[0] - __half2float(__float2half_rn(f[0]));
            float r1 = f[1] - __half2float(__float2half_rn(f[1]));
            float r2 = f[2] - __half2float(__float2half_rn(f[2]));
            float r3 = f[3] - __half2float(__float2half_rn(f[3]));
            float r4 = f[4] - __half2float(__float2half_rn(f[4]));
            int base = pos * 25 + ii * 3;
            A0[base + 0] = packh(f[0], f[1]);
            A0[base + 1] = packh(f[2], f[3]);
            A0[base + 2] = packh(f[4], 0.f);
            A1[base + 0] = packh(r0, r1);
            A1[base + 1] = packh(r2, r3);
            A1[base + 2] = packh(r4, 0.f);
        }
        __syncthreads();
#pragma unroll
        for (int ks = 0; ks < 3; ks++) {
            uint32_t ah[2][4], al[2][4];
            int kw = ks * 8 + tig;
#pragma unroll
            for (int mh = 0; mh < 2; mh++) {
                int rlo = wm * 32 + mh * 16 + gid;
                const uint32_t* p0l = A0 + rlo * 25;
                const uint32_t* p0h = A0 + (rlo + 8) * 25;
                const uint32_t* p1l = A1 + rlo * 25;
                const uint32_t* p1h = A1 + (rlo + 8) * 25;
                ah[mh][0] = p0l[kw]; ah[mh][1] = p0h[kw]; ah[mh][2] = p0l[kw + 4]; ah[mh][3] = p0h[kw + 4];
                al[mh][0] = p1l[kw]; al[mh][1] = p1h[kw]; al[mh][2] = p1l[kw + 4]; al[mh][3] = p1h[kw + 4];
            }
#pragma unroll
            for (int j = 0; j < 4; j++) {
                int idx = ((chunk * 3 + ks) * 8 + wn * 4 + j) * 32 + lane;
                uint2 bh = g_Bf0[idx];
                uint2 bl = g_Bf1[idx];
#pragma unroll
                for (int mh = 0; mh < 2; mh++) {
                    mma16816(d[mh][j], ah[mh], bh);
                    mma16816(d[mh][j], ah[mh], bl);
                    mma16816(d[mh][j], al[mh], bh);
                }
            }
        }
    }
#pragma unroll
    for (int mh = 0; mh < 2; mh++) {
        int mlo = m0 + wm * 32 + mh * 16 + gid;
        int bb0 = mlo / 196, rr0 = mlo - bb0 * 196;
        int y0 = rr0 / 14, x0 = rr0 - y0 * 14;
        int mhi = mlo + 8;
        int bb1 = mhi / 196, rr1 = mhi - bb1 * 196;
        int y1 = rr1 / 14, x1 = rr1 - y1 * 14;
#pragma unroll
        for (int j = 0; j < 4; j++) {
            int n = (wn * 4 + j) * 8 + tig * 2;
            g_h2[(bb0 * 64 + n) * 224 + y0 * 16 + x0]     = d[mh][j][0];
            g_h2[(bb0 * 64 + n + 1) * 224 + y0 * 16 + x0] = d[mh][j][1];
            g_h2[(bb1 * 64 + n) * 224 + y1 * 16 + x1]     = d[mh][j][2];
            g_h2[(bb1 * 64 + n + 1) * 224 + y1 * 16 + x1] = d[mh][j][3];
        }
    }
#pragma unroll
    for (int j = 0; j < 4; j++)
#pragma unroll
        for (int par = 0; par < 2; par++) {
            float a0 = d[0][j][par], a1 = d[0][j][par + 2];
            float a2 = d[1][j][par], a3 = d[1][j][par + 2];
            float s = (a0 + a1) + (a2 + a3);
            float q = (a0 * a0 + a1 * a1) + (a2 * a2 + a3 * a3);
#pragma unroll
            for (int off = 4; off < 32; off <<= 1) {
                s += __shfl_xor_sync(0xffffffffu, s, off);
                q += __shfl_xor_sync(0xffffffffu, q, off);
            }
            if (gid == 0) {
                int local = j * 8 + tig * 2 + par;
                sstat[warp][local][0] = s;
                sstat[warp][local][1] = q;
            }
        }
    __syncthreads();
    if (tid < 128) {
        int wn2 = tid >> 6, local = (tid >> 1) & 31, stat = tid & 1;
        float s = sstat[wn2][local][stat] + sstat[wn2 + 2][local][stat]
                + sstat[wn2 + 4][local][stat] + sstat[wn2 + 6][local][stat];
        int c = wn2 * 32 + local;
        g_part2[(c * NB2 + blockIdx.x) * 2 + stat] = s;
    }
}

__global__ void pool2_kernel() {
    int idx = blockIdx.x * 256 + threadIdx.x;
    if (idx >= 3211264) return;
    int xo = idx % 7; int t1 = idx / 7;
    int yo = t1 % 7;  int t2 = t1 / 7;
    int c  = t2 & 63;  int b  = t2 >> 6;
    float sc = g_bn2p[2 * c], sh = g_bn2p[2 * c + 1];
    const float* p = g_h2 + (b * 64 + c) * 224 + (2 * yo) * 16 + 2 * xo;
    float2 r0 = *(const float2*)p;
    float2 r1 = *(const float2*)(p + 16);
    float m = fmaxf(fmaxf(r0.x, r0.y), fmaxf(r1.x, r1.y));
    g_p2[idx] = fmaxf(fmaf(m, sc, sh), 0.f);
}

// fc1: k-split 16 (196 k each, 4 chunks of 49)
__global__ __launch_bounds__(256) void fc1_kernel(const float* __restrict__ w) {
    __shared__ __align__(16) float Xs[49][64];
    __shared__ __align__(16) float Ws[49][64];
    const int tid = threadIdx.x;
    const int b0 = blockIdx.x * 64;
    const int ks = blockIdx.y;
    const int o0 = (tid & 15) * 4, r0 = (tid >> 4) * 4;
    unsigned long long acc2[4][2];
#pragma unroll
    for (int a = 0; a < 4; a++) { acc2[a][0] = 0ull; acc2[a][1] = 0ull; }
    for (int cc = 0; cc < 4; cc++) {
        int k0 = ks * 196 + cc * 49;
        __syncthreads();
        for (int q = tid; q < 3136; q += 256) {
            int k = q >> 6, rr = q & 63;
            Xs[k][rr] = g_p2[(b0 + rr) * 3136 + k0 + k];
            Ws[k][rr] = w[rr * 3136 + k0 + k];
        }
        __syncthreads();
#pragma unroll 7
        for (int k = 0; k < 49; k++) {
            float4 xv = *(const float4*)&Xs[k][r0];
            ulonglong2 wv = *(const ulonglong2*)&Ws[k][o0];
            float aa[4] = {xv.x, xv.y, xv.z, xv.w};
#pragma unroll
            for (int a = 0; a < 4; a++) {
                unsigned long long a2 = pack2(aa[a]);
                fma2(acc2[a][0], a2, wv.x);
                fma2(acc2[a][1], a2, wv.y);
            }
        }
    }
#pragma unroll
    for (int a = 0; a < 4; a++) {
        float2 v0 = u2f(acc2[a][0]);
        float2 v1 = u2f(acc2[a][1]);
        float* dst = g_fc1p + ks * 65536 + (b0 + r0 + a) * 64 + o0;
        dst[0] = v0.x; dst[1] = v0.y; dst[2] = v1.x; dst[3] = v1.y;
    }
}

__global__ void bn3_kernel(const float* __restrict__ fc1b,
                           const float* __restrict__ gam, const float* __restrict__ bet) {
    __shared__ float rs[256], rq[256];
    int c = blockIdx.x;
    float bias = fc1b[c];
    float s = 0.f, ss = 0.f;
    for (int b = threadIdx.x; b < 1024; b += 256) {
        float v = bias;
#pragma unroll
        for (int k = 0; k < 16; k++) v += g_fc1p[k * 65536 + b * 64 + c];
        g_a1[b * 64 + c] = v;
        s += v; ss += v * v;
    }
    rs[threadIdx.x] = s; rq[threadIdx.x] = ss; __syncthreads();
    for (int st = 128; st; st >>= 1) {
        if (threadIdx.x < st) { rs[threadIdx.x] += rs[threadIdx.x + st]; rq[threadIdx.x] += rq[threadIdx.x + st]; }
        __syncthreads();
    }
    if (threadIdx.x == 0) {
        float mean = rs[0] / 1024.f;
        float var  = rq[0] / 1024.f - mean * mean;
        float sc   = gam[c] * rsqrtf(var + EPSBN);
        g_bn3p[2 * c + 0] = sc;
        g_bn3p[2 * c + 1] = bet[c] - mean * sc;
    }
}

__global__ void final_kernel(const float* __restrict__ w2, const float* __restrict__ b2,
                             float* __restrict__ out) {
    __shared__ float hm[64];
    int b = blockIdx.x, tid = threadIdx.x;
    float v = g_a1[b * 64 + tid];
    hm[tid] = fmaxf(fmaf(v, g_bn3p[2 * tid], g_bn3p[2 * tid + 1]), 0.f);
    __syncthreads();
    if (tid < 10) {
        float acc = b2[tid];
#pragma unroll
        for (int k = 0; k < 64; k++) acc = fmaf(hm[k], w2[tid * 64 + k], acc);
        out[b * 10 + tid] = acc;
    }
}

extern "C" void kernel_launch(void* const* d_in, const int* in_sizes, int n_in,
                              void* d_out, int out_size) {
    const float* x    = (const float*)d_in[0];
    const float* bw1  = (const float*)d_in[1];
    const float* sw1  = (const float*)d_in[2];
    const float* bn1g = (const float*)d_in[3];
    const float* bn1b = (const float*)d_in[4];
    const float* bw2  = (const float*)d_in[5];
    const float* sw2  = (const float*)d_in[6];
    const float* bn2g = (const float*)d_in[7];
    const float* bn2b = (const float*)d_in[8];
    const float* fc1w = (const float*)d_in[9];
    const float* fc1b = (const float*)d_in[10];
    const float* bn3g = (const float*)d_in[11];
    const float* bn3b = (const float*)d_in[12];
    const float* fc2w = (const float*)d_in[13];
    const float* fc2b = (const float*)d_in[14];
    float* out = (float*)d_out;

    wprep1_kernel<<<3, 256>>>(bw1, sw1);
    wprep2_kernel<<<48, 256>>>(bw2, sw2);
    conv1_mma<<<NB1, 256>>>(x);
    finalize_bn<<<32, 256>>>(0, bn1g, bn1b);
    pool1_kernel<<<28800, 256>>>();
    conv2_mma<<<NB2, 256>>>();
    finalize_bn<<<64, 256>>>(1, bn2g, bn2b);
    pool2_kernel<<<12544, 256>>>();
    fc1_kernel<<<dim3(16, 16), 256>>>(fc1w);
    bn3_kernel<<<64, 256>>>(fc1b, bn3g, bn3b);
    final_kernel<<<1024, 64>>>(fc2w, fc2b, out);
}

// round 12
// speedup vs baseline: 2.0006x; 1.0407x over previous
#include <cuda_runtime.h>
#include <cuda_fp16.h>
#include <stdint.h>

#define EPSBN 1e-5f
#define NB1 7688
#define NB2 1568

// ---------------- device scratch ----------------
__device__ float  g_h1[32505856];          // [1024,32,31,32] rows padded
__device__ float  g_part1[32*NB1*2];
__device__ float  g_bn1p[64];
__device__ float  g_p1[7372800];           // pooled1 [1024,32,15,15]
__device__ float  g_h2[14680064];          // [1024,64,14,16] rows padded
__device__ float  g_part2[64*NB2*2];
__device__ float  g_bn2p[128];
__device__ float  g_p2[3211264];           // [1024,3136]
__device__ float  g_fc1p[16*65536];
__device__ float  g_a1[65536];
__device__ float  g_bn3p[128];
__device__ uint2  g_B1f0[640];             // conv1 B frags (5 ksteps)
__device__ uint2  g_B1f1[640];
__device__ uint2  g_Bf0[12288];
__device__ uint2  g_Bf1[12288];

// ---------------- f32x2 packed math ----------------
__device__ __forceinline__ void fma2(unsigned long long &d, unsigned long long a, unsigned long long b) {
    asm("fma.rn.f32x2 %0, %1, %2, %3;" : "=l"(d) : "l"(a), "l"(b), "l"(d));
}
__device__ __forceinline__ unsigned long long pack2(float v) {
    unsigned long long r;
    asm("mov.b64 %0, {%1, %1};" : "=l"(r) : "r"(__float_as_uint(v)));
    return r;
}
__device__ __forceinline__ float2 u2f(unsigned long long u) {
    float2 f;
    f.x = __uint_as_float((unsigned)u);
    f.y = __uint_as_float((unsigned)(u >> 32));
    return f;
}

__device__ __forceinline__ void mma16816(float* d, const uint32_t* a, uint2 b) {
    asm volatile("mma.sync.aligned.m16n8k16.row.col.f32.f16.f16.f32 "
        "{%0,%1,%2,%3}, {%4,%5,%6,%7}, {%8,%9}, {%0,%1,%2,%3};"
        : "+f"(d[0]), "+f"(d[1]), "+f"(d[2]), "+f"(d[3])
        : "r"(a[0]), "r"(a[1]), "r"(a[2]), "r"(a[3]), "r"(b.x), "r"(b.y));
}

__device__ __forceinline__ uint32_t packh(float a, float b) {
    half ha = __float2half_rn(a), hb = __float2half_rn(b);
    return (uint32_t)__half_as_ushort(ha) | ((uint32_t)__half_as_ushort(hb) << 16);
}

// silu + 4 cubic B-spline bases on uniform knots {-7,-5,...,7} — CLOSED FORM.
// Segment s = floor((v+7)/2), u in [0,1): bases B_j = w[j-s+3] with standard
// uniform cubic blending weights. Matches the Cox-de Boor recursion to ~ulp.
__device__ __forceinline__ void feats5(float v, float f[5]) {
    f[0] = v / (1.f + __expf(-v));
    float t = (v + 7.f) * 0.5f;
    float sf = floorf(t);
    int s = (int)sf;
    float u = t - sf;
    bool in = (v >= -7.f) && (v < 7.f);
    float u2 = u * u, u3 = u2 * u;
    float om = 1.f - u;
    const float i6 = 1.f / 6.f;
    float w[4];
    w[0] = om * om * om * i6;
    w[1] = (3.f * u3 - 6.f * u2 + 4.f) * i6;
    w[2] = (-3.f * u3 + 3.f * u2 + 3.f * u + 1.f) * i6;
    w[3] = u3 * i6;
#pragma unroll
    for (int j = 0; j < 4; j++) {
        int k = j - s + 3;
        float val = 0.f;
#pragma unroll
        for (int kk = 0; kk < 4; kk++) val = (k == kk) ? w[kk] : val;
        f[j + 1] = (in && k >= 0 && k < 4) ? val : 0.f;
    }
}

// conv1 weights, K mapped kk = i*6 + t (t<5), K=80 (5 ksteps), pad zero
__global__ void wprep1_kernel(const float* __restrict__ wb1, const float* __restrict__ ws1) {
    int q = blockIdx.x * 256 + threadIdx.x;
    if (q >= 640) return;
    int lane = q & 31; int r = q >> 5;
    int n8t = r & 3; int ks = r >> 2;
    int gid = lane >> 2, tig = lane & 3;
    int n = n8t * 8 + gid;
    uint32_t h[2], l[2];
#pragma unroll
    for (int reg = 0; reg < 2; reg++) {
        uint32_t ph = 0, pl = 0;
#pragma unroll
        for (int e = 0; e < 2; e++) {
            int kk = ks * 16 + tig * 2 + reg * 8 + e;
            int i = kk / 6, t = kk - i * 6;
            float w = 0.f;
            if (t < 5 && i < 12)
                w = (t == 0) ? wb1[n * 12 + i] : ws1[(n * 12 + i) * 4 + (t - 1)];
            half hh = __float2half_rn(w);
            half hl = __float2half_rn(w - __half2float(hh));
            ph |= (uint32_t)__half_as_ushort(hh) << (16 * e);
            pl |= (uint32_t)__half_as_ushort(hl) << (16 * e);
        }
        h[reg] = ph; l[reg] = pl;
    }
    g_B1f0[q] = make_uint2(h[0], h[1]);
    g_B1f1[q] = make_uint2(l[0], l[1]);
}

// conv2 weights, K mapped kk = i_local*6 + t (t<5), 48 cols = 3 ksteps
__global__ void wprep2_kernel(const float* __restrict__ wb2, const float* __restrict__ ws2) {
    int q = blockIdx.x * 256 + threadIdx.x;
    if (q >= 12288) return;
    int lane = q & 31; int r = q >> 5;
    int n8t = r & 7; r >>= 3;
    int ks = r % 3; int chunk = r / 3;
    int gid = lane >> 2, tig = lane & 3;
    int n = n8t * 8 + gid;
    uint32_t h[2], l[2];
#pragma unroll
    for (int reg = 0; reg < 2; reg++) {
        uint32_t ph = 0, pl = 0;
#pragma unroll
        for (int e = 0; e < 2; e++) {
            int kk = ks * 16 + tig * 2 + reg * 8 + e;
            int il = kk / 6, t = kk - il * 6;
            float w = 0.f;
            if (t < 5) {
                int i = chunk * 8 + il;
                w = (t == 0) ? wb2[n * 128 + i] : ws2[(n * 128 + i) * 4 + (t - 1)];
            }
            half hh = __float2half_rn(w);
            half hl = __float2half_rn(w - __half2float(hh));
            ph |= (uint32_t)__half_as_ushort(hh) << (16 * e);
            pl |= (uint32_t)__half_as_ushort(hl) << (16 * e);
        }
        h[reg] = ph; l[reg] = pl;
    }
    g_Bf0[q] = make_uint2(h[0], h[1]);
    g_Bf1[q] = make_uint2(l[0], l[1]);
}

// conv1 via warp mma + fused BN partials; A row stride 41 b32
__global__ __launch_bounds__(256) void conv1_mma(const float* __restrict__ x) {
    __shared__ __align__(16) uint32_t A0[128 * 41];
    __shared__ __align__(16) uint32_t A1[128 * 41];
    __shared__ int ipb[128];
    __shared__ float sstat[8][16][2];
    const int tid = threadIdx.x;
    const int m0 = blockIdx.x * 128;
    const int warp = tid >> 5, lane = tid & 31;
    const int wm = warp >> 1, wn = warp & 1;
    const int gid = lane >> 2, tig = lane & 3;

    if (tid < 128) {
        int m = m0 + tid;
        int bb = m / 961, r = m - bb * 961;
        int y = r / 31, xx = r - y * 31;
        ipb[tid] = ((bb * 3) * 32 + y) * 32 + xx;
    }
    {
        int pos = tid & 127;
        uint32_t* dst = (tid >> 7) ? A1 : A0;
        int base = pos * 41 + 36;
        dst[base] = 0u; dst[base + 1] = 0u; dst[base + 2] = 0u; dst[base + 3] = 0u;
    }
    __syncthreads();
    for (int q = tid; q < 1536; q += 256) {
        int pos = q & 127, ii = q >> 7;
        int c = ii >> 2, j = ii & 3;
        int pix = ipb[pos] + c * 1024 + ((j & 2) << 4) + (j & 1);
        float f[5]; feats5(x[pix], f);
        float r0 = f[0] - __half2float(__float2half_rn(f[0]));
        float r1 = f[1] - __half2float(__float2half_rn(f[1]));
        float r2 = f[2] - __half2float(__float2half_rn(f[2]));
        float r3 = f[3] - __half2float(__float2half_rn(f[3]));
        float r4 = f[4] - __half2float(__float2half_rn(f[4]));
        int base = pos * 41 + ii * 3;
        A0[base + 0] = packh(f[0], f[1]);
        A0[base + 1] = packh(f[2], f[3]);
        A0[base + 2] = packh(f[4], 0.f);
        A1[base + 0] = packh(r0, r1);
        A1[base + 1] = packh(r2, r3);
        A1[base + 2] = packh(r4, 0.f);
    }
    __syncthreads();

    float d[2][2][4];
#pragma unroll
    for (int mh = 0; mh < 2; mh++)
#pragma unroll
        for (int j = 0; j < 2; j++)
#pragma unroll
            for (int e = 0; e < 4; e++) d[mh][j][e] = 0.f;

#pragma unroll
    for (int ks = 0; ks < 5; ks++) {
        uint32_t ah[2][4], al[2][4];
        int kw = ks * 8 + tig;
#pragma unroll
        for (int mh = 0; mh < 2; mh++) {
            int rlo = wm * 32 + mh * 16 + gid;
            const uint32_t* p0l = A0 + rlo * 41;
            const uint32_t* p0h = A0 + (rlo + 8) * 41;
            const uint32_t* p1l = A1 + rlo * 41;
            const uint32_t* p1h = A1 + (rlo + 8) * 41;
            ah[mh][0] = p0l[kw]; ah[mh][1] = p0h[kw]; ah[mh][2] = p0l[kw + 4]; ah[mh][3] = p0h[kw + 4];
            al[mh][0] = p1l[kw]; al[mh][1] = p1h[kw]; al[mh][2] = p1l[kw + 4]; al[mh][3] = p1h[kw + 4];
        }
#pragma unroll
        for (int j = 0; j < 2; j++) {
            int idx = (ks * 4 + wn * 2 + j) * 32 + lane;
            uint2 bh = g_B1f0[idx];
            uint2 bl = g_B1f1[idx];
#pragma unroll
            for (int mh = 0; mh < 2; mh++) {
                mma16816(d[mh][j], ah[mh], bh);
                mma16816(d[mh][j], ah[mh], bl);
                mma16816(d[mh][j], al[mh], bh);
            }
        }
    }
#pragma unroll
    for (int mh = 0; mh < 2; mh++) {
        int mlo = m0 + wm * 32 + mh * 16 + gid;
        int bb0 = mlo / 961, rr0 = mlo - bb0 * 961;
        int y0 = rr0 / 31, x0 = rr0 - y0 * 31;
        int mhi = mlo + 8;
        int bb1 = mhi / 961, rr1 = mhi - bb1 * 961;
        int y1 = rr1 / 31, x1 = rr1 - y1 * 31;
#pragma unroll
        for (int j = 0; j < 2; j++) {
            int n = (wn * 2 + j) * 8 + tig * 2;
            g_h1[(bb0 * 32 + n) * 992 + y0 * 32 + x0]     = d[mh][j][0];
            g_h1[(bb0 * 32 + n + 1) * 992 + y0 * 32 + x0] = d[mh][j][1];
            g_h1[(bb1 * 32 + n) * 992 + y1 * 32 + x1]     = d[mh][j][2];
            g_h1[(bb1 * 32 + n + 1) * 992 + y1 * 32 + x1] = d[mh][j][3];
        }
    }
#pragma unroll
    for (int j = 0; j < 2; j++)
#pragma unroll
        for (int par = 0; par < 2; par++) {
            float a0 = d[0][j][par], a1 = d[0][j][par + 2];
            float a2 = d[1][j][par], a3 = d[1][j][par + 2];
            float s = (a0 + a1) + (a2 + a3);
            float q = (a0 * a0 + a1 * a1) + (a2 * a2 + a3 * a3);
#pragma unroll
            for (int off = 4; off < 32; off <<= 1) {
                s += __shfl_xor_sync(0xffffffffu, s, off);
                q += __shfl_xor_sync(0xffffffffu, q, off);
            }
            if (gid == 0) {
                int local = j * 8 + tig * 2 + par;
                sstat[warp][local][0] = s;
                sstat[warp][local][1] = q;
            }
        }
    __syncthreads();
    if (tid < 64) {
        int wn2 = tid >> 5, local = (tid >> 1) & 15, stat = tid & 1;
        float s = sstat[wn2][local][stat] + sstat[wn2 + 2][local][stat]
                + sstat[wn2 + 4][local][stat] + sstat[wn2 + 6][local][stat];
        int c = wn2 * 16 + local;
        g_part1[(c * NB1 + blockIdx.x) * 2 + stat] = s;
    }
}

__global__ void finalize_bn(int which, const float* __restrict__ gam, const float* __restrict__ bet) {
    __shared__ float rs[256], rq[256];
    int c = blockIdx.x;
    const float* part; float* out2; int nparts; float invc;
    if (which == 0) { part = g_part1; out2 = g_bn1p; nparts = NB1; invc = 1.f / 984064.f; }
    else            { part = g_part2; out2 = g_bn2p; nparts = NB2; invc = 1.f / 200704.f; }
    float s = 0.f, ss = 0.f;
    for (int i = threadIdx.x; i < nparts; i += 256) {
        s  += part[(c * nparts + i) * 2 + 0];
        ss += part[(c * nparts + i) * 2 + 1];
    }
    rs[threadIdx.x] = s; rq[threadIdx.x] = ss; __syncthreads();
    for (int st = 128; st; st >>= 1) {
        if (threadIdx.x < st) { rs[threadIdx.x] += rs[threadIdx.x + st]; rq[threadIdx.x] += rq[threadIdx.x + st]; }
        __syncthreads();
    }
    if (threadIdx.x == 0) {
        float mean = rs[0] * invc;
        float var  = rq[0] * invc - mean * mean;
        float sc   = gam[c] * rsqrtf(var + EPSBN);
        out2[2 * c + 0] = sc;
        out2[2 * c + 1] = bet[c] - mean * sc;
    }
}

__global__ void pool1_kernel() {
    int idx = blockIdx.x * 256 + threadIdx.x;
    if (idx >= 7372800) return;
    int xo = idx % 15; int t1 = idx / 15;
    int yo = t1 % 15;  int t2 = t1 / 15;
    int c  = t2 & 31;  int b  = t2 >> 5;
    float sc = g_bn1p[2 * c], sh = g_bn1p[2 * c + 1];
    const float* p = g_h1 + (b * 32 + c) * 992 + (2 * yo) * 32 + 2 * xo;
    float2 r0 = *(const float2*)p;
    float2 r1 = *(const float2*)(p + 32);
    float m = fmaxf(fmaxf(r0.x, r0.y), fmaxf(r1.x, r1.y));
    g_p1[idx] = fmaxf(fmaf(m, sc, sh), 0.f);
}

// conv2 via warp mma + fused BN partials; A row stride 25 b32
__global__ __launch_bounds__(256) void conv2_mma() {
    __shared__ __align__(16) uint32_t A0[128 * 25];
    __shared__ __align__(16) uint32_t A1[128 * 25];
    __shared__ int ipb[128];
    __shared__ float sstat[8][32][2];
    const int tid = threadIdx.x;
    const int m0 = blockIdx.x * 128;
    const int warp = tid >> 5, lane = tid & 31;
    const int wm = warp >> 1, wn = warp & 1;
    const int gid = lane >> 2, tig = lane & 3;

    if (tid < 128) {
        int m = m0 + tid;
        int bb = m / 196, r = m - bb * 196;
        int y = r / 14, xx = r - y * 14;
        ipb[tid] = ((bb * 32) * 15 + y) * 15 + xx;
    }

    float d[2][4][4];
#pragma unroll
    for (int mh = 0; mh < 2; mh++)
#pragma unroll
        for (int j = 0; j < 4; j++)
#pragma unroll
            for (int e = 0; e < 4; e++) d[mh][j][e] = 0.f;

    for (int chunk = 0; chunk < 16; chunk++) {
        __syncthreads();
        for (int q = tid; q < 1024; q += 256) {
            int pos = q & 127, ii = q >> 7;
            int i = chunk * 8 + ii;
            int c = i >> 2, j = i & 3;
            int pix = ipb[pos] + c * 225 + (j >> 1) * 15 + (j & 1);
            float f[5]; feats5(g_p1[pix], f);
            float r0 = f[0] - __half2float(__float2half_rn(f[0]));
            float r1 = f[1] - __half2float(__float2half_rn(f[1]));
            float r2 = f[2] - __half2float(__float2half_rn(f[2]));
            float r3 = f[3] - __half2float(__float2half_rn(f[3]));
            float r4 = f[4] - __half2float(__float2half_rn(f[4]));
            int base = pos * 25 + ii * 3;
            A0[base + 0] = packh(f[0], f[1]);
            A0[base + 1] = packh(f[2], f[3]);
            A0[base + 2] = packh(f[4], 0.f);
            A1[base + 0] = packh(r0, r1);
            A1[base + 1] = packh(r2, r3);
            A1[base + 2] = packh(r4, 0.f);
        }
        __syncthreads();
#pragma unroll
        for (int ks = 0; ks < 3; ks++) {
            uint32_t ah[2][4], al[2][4];
            int kw = ks * 8 + tig;
#pragma unroll
            for (int mh = 0; mh < 2; mh++) {
                int rlo = wm * 32 + mh * 16 + gid;
                const uint32_t* p0l = A0 + rlo * 25;
                const uint32_t* p0h = A0 + (rlo + 8) * 25;
                const uint32_t* p1l = A1 + rlo * 25;
                const uint32_t* p1h = A1 + (rlo + 8) * 25;
                ah[mh][0] = p0l[kw]; ah[mh][1] = p0h[kw]; ah[mh][2] = p0l[kw + 4]; ah[mh][3] = p0h[kw + 4];
                al[mh][0] = p1l[kw]; al[mh][1] = p1h[kw]; al[mh][2] = p1l[kw + 4]; al[mh][3] = p1h[kw + 4];
            }
#pragma unroll
            for (int j = 0; j < 4; j++) {
                int idx = ((chunk * 3 + ks) * 8 + wn * 4 + j) * 32 + lane;
                uint2 bh = g_Bf0[idx];
                uint2 bl = g_Bf1[idx];
#pragma unroll
                for (int mh = 0; mh < 2; mh++) {
                    mma16816(d[mh][j], ah[mh], bh);
                    mma16816(d[mh][j], ah[mh], bl);
                    mma16816(d[mh][j], al[mh], bh);
                }
            }
        }
    }
#pragma unroll
    for (int mh = 0; mh < 2; mh++) {
        int mlo = m0 + wm * 32 + mh * 16 + gid;
        int bb0 = mlo / 196, rr0 = mlo - bb0 * 196;
        int y0 = rr0 / 14, x0 = rr0 - y0 * 14;
        int mhi = mlo + 8;
        int bb1 = mhi / 196, rr1 = mhi - bb1 * 196;
        int y1 = rr1 / 14, x1 = rr1 - y1 * 14;
#pragma unroll
        for (int j = 0; j < 4; j++) {
            int n = (wn * 4 + j) * 8 + tig * 2;
            g_h2[(bb0 * 64 + n) * 224 + y0 * 16 + x0]     = d[mh][j][0];
            g_h2[(bb0 * 64 + n + 1) * 224 + y0 * 16 + x0] = d[mh][j][1];
            g_h2[(bb1 * 64 + n) * 224 + y1 * 16 + x1]     = d[mh][j][2];
            g_h2[(bb1 * 64 + n + 1) * 224 + y1 * 16 + x1] = d[mh][j][3];
        }
    }
#pragma unroll
    for (int j = 0; j < 4; j++)
#pragma unroll
        for (int par = 0; par < 2; par++) {
            float a0 = d[0][j][par], a1 = d[0][j][par + 2];
            float a2 = d[1][j][par], a3 = d[1][j][par + 2];
            float s = (a0 + a1) + (a2 + a3);
            float q = (a0 * a0 + a1 * a1) + (a2 * a2 + a3 * a3);
#pragma unroll
            for (int off = 4; off < 32; off <<= 1) {
                s += __shfl_xor_sync(0xffffffffu, s, off);
                q += __shfl_xor_sync(0xffffffffu, q, off);
            }
            if (gid == 0) {
                int local = j * 8 + tig * 2 + par;
                sstat[warp][local][0] = s;
                sstat[warp][local][1] = q;
            }
        }
    __syncthreads();
    if (tid < 128) {
        int wn2 = tid >> 6, local = (tid >> 1) & 31, stat = tid & 1;
        float s = sstat[wn2][local][stat] + sstat[wn2 + 2][local][stat]
                + sstat[wn2 + 4][local][stat] + sstat[wn2 + 6][local][stat];
        int c = wn2 * 32 + local;
        g_part2[(c * NB2 + blockIdx.x) * 2 + stat] = s;
    }
}

__global__ void pool2_kernel() {
    int idx = blockIdx.x * 256 + threadIdx.x;
    if (idx >= 3211264) return;
    int xo = idx % 7; int t1 = idx / 7;
    int yo = t1 % 7;  int t2 = t1 / 7;
    int c  = t2 & 63;  int b  = t2 >> 6;
    float sc = g_bn2p[2 * c], sh = g_bn2p[2 * c + 1];
    const float* p = g_h2 + (b * 64 + c) * 224 + (2 * yo) * 16 + 2 * xo;
    float2 r0 = *(const float2*)p;
    float2 r1 = *(const float2*)(p + 16);
    float m = fmaxf(fmaxf(r0.x, r0.y), fmaxf(r1.x, r1.y));
    g_p2[idx] = fmaxf(fmaf(m, sc, sh), 0.f);
}

// fc1: k-split 16 (196 k each, 4 chunks of 49)
__global__ __launch_bounds__(256) void fc1_kernel(const float* __restrict__ w) {
    __shared__ __align__(16) float Xs[49][64];
    __shared__ __align__(16) float Ws[49][64];
    const int tid = threadIdx.x;
    const int b0 = blockIdx.x * 64;
    const int ks = blockIdx.y;
    const int o0 = (tid & 15) * 4, r0 = (tid >> 4) * 4;
    unsigned long long acc2[4][2];
#pragma unroll
    for (int a = 0; a < 4; a++) { acc2[a][0] = 0ull; acc2[a][1] = 0ull; }
    for (int cc = 0; cc < 4; cc++) {
        int k0 = ks * 196 + cc * 49;
        __syncthreads();
        for (int q = tid; q < 3136; q += 256) {
            int k = q >> 6, rr = q & 63;
            Xs[k][rr] = g_p2[(b0 + rr) * 3136 + k0 + k];
            Ws[k][rr] = w[rr * 3136 + k0 + k];
        }
        __syncthreads();
#pragma unroll 7
        for (int k = 0; k < 49; k++) {
            float4 xv = *(const float4*)&Xs[k][r0];
            ulonglong2 wv = *(const ulonglong2*)&Ws[k][o0];
            float aa[4] = {xv.x, xv.y, xv.z, xv.w};
#pragma unroll
            for (int a = 0; a < 4; a++) {
                unsigned long long a2 = pack2(aa[a]);
                fma2(acc2[a][0], a2, wv.x);
                fma2(acc2[a][1], a2, wv.y);
            }
        }
    }
#pragma unroll
    for (int a = 0; a < 4; a++) {
        float2 v0 = u2f(acc2[a][0]);
        float2 v1 = u2f(acc2[a][1]);
        float* dst = g_fc1p + ks * 65536 + (b0 + r0 + a) * 64 + o0;
        dst[0] = v0.x; dst[1] = v0.y; dst[2] = v1.x; dst[3] = v1.y;
    }
}

__global__ void bn3_kernel(const float* __restrict__ fc1b,
                           const float* __restrict__ gam, const float* __restrict__ bet) {
    __shared__ float rs[256], rq[256];
    int c = blockIdx.x;
    float bias = fc1b[c];
    float s = 0.f, ss = 0.f;
    for (int b = threadIdx.x; b < 1024; b += 256) {
        float v = bias;
#pragma unroll
        for (int k = 0; k < 16; k++) v += g_fc1p[k * 65536 + b * 64 + c];
        g_a1[b * 64 + c] = v;
        s += v; ss += v * v;
    }
    rs[threadIdx.x] = s; rq[threadIdx.x] = ss; __syncthreads();
    for (int st = 128; st; st >>= 1) {
        if (threadIdx.x < st) { rs[threadIdx.x] += rs[threadIdx.x + st]; rq[threadIdx.x] += rq[threadIdx.x + st]; }
        __syncthreads();
    }
    if (threadIdx.x == 0) {
        float mean = rs[0] / 1024.f;
        float var  = rq[0] / 1024.f - mean * mean;
        float sc   = gam[c] * rsqrtf(var + EPSBN);
        g_bn3p[2 * c + 0] = sc;
        g_bn3p[2 * c + 1] = bet[c] - mean * sc;
    }
}

__global__ void final_kernel(const float* __restrict__ w2, const float* __restrict__ b2,
                             float* __restrict__ out) {
    __shared__ float hm[64];
    int b = blockIdx.x, tid = threadIdx.x;
    float v = g_a1[b * 64 + tid];
    hm[tid] = fmaxf(fmaf(v, g_bn3p[2 * tid], g_bn3p[2 * tid + 1]), 0.f);
    __syncthreads();
    if (tid < 10) {
        float acc = b2[tid];
#pragma unroll
        for (int k = 0; k < 64; k++) acc = fmaf(hm[k], w2[tid * 64 + k], acc);
        out[b * 10 + tid] = acc;
    }
}

extern "C" void kernel_launch(void* const* d_in, const int* in_sizes, int n_in,
                              void* d_out, int out_size) {
    const float* x    = (const float*)d_in[0];
    const float* bw1  = (const float*)d_in[1];
    const float* sw1  = (const float*)d_in[2];
    const float* bn1g = (const float*)d_in[3];
    const float* bn1b = (const float*)d_in[4];
    const float* bw2  = (const float*)d_in[5];
    const float* sw2  = (const float*)d_in[6];
    const float* bn2g = (const float*)d_in[7];
    const float* bn2b = (const float*)d_in[8];
    const float* fc1w = (const float*)d_in[9];
    const float* fc1b = (const float*)d_in[10];
    const float* bn3g = (const float*)d_in[11];
    const float* bn3b = (const float*)d_in[12];
    const float* fc2w = (const float*)d_in[13];
    const float* fc2b = (const float*)d_in[14];
    float* out = (float*)d_out;

    wprep1_kernel<<<3, 256>>>(bw1, sw1);
    wprep2_kernel<<<48, 256>>>(bw2, sw2);
    conv1_mma<<<NB1, 256>>>(x);
    finalize_bn<<<32, 256>>>(0, bn1g, bn1b);
    pool1_kernel<<<28800, 256>>>();
    conv2_mma<<<NB2, 256>>>();
    finalize_bn<<<64, 256>>>(1, bn2g, bn2b);
    pool2_kernel<<<12544, 256>>>();
    fc1_kernel<<<dim3(16, 16), 256>>>(fc1w);
    bn3_kernel<<<64, 256>>>(fc1b, bn3g, bn3b);
    final_kernel<<<1024, 64>>>(fc2w, fc2b, out);
}

// round 14
// speedup vs baseline: 2.0144x; 1.0069x over previous
#include <cuda_runtime.h>
#include <cuda_fp16.h>
#include <stdint.h>

#define EPSBN 1e-5f
#define NB1 7688
#define NB2 1568

// ---------------- device scratch ----------------
__device__ float  g_h1[32505856];          // [1024,32,31,32] rows padded
__device__ float  g_part1[32*NB1*2];
__device__ float  g_bn1p[64];
__device__ float  g_p1[7372800];           // pooled1 [1024,32,15,15]
__device__ float  g_h2[14680064];          // [1024,64,14,16] rows padded
__device__ float  g_part2[64*NB2*2];
__device__ float  g_bn2p[128];
__device__ float  g_p2[3211264];           // [1024,3136]
__device__ float  g_fc1p[7*65536];
__device__ float  g_a1[65536];
__device__ float  g_bn3p[128];
__device__ uint2  g_B1f0[640];
__device__ uint2  g_B1f1[640];
__device__ uint2  g_Bf0[12288];
__device__ uint2  g_Bf1[12288];
__device__ uint2  g_Wf0[50176];            // fc1 B frags hi: [chunk49][ks4][n8t8][lane32]
__device__ uint2  g_Wf1[50176];            // lo

__device__ __forceinline__ void mma16816(float* d, const uint32_t* a, uint2 b) {
    asm volatile("mma.sync.aligned.m16n8k16.row.col.f32.f16.f16.f32 "
        "{%0,%1,%2,%3}, {%4,%5,%6,%7}, {%8,%9}, {%0,%1,%2,%3};"
        : "+f"(d[0]), "+f"(d[1]), "+f"(d[2]), "+f"(d[3])
        : "r"(a[0]), "r"(a[1]), "r"(a[2]), "r"(a[3]), "r"(b.x), "r"(b.y));
}

__device__ __forceinline__ uint32_t packh(float a, float b) {
    half ha = __float2half_rn(a), hb = __float2half_rn(b);
    return (uint32_t)__half_as_ushort(ha) | ((uint32_t)__half_as_ushort(hb) << 16);
}

// silu + 4 cubic B-spline bases on uniform knots {-7,-5,...,7} — closed form
__device__ __forceinline__ void feats5(float v, float f[5]) {
    f[0] = v / (1.f + __expf(-v));
    float t = (v + 7.f) * 0.5f;
    float sf = floorf(t);
    int s = (int)sf;
    float u = t - sf;
    bool in = (v >= -7.f) && (v < 7.f);
    float u2 = u * u, u3 = u2 * u;
    float om = 1.f - u;
    const float i6 = 1.f / 6.f;
    float w[4];
    w[0] = om * om * om * i6;
    w[1] = (3.f * u3 - 6.f * u2 + 4.f) * i6;
    w[2] = (-3.f * u3 + 3.f * u2 + 3.f * u + 1.f) * i6;
    w[3] = u3 * i6;
#pragma unroll
    for (int j = 0; j < 4; j++) {
        int k = j - s + 3;
        float val = 0.f;
#pragma unroll
        for (int kk = 0; kk < 4; kk++) val = (k == kk) ? w[kk] : val;
        f[j + 1] = (in && k >= 0 && k < 4) ? val : 0.f;
    }
}

// conv1 weights, K mapped kk = i*6 + t (t<5), K=80 (5 ksteps)
__global__ void wprep1_kernel(const float* __restrict__ wb1, const float* __restrict__ ws1) {
    int q = blockIdx.x * 256 + threadIdx.x;
    if (q >= 640) return;
    int lane = q & 31; int r = q >> 5;
    int n8t = r & 3; int ks = r >> 2;
    int gid = lane >> 2, tig = lane & 3;
    int n = n8t * 8 + gid;
    uint32_t h[2], l[2];
#pragma unroll
    for (int reg = 0; reg < 2; reg++) {
        uint32_t ph = 0, pl = 0;
#pragma unroll
        for (int e = 0; e < 2; e++) {
            int kk = ks * 16 + tig * 2 + reg * 8 + e;
            int i = kk / 6, t = kk - i * 6;
            float w = 0.f;
            if (t < 5 && i < 12)
                w = (t == 0) ? wb1[n * 12 + i] : ws1[(n * 12 + i) * 4 + (t - 1)];
            half hh = __float2half_rn(w);
            half hl = __float2half_rn(w - __half2float(hh));
            ph |= (uint32_t)__half_as_ushort(hh) << (16 * e);
            pl |= (uint32_t)__half_as_ushort(hl) << (16 * e);
        }
        h[reg] = ph; l[reg] = pl;
    }
    g_B1f0[q] = make_uint2(h[0], h[1]);
    g_B1f1[q] = make_uint2(l[0], l[1]);
}

// conv2 weights, kk = i_local*6 + t, 48 cols = 3 ksteps
__global__ void wprep2_kernel(const float* __restrict__ wb2, const float* __restrict__ ws2) {
    int q = blockIdx.x * 256 + threadIdx.x;
    if (q >= 12288) return;
    int lane = q & 31; int r = q >> 5;
    int n8t = r & 7; r >>= 3;
    int ks = r % 3; int chunk = r / 3;
    int gid = lane >> 2, tig = lane & 3;
    int n = n8t * 8 + gid;
    uint32_t h[2], l[2];
#pragma unroll
    for (int reg = 0; reg < 2; reg++) {
        uint32_t ph = 0, pl = 0;
#pragma unroll
        for (int e = 0; e < 2; e++) {
            int kk = ks * 16 + tig * 2 + reg * 8 + e;
            int il = kk / 6, t = kk - il * 6;
            float w = 0.f;
            if (t < 5) {
                int i = chunk * 8 + il;
                w = (t == 0) ? wb2[n * 128 + i] : ws2[(n * 128 + i) * 4 + (t - 1)];
            }
            half hh = __float2half_rn(w);
            half hl = __float2half_rn(w - __half2float(hh));
            ph |= (uint32_t)__half_as_ushort(hh) << (16 * e);
            pl |= (uint32_t)__half_as_ushort(hl) << (16 * e);
        }
        h[reg] = ph; l[reg] = pl;
    }
    g_Bf0[q] = make_uint2(h[0], h[1]);
    g_Bf1[q] = make_uint2(l[0], l[1]);
}

// fc1 weights -> frags: q = ((chunk*4+ks)*8+n8t)*32+lane
__global__ void wprepf_kernel(const float* __restrict__ w) {
    int q = blockIdx.x * 256 + threadIdx.x;
    if (q >= 50176) return;
    int lane = q & 31; int r = q >> 5;
    int n8t = r & 7; r >>= 3;
    int ks = r & 3; int chunk = r >> 2;
    int gid = lane >> 2, tig = lane & 3;
    int n = n8t * 8 + gid;
    uint32_t h[2], l[2];
#pragma unroll
    for (int reg = 0; reg < 2; reg++) {
        uint32_t ph = 0, pl = 0;
#pragma unroll
        for (int e = 0; e < 2; e++) {
            int k = chunk * 64 + ks * 16 + tig * 2 + reg * 8 + e;
            float wv = w[n * 3136 + k];
            half hh = __float2half_rn(wv);
            half hl = __float2half_rn(wv - __half2float(hh));
            ph |= (uint32_t)__half_as_ushort(hh) << (16 * e);
            pl |= (uint32_t)__half_as_ushort(hl) << (16 * e);
        }
        h[reg] = ph; l[reg] = pl;
    }
    g_Wf0[q] = make_uint2(h[0], h[1]);
    g_Wf1[q] = make_uint2(l[0], l[1]);
}

// conv1 via warp mma + fused BN partials
__global__ __launch_bounds__(256) void conv1_mma(const float* __restrict__ x) {
    __shared__ __align__(16) uint32_t A0[128 * 41];
    __shared__ __align__(16) uint32_t A1[128 * 41];
    __shared__ int ipb[128];
    __shared__ float sstat[8][16][2];
    const int tid = threadIdx.x;
    const int m0 = blockIdx.x * 128;
    const int warp = tid >> 5, lane = tid & 31;
    const int wm = warp >> 1, wn = warp & 1;
    const int gid = lane >> 2, tig = lane & 3;

    if (tid < 128) {
        int m = m0 + tid;
        int bb = m / 961, r = m - bb * 961;
        int y = r / 31, xx = r - y * 31;
        ipb[tid] = ((bb * 3) * 32 + y) * 32 + xx;
    }
    {
        int pos = tid & 127;
        uint32_t* dst = (tid >> 7) ? A1 : A0;
        int base = pos * 41 + 36;
        dst[base] = 0u; dst[base + 1] = 0u; dst[base + 2] = 0u; dst[base + 3] = 0u;
    }
    __syncthreads();
    for (int q = tid; q < 1536; q += 256) {
        int pos = q & 127, ii = q >> 7;
        int c = ii >> 2, j = ii & 3;
        int pix = ipb[pos] + c * 1024 + ((j & 2) << 4) + (j & 1);
        float f[5]; feats5(x[pix], f);
        float r0 = f[0] - __half2float(__float2half_rn(f[0]));
        float r1 = f[1] - __half2float(__float2half_rn(f[1]));
        float r2 = f[2] - __half2float(__float2half_rn(f[2]));
        float r3 = f[3] - __half2float(__float2half_rn(f[3]));
        float r4 = f[4] - __half2float(__float2half_rn(f[4]));
        int base = pos * 41 + ii * 3;
        A0[base + 0] = packh(f[0], f[1]);
        A0[base + 1] = packh(f[2], f[3]);
        A0[base + 2] = packh(f[4], 0.f);
        A1[base + 0] = packh(r0, r1);
        A1[base + 1] = packh(r2, r3);
        A1[base + 2] = packh(r4, 0.f);
    }
    __syncthreads();

    float d[2][2][4];
#pragma unroll
    for (int mh = 0; mh < 2; mh++)
#pragma unroll
        for (int j = 0; j < 2; j++)
#pragma unroll
            for (int e = 0; e < 4; e++) d[mh][j][e] = 0.f;

#pragma unroll
    for (int ks = 0; ks < 5; ks++) {
        uint32_t ah[2][4], al[2][4];
        int kw = ks * 8 + tig;
#pragma unroll
        for (int mh = 0; mh < 2; mh++) {
            int rlo = wm * 32 + mh * 16 + gid;
            const uint32_t* p0l = A0 + rlo * 41;
            const uint32_t* p0h = A0 + (rlo + 8) * 41;
            const uint32_t* p1l = A1 + rlo * 41;
            const uint32_t* p1h = A1 + (rlo + 8) * 41;
            ah[mh][0] = p0l[kw]; ah[mh][1] = p0h[kw]; ah[mh][2] = p0l[kw + 4]; ah[mh][3] = p0h[kw + 4];
            al[mh][0] = p1l[kw]; al[mh][1] = p1h[kw]; al[mh][2] = p1l[kw + 4]; al[mh][3] = p1h[kw + 4];
        }
#pragma unroll
        for (int j = 0; j < 2; j++) {
            int idx = (ks * 4 + wn * 2 + j) * 32 + lane;
            uint2 bh = g_B1f0[idx];
            uint2 bl = g_B1f1[idx];
#pragma unroll
            for (int mh = 0; mh < 2; mh++) {
                mma16816(d[mh][j], ah[mh], bh);
                mma16816(d[mh][j], ah[mh], bl);
                mma16816(d[mh][j], al[mh], bh);
            }
        }
    }
#pragma unroll
    for (int mh = 0; mh < 2; mh++) {
        int mlo = m0 + wm * 32 + mh * 16 + gid;
        int bb0 = mlo / 961, rr0 = mlo - bb0 * 961;
        int y0 = rr0 / 31, x0 = rr0 - y0 * 31;
        int mhi = mlo + 8;
        int bb1 = mhi / 961, rr1 = mhi - bb1 * 961;
        int y1 = rr1 / 31, x1 = rr1 - y1 * 31;
#pragma unroll
        for (int j = 0; j < 2; j++) {
            int n = (wn * 2 + j) * 8 + tig * 2;
            g_h1[(bb0 * 32 + n) * 992 + y0 * 32 + x0]     = d[mh][j][0];
            g_h1[(bb0 * 32 + n + 1) * 992 + y0 * 32 + x0] = d[mh][j][1];
            g_h1[(bb1 * 32 + n) * 992 + y1 * 32 + x1]     = d[mh][j][2];
            g_h1[(bb1 * 32 + n + 1) * 992 + y1 * 32 + x1] = d[mh][j][3];
        }
    }
#pragma unroll
    for (int j = 0; j < 2; j++)
#pragma unroll
        for (int par = 0; par < 2; par++) {
            float a0 = d[0][j][par], a1 = d[0][j][par + 2];
            float a2 = d[1][j][par], a3 = d[1][j][par + 2];
            float s = (a0 + a1) + (a2 + a3);
            float q = (a0 * a0 + a1 * a1) + (a2 * a2 + a3 * a3);
#pragma unroll
            for (int off = 4; off < 32; off <<= 1) {
                s += __shfl_xor_sync(0xffffffffu, s, off);
                q += __shfl_xor_sync(0xffffffffu, q, off);
            }
            if (gid == 0) {
                int local = j * 8 + tig * 2 + par;
                sstat[warp][local][0] = s;
                sstat[warp][local][1] = q;
            }
        }
    __syncthreads();
    if (tid < 64) {
        int wn2 = tid >> 5, local = (tid >> 1) & 15, stat = tid & 1;
        float s = sstat[wn2][local][stat] + sstat[wn2 + 2][local][stat]
                + sstat[wn2 + 4][local][stat] + sstat[wn2 + 6][local][stat];
        int c = wn2 * 16 + local;
        g_part1[(c * NB1 + blockIdx.x) * 2 + stat] = s;
    }
}

__global__ __launch_bounds__(1024) void finalize_bn(int which, const float* __restrict__ gam, const float* __restrict__ bet) {
    __shared__ float rs[1024], rq[1024];
    int c = blockIdx.x;
    const float* part; float* out2; int nparts; float invc;
    if (which == 0) { part = g_part1; out2 = g_bn1p; nparts = NB1; invc = 1.f / 984064.f; }
    else            { part = g_part2; out2 = g_bn2p; nparts = NB2; invc = 1.f / 200704.f; }
    float s = 0.f, ss = 0.f;
    for (int i = threadIdx.x; i < nparts; i += 1024) {
        s  += part[(c * nparts + i) * 2 + 0];
        ss += part[(c * nparts + i) * 2 + 1];
    }
    rs[threadIdx.x] = s; rq[threadIdx.x] = ss; __syncthreads();
    for (int st = 512; st; st >>= 1) {
        if (threadIdx.x < st) { rs[threadIdx.x] += rs[threadIdx.x + st]; rq[threadIdx.x] += rq[threadIdx.x + st]; }
        __syncthreads();
    }
    if (threadIdx.x == 0) {
        float mean = rs[0] * invc;
        float var  = rq[0] * invc - mean * mean;
        float sc   = gam[c] * rsqrtf(var + EPSBN);
        out2[2 * c + 0] = sc;
        out2[2 * c + 1] = bet[c] - mean * sc;
    }
}

__global__ void pool1_kernel() {
    int idx = blockIdx.x * 256 + threadIdx.x;
    if (idx >= 7372800) return;
    int xo = idx % 15; int t1 = idx / 15;
    int yo = t1 % 15;  int t2 = t1 / 15;
    int c  = t2 & 31;  int b  = t2 >> 5;
    float sc = g_bn1p[2 * c], sh = g_bn1p[2 * c + 1];
    const float* p = g_h1 + (b * 32 + c) * 992 + (2 * yo) * 32 + 2 * xo;
    float2 r0 = *(const float2*)p;
    float2 r1 = *(const float2*)(p + 32);
    float m = fmaxf(fmaxf(r0.x, r0.y), fmaxf(r1.x, r1.y));
    g_p1[idx] = fmaxf(fmaf(m, sc, sh), 0.f);
}

// conv2 via warp mma + fused BN partials
__global__ __launch_bounds__(256) void conv2_mma() {
    __shared__ __align__(16) uint32_t A0[128 * 25];
    __shared__ __align__(16) uint32_t A1[128 * 25];
    __shared__ int ipb[128];
    __shared__ float sstat[8][32][2];
    const int tid = threadIdx.x;
    const int m0 = blockIdx.x * 128;
    const int warp = tid >> 5, lane = tid & 31;
    const int wm = warp >> 1, wn = warp & 1;
    const int gid = lane >> 2, tig = lane & 3;

    if (tid < 128) {
        int m = m0 + tid;
        int bb = m / 196, r = m - bb * 196;
        int y = r / 14, xx = r - y * 14;
        ipb[tid] = ((bb * 32) * 15 + y) * 15 + xx;
    }

    float d[2][4][4];
#pragma unroll
    for (int mh = 0; mh < 2; mh++)
#pragma unroll
        for (int j = 0; j < 4; j++)
#pragma unroll
            for (int e = 0; e < 4; e++) d[mh][j][e] = 0.f;

    for (int chunk = 0; chunk < 16; chunk++) {
        __syncthreads();
        for (int q = tid; q < 1024; q += 256) {
            int pos = q & 127, ii = q >> 7;
            int i = chunk * 8 + ii;
            int c = i >> 2, j = i & 3;
            int pix = ipb[pos] + c * 225 + (j >> 1) * 15 + (j & 1);
            float f[5]; feats5(g_p1[pix], f);
            float r0 = f[0] - __half2float(__float2half_rn(f[0]));
            float r1 = f[1] - __half2float(__float2half_rn(f[1]));
            float r2 = f[2] - __half2float(__float2half_rn(f[2]));
            float r3 = f[3] - __half2float(__float2half_rn(f[3]));
            float r4 = f[4] - __half2float(__float2half_rn(f[4]));
            int base = pos * 25 + ii * 3;
            A0[base + 0] = packh(f[0], f[1]);
            A0[base + 1] = packh(f[2], f[3]);
            A0[base + 2] = packh(f[4], 0.f);
            A1[base + 0] = packh(r0, r1);
            A1[base + 1] = packh(r2, r3);
            A1[base + 2] = packh(r4, 0.f);
        }
        __syncthreads();
#pragma unroll
        for (int ks = 0; ks < 3; ks++) {
            uint32_t ah[2][4], al[2][4];
            int kw = ks * 8 + tig;
#pragma unroll
            for (int mh = 0; mh < 2; mh++) {
                int rlo = wm * 32 + mh * 16 + gid;
                const uint32_t* p0l = A0 + rlo * 25;
                const uint32_t* p0h = A0 + (rlo + 8) * 25;
                const uint32_t* p1l = A1 + rlo * 25;
                const uint32_t* p1h = A1 + (rlo + 8) * 25;
                ah[mh][0] = p0l[kw]; ah[mh][1] = p0h[kw]; ah[mh][2] = p0l[kw + 4]; ah[mh][3] = p0h[kw + 4];
                al[mh][0] = p1l[kw]; al[mh][1] = p1h[kw]; al[mh][2] = p1l[kw + 4]; al[mh][3] = p1h[kw + 4];
            }
#pragma unroll
            for (int j = 0; j < 4; j++) {
                int idx = ((chunk * 3 + ks) * 8 + wn * 4 + j) * 32 + lane;
                uint2 bh = g_Bf0[idx];
                uint2 bl = g_Bf1[idx];
#pragma unroll
                for (int mh = 0; mh < 2; mh++) {
                    mma16816(d[mh][j], ah[mh], bh);
                    mma16816(d[mh][j], ah[mh], bl);
                    mma16816(d[mh][j], al[mh], bh);
                }
            }
        }
    }
#pragma unroll
    for (int mh = 0; mh < 2; mh++) {
        int mlo = m0 + wm * 32 + mh * 16 + gid;
        int bb0 = mlo / 196, rr0 = mlo - bb0 * 196;
        int y0 = rr0 / 14, x0 = rr0 - y0 * 14;
        int mhi = mlo + 8;
        int bb1 = mhi / 196, rr1 = mhi - bb1 * 196;
        int y1 = rr1 / 14, x1 = rr1 - y1 * 14;
#pragma unroll
        for (int j = 0; j < 4; j++) {
            int n = (wn * 4 + j) * 8 + tig * 2;
            g_h2[(bb0 * 64 + n) * 224 + y0 * 16 + x0]     = d[mh][j][0];
            g_h2[(bb0 * 64 + n + 1) * 224 + y0 * 16 + x0] = d[mh][j][1];
            g_h2[(bb1 * 64 + n) * 224 + y1 * 16 + x1]     = d[mh][j][2];
            g_h2[(bb1 * 64 + n + 1) * 224 + y1 * 16 + x1] = d[mh][j][3];
        }
    }
#pragma unroll
    for (int j = 0; j < 4; j++)
#pragma unroll
        for (int par = 0; par < 2; par++) {
            float a0 = d[0][j][par], a1 = d[0][j][par + 2];
            float a2 = d[1][j][par], a3 = d[1][j][par + 2];
            float s = (a0 + a1) + (a2 + a3);
            float q = (a0 * a0 + a1 * a1) + (a2 * a2 + a3 * a3);
#pragma unroll
            for (int off = 4; off < 32; off <<= 1) {
                s += __shfl_xor_sync(0xffffffffu, s, off);
                q += __shfl_xor_sync(0xffffffffu, q, off);
            }
            if (gid == 0) {
                int local = j * 8 + tig * 2 + par;
                sstat[warp][local][0] = s;
                sstat[warp][local][1] = q;
            }
        }
    __syncthreads();
    if (tid < 128) {
        int wn2 = tid >> 6, local = (tid >> 1) & 31, stat = tid & 1;
        float s = sstat[wn2][local][stat] + sstat[wn2 + 2][local][stat]
                + sstat[wn2 + 4][local][stat] + sstat[wn2 + 6][local][stat];
        int c = wn2 * 32 + local;
        g_part2[(c * NB2 + blockIdx.x) * 2 + stat] = s;
    }
}

__global__ void pool2_kernel() {
    int idx = blockIdx.x * 256 + threadIdx.x;
    if (idx >= 3211264) return;
    int xo = idx % 7; int t1 = idx / 7;
    int yo = t1 % 7;  int t2 = t1 / 7;
    int c  = t2 & 63;  int b  = t2 >> 6;
    float sc = g_bn2p[2 * c], sh = g_bn2p[2 * c + 1];
    const float* p = g_h2 + (b * 64 + c) * 224 + (2 * yo) * 16 + 2 * xo;
    float2 r0 = *(const float2*)p;
    float2 r1 = *(const float2*)(p + 16);
    float m = fmaxf(fmaxf(r0.x, r0.y), fmaxf(r1.x, r1.y));
    g_p2[idx] = fmaxf(fmaf(m, sc, sh), 0.f);
}

// fc1 via warp mma: M=64/block, N=64, k-split 7 x 7 chunks of 64
__global__ __launch_bounds__(256) void fc1_mma() {
    __shared__ __align__(16) uint32_t A0[64 * 33];
    __shared__ __align__(16) uint32_t A1[64 * 33];
    const int tid = threadIdx.x;
    const int m0 = blockIdx.x * 64;
    const int warp = tid >> 5, lane = tid & 31;
    const int wm = warp >> 1, wn = warp & 1;
    const int gid = lane >> 2, tig = lane & 3;

    float d[4][4];
#pragma unroll
    for (int j = 0; j < 4; j++)
#pragma unroll
        for (int e = 0; e < 4; e++) d[j][e] = 0.f;

    for (int cc = 0; cc < 7; cc++) {
        int chunk = blockIdx.y * 7 + cc;
        int k0 = chunk * 64;
        __syncthreads();
        for (int q = tid; q < 2048; q += 256) {
            int row = q >> 5, col = q & 31;
            const float* src = g_p2 + (m0 + row) * 3136 + k0 + col * 2;
            float f0 = src[0], f1 = src[1];
            float r0 = f0 - __half2float(__float2half_rn(f0));
            float r1 = f1 - __half2float(__float2half_rn(f1));
            A0[row * 33 + col] = packh(f0, f1);
            A1[row * 33 + col] = packh(r0, r1);
        }
        __syncthreads();
#pragma unroll
        for (int ks = 0; ks < 4; ks++) {
            uint32_t ah[4], al[4];
            int kw = ks * 8 + tig;
            int rlo = wm * 16 + gid;
            const uint32_t* p0l = A0 + rlo * 33;
            const uint32_t* p0h = A0 + (rlo + 8) * 33;
            const uint32_t* p1l = A1 + rlo * 33;
            const uint32_t* p1h = A1 + (rlo + 8) * 33;
            ah[0] = p0l[kw]; ah[1] = p0h[kw]; ah[2] = p0l[kw + 4]; ah[3] = p0h[kw + 4];
            al[0] = p1l[kw]; al[1] = p1h[kw]; al[2] = p1l[kw + 4]; al[3] = p1h[kw + 4];
#pragma unroll
            for (int j = 0; j < 4; j++) {
                int idx = ((chunk * 4 + ks) * 8 + wn * 4 + j) * 32 + lane;
                uint2 bh = g_Wf0[idx];
                uint2 bl = g_Wf1[idx];
                mma16816(d[j], ah, bh);
                mma16816(d[j], ah, bl);
                mma16816(d[j], al, bh);
            }
        }
    }
    float* dst = g_fc1p + blockIdx.y * 65536;
    int row_lo = m0 + wm * 16 + gid, row_hi = row_lo + 8;
#pragma unroll
    for (int j = 0; j < 4; j++) {
        int n = (wn * 4 + j) * 8 + tig * 2;
        dst[row_lo * 64 + n]     = d[j][0];
        dst[row_lo * 64 + n + 1] = d[j][1];
        dst[row_hi * 64 + n]     = d[j][2];
        dst[row_hi * 64 + n + 1] = d[j][3];
    }
}

__global__ void bn3_kernel(const float* __restrict__ fc1b,
                           const float* __restrict__ gam, const float* __restrict__ bet) {
    __shared__ float rs[256], rq[256];
    int c = blockIdx.x;
    float bias = fc1b[c];
    float s = 0.f, ss = 0.f;
    for (int b = threadIdx.x; b < 1024; b += 256) {
        float v = bias;
#pragma unroll
        for (int k = 0; k < 7; k++) v += g_fc1p[k * 65536 + b * 64 + c];
        g_a1[b * 64 + c] = v;
        s += v; ss += v * v;
    }
    rs[threadIdx.x] = s; rq[threadIdx.x] = ss; __syncthreads();
    for (int st = 128; st; st >>= 1) {
        if (threadIdx.x < st) { rs[threadIdx.x] += rs[threadIdx.x + st]; rq[threadIdx.x] += rq[threadIdx.x + st]; }
        __syncthreads();
    }
    if (threadIdx.x == 0) {
        float mean = rs[0] / 1024.f;
        float var  = rq[0] / 1024.f - mean * mean;
        float sc   = gam[c] * rsqrtf(var + EPSBN);
        g_bn3p[2 * c + 0] = sc;
        g_bn3p[2 * c + 1] = bet[c] - mean * sc;
    }
}

__global__ void final_kernel(const float* __restrict__ w2, const float* __restrict__ b2,
                             float* __restrict__ out) {
    __shared__ float hm[64];
    int b = blockIdx.x, tid = threadIdx.x;
    float v = g_a1[b * 64 + tid];
    hm[tid] = fmaxf(fmaf(v, g_bn3p[2 * tid], g_bn3p[2 * tid + 1]), 0.f);
    __syncthreads();
    if (tid < 10) {
        float acc = b2[tid];
#pragma unroll
        for (int k = 0; k < 64; k++) acc = fmaf(hm[k], w2[tid * 64 + k], acc);
        out[b * 10 + tid] = acc;
    }
}

extern "C" void kernel_launch(void* const* d_in, const int* in_sizes, int n_in,
                              void* d_out, int out_size) {
    const float* x    = (const float*)d_in[0];
    const float* bw1  = (const float*)d_in[1];
    const float* sw1  = (const float*)d_in[2];
    const float* bn1g = (const float*)d_in[3];
    const float* bn1b = (const float*)d_in[4];
    const float* bw2  = (const float*)d_in[5];
    const float* sw2  = (const float*)d_in[6];
    const float* bn2g = (const float*)d_in[7];
    const float* bn2b = (const float*)d_in[8];
    const float* fc1w = (const float*)d_in[9];
    const float* fc1b = (const float*)d_in[10];
    const float* bn3g = (const float*)d_in[11];
    const float* bn3b = (const float*)d_in[12];
    const float* fc2w = (const float*)d_in[13];
    const float* fc2b = (const float*)d_in[14];
    float* out = (float*)d_out;

    wprep1_kernel<<<3, 256>>>(bw1, sw1);
    wprep2_kernel<<<48, 256>>>(bw2, sw2);
    wprepf_kernel<<<196, 256>>>(fc1w);
    conv1_mma<<<NB1, 256>>>(x);
    finalize_bn<<<32, 1024>>>(0, bn1g, bn1b);
    pool1_kernel<<<28800, 256>>>();
    conv2_mma<<<NB2, 256>>>();
    finalize_bn<<<64, 1024>>>(1, bn2g, bn2b);
    pool2_kernel<<<12544, 256>>>();
    fc1_mma<<<dim3(16, 7), 256>>>();
    bn3_kernel<<<64, 256>>>(fc1b, bn3g, bn3b);
    final_kernel<<<1024, 64>>>(fc2w, fc2b, out);
}

// round 17
// speedup vs baseline: 2.0383x; 1.0119x over previous
#include <cuda_runtime.h>
#include <cuda_fp16.h>
#include <stdint.h>

#define EPSBN 1e-5f
#define NB1 8192
#define NB2 1568

// ---------------- device scratch ----------------
__device__ float  g_h1[32505856];          // [1024,32,31,32] rows padded
__device__ float  g_part1[32*NB1*2];
__device__ float  g_bn1p[64];
__device__ float  g_p1[7372800];           // pooled1 [1024,32,15,15]
__device__ float  g_h2[14680064];          // [1024,64,14,16] rows padded
__device__ float  g_part2[64*NB2*2];
__device__ float  g_bn2p[128];
__device__ float  g_p2[3211264];           // [1024,3136]
__device__ float  g_fc1p[7*65536];
__device__ float  g_a1[65536];
__device__ float  g_bn3p[128];
__device__ uint2  g_B1f0[640];
__device__ uint2  g_B1f1[640];
__device__ uint2  g_Bf0[12288];
__device__ uint2  g_Bf1[12288];
__device__ uint2  g_Wf0[50176];
__device__ uint2  g_Wf1[50176];

__device__ __forceinline__ void mma16816(float* d, const uint32_t* a, uint2 b) {
    asm volatile("mma.sync.aligned.m16n8k16.row.col.f32.f16.f16.f32 "
        "{%0,%1,%2,%3}, {%4,%5,%6,%7}, {%8,%9}, {%0,%1,%2,%3};"
        : "+f"(d[0]), "+f"(d[1]), "+f"(d[2]), "+f"(d[3])
        : "r"(a[0]), "r"(a[1]), "r"(a[2]), "r"(a[3]), "r"(b.x), "r"(b.y));
}

__device__ __forceinline__ uint32_t packh(float a, float b) {
    half ha = __float2half_rn(a), hb = __float2half_rn(b);
    return (uint32_t)__half_as_ushort(ha) | ((uint32_t)__half_as_ushort(hb) << 16);
}

// silu + 4 cubic B-spline bases on uniform knots {-7,-5,...,7} — closed form
__device__ __forceinline__ void feats5(float v, float f[5]) {
    f[0] = v / (1.f + __expf(-v));
    float t = (v + 7.f) * 0.5f;
    float sf = floorf(t);
    int s = (int)sf;
    float u = t - sf;
    bool in = (v >= -7.f) && (v < 7.f);
    float u2 = u * u, u3 = u2 * u;
    float om = 1.f - u;
    const float i6 = 1.f / 6.f;
    float w[4];
    w[0] = om * om * om * i6;
    w[1] = (3.f * u3 - 6.f * u2 + 4.f) * i6;
    w[2] = (-3.f * u3 + 3.f * u2 + 3.f * u + 1.f) * i6;
    w[3] = u3 * i6;
#pragma unroll
    for (int j = 0; j < 4; j++) {
        int k = j - s + 3;
        float val = 0.f;
#pragma unroll
        for (int kk = 0; kk < 4; kk++) val = (k == kk) ? w[kk] : val;
        f[j + 1] = (in && k >= 0 && k < 4) ? val : 0.f;
    }
}

// conv1 weights, K mapped kk = i*6 + t (t<5), K=80 (5 ksteps)
__global__ void wprep1_kernel(const float* __restrict__ wb1, const float* __restrict__ ws1) {
    int q = blockIdx.x * 256 + threadIdx.x;
    if (q >= 640) return;
    int lane = q & 31; int r = q >> 5;
    int n8t = r & 3; int ks = r >> 2;
    int gid = lane >> 2, tig = lane & 3;
    int n = n8t * 8 + gid;
    uint32_t h[2], l[2];
#pragma unroll
    for (int reg = 0; reg < 2; reg++) {
        uint32_t ph = 0, pl = 0;
#pragma unroll
        for (int e = 0; e < 2; e++) {
            int kk = ks * 16 + tig * 2 + reg * 8 + e;
            int i = kk / 6, t = kk - i * 6;
            float w = 0.f;
            if (t < 5 && i < 12)
                w = (t == 0) ? wb1[n * 12 + i] : ws1[(n * 12 + i) * 4 + (t - 1)];
            half hh = __float2half_rn(w);
            half hl = __float2half_rn(w - __half2float(hh));
            ph |= (uint32_t)__half_as_ushort(hh) << (16 * e);
            pl |= (uint32_t)__half_as_ushort(hl) << (16 * e);
        }
        h[reg] = ph; l[reg] = pl;
    }
    g_B1f0[q] = make_uint2(h[0], h[1]);
    g_B1f1[q] = make_uint2(l[0], l[1]);
}

// conv2 weights, kk = i_local*6 + t, 48 cols = 3 ksteps
__global__ void wprep2_kernel(const float* __restrict__ wb2, const float* __restrict__ ws2) {
    int q = blockIdx.x * 256 + threadIdx.x;
    if (q >= 12288) return;
    int lane = q & 31; int r = q >> 5;
    int n8t = r & 7; r >>= 3;
    int ks = r % 3; int chunk = r / 3;
    int gid = lane >> 2, tig = lane & 3;
    int n = n8t * 8 + gid;
    uint32_t h[2], l[2];
#pragma unroll
    for (int reg = 0; reg < 2; reg++) {
        uint32_t ph = 0, pl = 0;
#pragma unroll
        for (int e = 0; e < 2; e++) {
            int kk = ks * 16 + tig * 2 + reg * 8 + e;
            int il = kk / 6, t = kk - il * 6;
            float w = 0.f;
            if (t < 5) {
                int i = chunk * 8 + il;
                w = (t == 0) ? wb2[n * 128 + i] : ws2[(n * 128 + i) * 4 + (t - 1)];
            }
            half hh = __float2half_rn(w);
            half hl = __float2half_rn(w - __half2float(hh));
            ph |= (uint32_t)__half_as_ushort(hh) << (16 * e);
            pl |= (uint32_t)__half_as_ushort(hl) << (16 * e);
        }
        h[reg] = ph; l[reg] = pl;
    }
    g_Bf0[q] = make_uint2(h[0], h[1]);
    g_Bf1[q] = make_uint2(l[0], l[1]);
}

// fc1 weights -> frags
__global__ void wprepf_kernel(const float* __restrict__ w) {
    int q = blockIdx.x * 256 + threadIdx.x;
    if (q >= 50176) return;
    int lane = q & 31; int r = q >> 5;
    int n8t = r & 7; r >>= 3;
    int ks = r & 3; int chunk = r >> 2;
    int gid = lane >> 2, tig = lane & 3;
    int n = n8t * 8 + gid;
    uint32_t h[2], l[2];
#pragma unroll
    for (int reg = 0; reg < 2; reg++) {
        uint32_t ph = 0, pl = 0;
#pragma unroll
        for (int e = 0; e < 2; e++) {
            int k = chunk * 64 + ks * 16 + tig * 2 + reg * 8 + e;
            float wv = w[n * 3136 + k];
            half hh = __float2half_rn(wv);
            half hl = __float2half_rn(wv - __half2float(hh));
            ph |= (uint32_t)__half_as_ushort(hh) << (16 * e);
            pl |= (uint32_t)__half_as_ushort(hl) << (16 * e);
        }
        h[reg] = ph; l[reg] = pl;
    }
    g_Wf0[q] = make_uint2(h[0], h[1]);
    g_Wf1[q] = make_uint2(l[0], l[1]);
}

// conv1 via warp mma, strip-tiled gather (each pixel's feats computed ONCE)
// block = (batch, 4-row strip); positions pos = py*31+px, py 0..nrows-1
__global__ __launch_bounds__(256) void conv1_mma(const float* __restrict__ x) {
    __shared__ __align__(16) uint32_t A0[128 * 41];
    __shared__ __align__(16) uint32_t A1[128 * 41];
    __shared__ float sstat[8][16][2];
    const int tid = threadIdx.x;
    const int b = blockIdx.x >> 3;
    const int strip = blockIdx.x & 7;
    const int y0 = strip * 4;
    const int nrows = (strip == 7) ? 3 : 4;
    const int npos = nrows * 31;            // 124 or 93
    const int ninr = nrows + 1;             // input rows needed
    const int warp = tid >> 5, lane = tid & 31;
    const int wm = warp >> 1, wn = warp & 1;
    const int gid = lane >> 2, tig = lane & 3;

    // zero pad cols 36..39 for all rows, both tiles
    for (int q = tid; q < 1024; q += 256) {
        int w = q & 511, tile = q >> 9;
        int pos = w >> 2, cc = w & 3;
        (tile ? A1 : A0)[pos * 41 + 36 + cc] = 0u;
    }
    // zero full pad rows npos..127, both tiles
    {
        int padw = (128 - npos) * 41;
        for (int q = tid; q < padw * 2; q += 256) {
            int tile = q >= padw;
            int rem = tile ? q - padw : q;
            (tile ? A1 : A0)[npos * 41 + rem] = 0u;
        }
    }
    __syncthreads();
    // stage: one feats5 per needed input pixel, scatter to <=4 patch slots
    int tot = 96 * ninr;    // 3 channels * 32 cols * ninr rows
    for (int q = tid; q < tot; q += 256) {
        int c = q / (32 * ninr);
        int rem = q - c * 32 * ninr;
        int ry = rem >> 5, col = rem & 31;
        float v = x[((b * 3 + c) * 32 + y0 + ry) * 32 + col];
        float f[5]; feats5(v, f);
        float r0 = f[0] - __half2float(__float2half_rn(f[0]));
        float r1 = f[1] - __half2float(__float2half_rn(f[1]));
        float r2 = f[2] - __half2float(__float2half_rn(f[2]));
        float r3 = f[3] - __half2float(__float2half_rn(f[3]));
        float r4 = f[4] - __half2float(__float2half_rn(f[4]));
        uint32_t h0 = packh(f[0], f[1]), h1v = packh(f[2], f[3]), h2 = packh(f[4], 0.f);
        uint32_t l0 = packh(r0, r1),    l1 = packh(r2, r3),     l2 = packh(r4, 0.f);
#pragma unroll
        for (int dy = 0; dy < 2; dy++) {
            int py = ry - dy;
            if (py < 0 || py >= nrows) continue;
#pragma unroll
            for (int dx = 0; dx < 2; dx++) {
                int px = col - dx;
                if (px < 0 || px >= 31) continue;
                int base = (py * 31 + px) * 41 + (c * 4 + dy * 2 + dx) * 3;
                A0[base] = h0; A0[base + 1] = h1v; A0[base + 2] = h2;
                A1[base] = l0; A1[base + 1] = l1; A1[base + 2] = l2;
            }
        }
    }
    __syncthreads();

    float d[2][2][4];
#pragma unroll
    for (int mh = 0; mh < 2; mh++)
#pragma unroll
        for (int j = 0; j < 2; j++)
#pragma unroll
            for (int e = 0; e < 4; e++) d[mh][j][e] = 0.f;

#pragma unroll
    for (int ks = 0; ks < 5; ks++) {
        uint32_t ah[2][4], al[2][4];
        int kw = ks * 8 + tig;
#pragma unroll
        for (int mh = 0; mh < 2; mh++) {
            int rlo = wm * 32 + mh * 16 + gid;
            const uint32_t* p0l = A0 + rlo * 41;
            const uint32_t* p0h = A0 + (rlo + 8) * 41;
            const uint32_t* p1l = A1 + rlo * 41;
            const uint32_t* p1h = A1 + (rlo + 8) * 41;
            ah[mh][0] = p0l[kw]; ah[mh][1] = p0h[kw]; ah[mh][2] = p0l[kw + 4]; ah[mh][3] = p0h[kw + 4];
            al[mh][0] = p1l[kw]; al[mh][1] = p1h[kw]; al[mh][2] = p1l[kw + 4]; al[mh][3] = p1h[kw + 4];
        }
#pragma unroll
        for (int j = 0; j < 2; j++) {
            int idx = (ks * 4 + wn * 2 + j) * 32 + lane;
            uint2 bh = g_B1f0[idx];
            uint2 bl = g_B1f1[idx];
#pragma unroll
            for (int mh = 0; mh < 2; mh++) {
                mma16816(d[mh][j], ah[mh], bh);
                mma16816(d[mh][j], ah[mh], bl);
                mma16816(d[mh][j], al[mh], bh);
            }
        }
    }
    // epilogue: masked stores (pad positions produce zeros, excluded from output)
#pragma unroll
    for (int mh = 0; mh < 2; mh++) {
        int plo = wm * 32 + mh * 16 + gid;
        int phi = plo + 8;
        int ylo = y0 + plo / 31, xlo = plo % 31;
        int yhi = y0 + phi / 31, xhi = phi % 31;
        bool oklo = plo < npos, okhi = phi < npos;
#pragma unroll
        for (int j = 0; j < 2; j++) {
            int n = (wn * 2 + j) * 8 + tig * 2;
            if (oklo) {
                g_h1[(b * 32 + n) * 992 + ylo * 32 + xlo]     = d[mh][j][0];
                g_h1[(b * 32 + n + 1) * 992 + ylo * 32 + xlo] = d[mh][j][1];
            }
            if (okhi) {
                g_h1[(b * 32 + n) * 992 + yhi * 32 + xhi]     = d[mh][j][2];
                g_h1[(b * 32 + n + 1) * 992 + yhi * 32 + xhi] = d[mh][j][3];
            }
        }
    }
    // fused BN partials (pad rows contribute exact zeros)
#pragma unroll
    for (int j = 0; j < 2; j++)
#pragma unroll
        for (int par = 0; par < 2; par++) {
            float a0 = d[0][j][par], a1 = d[0][j][par + 2];
            float a2 = d[1][j][par], a3 = d[1][j][par + 2];
            float s = (a0 + a1) + (a2 + a3);
            float q = (a0 * a0 + a1 * a1) + (a2 * a2 + a3 * a3);
#pragma unroll
            for (int off = 4; off < 32; off <<= 1) {
                s += __shfl_xor_sync(0xffffffffu, s, off);
                q += __shfl_xor_sync(0xffffffffu, q, off);
            }
            if (gid == 0) {
                int local = j * 8 + tig * 2 + par;
                sstat[warp][local][0] = s;
                sstat[warp][local][1] = q;
            }
        }
    __syncthreads();
    if (tid < 64) {
        int wn2 = tid >> 5, local = (tid >> 1) & 15, stat = tid & 1;
        float s = sstat[wn2][local][stat] + sstat[wn2 + 2][local][stat]
                + sstat[wn2 + 4][local][stat] + sstat[wn2 + 6][local][stat];
        int c = wn2 * 16 + local;
        g_part1[(c * NB1 + blockIdx.x) * 2 + stat] = s;
    }
}

__global__ __launch_bounds__(1024) void finalize_bn(int which, const float* __restrict__ gam, const float* __restrict__ bet) {
    __shared__ float rs[1024], rq[1024];
    int c = blockIdx.x;
    const float* part; float* out2; int nparts; float invc;
    if (which == 0) { part = g_part1; out2 = g_bn1p; nparts = NB1; invc = 1.f / 984064.f; }
    else            { part = g_part2; out2 = g_bn2p; nparts = NB2; invc = 1.f / 200704.f; }
    float s = 0.f, ss = 0.f;
    for (int i = threadIdx.x; i < nparts; i += 1024) {
        s  += part[(c * nparts + i) * 2 + 0];
        ss += part[(c * nparts + i) * 2 + 1];
    }
    rs[threadIdx.x] = s; rq[threadIdx.x] = ss; __syncthreads();
    for (int st = 512; st; st >>= 1) {
        if (threadIdx.x < st) { rs[threadIdx.x] += rs[threadIdx.x + st]; rq[threadIdx.x] += rq[threadIdx.x + st]; }
        __syncthreads();
    }
    if (threadIdx.x == 0) {
        float mean = rs[0] * invc;
        float var  = rq[0] * invc - mean * mean;
        float sc   = gam[c] * rsqrtf(var + EPSBN);
        out2[2 * c + 0] = sc;
        out2[2 * c + 1] = bet[c] - mean * sc;
    }
}

__global__ void pool1_kernel() {
    int idx = blockIdx.x * 256 + threadIdx.x;
    if (idx >= 7372800) return;
    int xo = idx % 15; int t1 = idx / 15;
    int yo = t1 % 15;  int t2 = t1 / 15;
    int c  = t2 & 31;  int b  = t2 >> 5;
    float sc = g_bn1p[2 * c], sh = g_bn1p[2 * c + 1];
    const float* p = g_h1 + (b * 32 + c) * 992 + (2 * yo) * 32 + 2 * xo;
    float2 r0 = *(const float2*)p;
    float2 r1 = *(const float2*)(p + 32);
    float m = fmaxf(fmaxf(r0.x, r0.y), fmaxf(r1.x, r1.y));
    g_p1[idx] = fmaxf(fmaf(m, sc, sh), 0.f);
}

// conv2 via warp mma + fused BN partials
__global__ __launch_bounds__(256) void conv2_mma() {
    __shared__ __align__(16) uint32_t A0[128 * 25];
    __shared__ __align__(16) uint32_t A1[128 * 25];
    __shared__ int ipb[128];
    __shared__ float sstat[8][32][2];
    const int tid = threadIdx.x;
    const int m0 = blockIdx.x * 128;
    const int warp = tid >> 5, lane = tid & 31;
    const int wm = warp >> 1, wn = warp & 1;
    const int gid = lane >> 2, tig = lane & 3;

    if (tid < 128) {
        int m = m0 + tid;
        int bb = m / 196, r = m - bb * 196;
        int y = r / 14, xx = r - y * 14;
        ipb[tid] = ((bb * 32) * 15 + y) * 15 + xx;
    }

    float d[2][4][4];
#pragma unroll
    for (int mh = 0; mh < 2; mh++)
#pragma unroll
        for (int j = 0; j < 4; j++)
#pragma unroll
            for (int e = 0; e < 4; e++) d[mh][j][e] = 0.f;

    for (int chunk = 0; chunk < 16; chunk++) {
        __syncthreads();
        for (int q = tid; q < 1024; q += 256) {
            int pos = q & 127, ii = q >> 7;
            int i = chunk * 8 + ii;
            int c = i >> 2, j = i & 3;
            int pix = ipb[pos] + c * 225 + (j >> 1) * 15 + (j & 1);
            float f[5]; feats5(g_p1[pix], f);
            float r0 = f[0] - __half2float(__float2half_rn(f[0]));
            float r1 = f[1] - __half2float(__float2half_rn(f[1]));
            float r2 = f[2] - __half2float(__float2half_rn(f[2]));
            float r3 = f[3] - __half2float(__float2half_rn(f[3]));
            float r4 = f[4] - __half2float(__float2half_rn(f[4]));
            int base = pos * 25 + ii * 3;
            A0[base + 0] = packh(f[0], f[1]);
            A0[base + 1] = packh(f[2], f[3]);
            A0[base + 2] = packh(f[4], 0.f);
            A1[base + 0] = packh(r0, r1);
            A1[base + 1] = packh(r2, r3);
            A1[base + 2] = packh(r4, 0.f);
        }
        __syncthreads();
#pragma unroll
        for (int ks = 0; ks < 3; ks++) {
            uint32_t ah[2][4], al[2][4];
            int kw = ks * 8 + tig;
#pragma unroll
            for (int mh = 0; mh < 2; mh++) {
                int rlo = wm * 32 + mh * 16 + gid;
                const uint32_t* p0l = A0 + rlo * 25;
                const uint32_t* p0h = A0 + (rlo + 8) * 25;
                const uint32_t* p1l = A1 + rlo * 25;
                const uint32_t* p1h = A1 + (rlo + 8) * 25;
                ah[mh][0] = p0l[kw]; ah[mh][1] = p0h[kw]; ah[mh][2] = p0l[kw + 4]; ah[mh][3] = p0h[kw + 4];
                al[mh][0] = p1l[kw]; al[mh][1] = p1h[kw]; al[mh][2] = p1l[kw + 4]; al[mh][3] = p1h[kw + 4];
            }
#pragma unroll
            for (int j = 0; j < 4; j++) {
                int idx = ((chunk * 3 + ks) * 8 + wn * 4 + j) * 32 + lane;
                uint2 bh = g_Bf0[idx];
                uint2 bl = g_Bf1[idx];
#pragma unroll
                for (int mh = 0; mh < 2; mh++) {
                    mma16816(d[mh][j], ah[mh], bh);
                    mma16816(d[mh][j], ah[mh], bl);
                    mma16816(d[mh][j], al[mh], bh);
                }
            }
        }
    }
#pragma unroll
    for (int mh = 0; mh < 2; mh++) {
        int mlo = m0 + wm * 32 + mh * 16 + gid;
        int bb0 = mlo / 196, rr0 = mlo - bb0 * 196;
        int y0 = rr0 / 14, x0 = rr0 - y0 * 14;
        int mhi = mlo + 8;
        int bb1 = mhi / 196, rr1 = mhi - bb1 * 196;
        int y1 = rr1 / 14, x1 = rr1 - y1 * 14;
#pragma unroll
        for (int j = 0; j < 4; j++) {
            int n = (wn * 4 + j) * 8 + tig * 2;
            g_h2[(bb0 * 64 + n) * 224 + y0 * 16 + x0]     = d[mh][j][0];
            g_h2[(bb0 * 64 + n + 1) * 224 + y0 * 16 + x0] = d[mh][j][1];
            g_h2[(bb1 * 64 + n) * 224 + y1 * 16 + x1]     = d[mh][j][2];
            g_h2[(bb1 * 64 + n + 1) * 224 + y1 * 16 + x1] = d[mh][j][3];
        }
    }
#pragma unroll
    for (int j = 0; j < 4; j++)
#pragma unroll
        for (int par = 0; par < 2; par++) {
            float a0 = d[0][j][par], a1 = d[0][j][par + 2];
            float a2 = d[1][j][par], a3 = d[1][j][par + 2];
            float s = (a0 + a1) + (a2 + a3);
            float q = (a0 * a0 + a1 * a1) + (a2 * a2 + a3 * a3);
#pragma unroll
            for (int off = 4; off < 32; off <<= 1) {
                s += __shfl_xor_sync(0xffffffffu, s, off);
                q += __shfl_xor_sync(0xffffffffu, q, off);
            }
            if (gid == 0) {
                int local = j * 8 + tig * 2 + par;
                sstat[warp][local][0] = s;
                sstat[warp][local][1] = q;
            }
        }
    __syncthreads();
    if (tid < 128) {
        int wn2 = tid >> 6, local = (tid >> 1) & 31, stat = tid & 1;
        float s = sstat[wn2][local][stat] + sstat[wn2 + 2][local][stat]
                + sstat[wn2 + 4][local][stat] + sstat[wn2 + 6][local][stat];
        int c = wn2 * 32 + local;
        g_part2[(c * NB2 + blockIdx.x) * 2 + stat] = s;
    }
}

__global__ void pool2_kernel() {
    int idx = blockIdx.x * 256 + threadIdx.x;
    if (idx >= 3211264) return;
    int xo = idx % 7; int t1 = idx / 7;
    int yo = t1 % 7;  int t2 = t1 / 7;
    int c  = t2 & 63;  int b  = t2 >> 6;
    float sc = g_bn2p[2 * c], sh = g_bn2p[2 * c + 1];
    const float* p = g_h2 + (b * 64 + c) * 224 + (2 * yo) * 16 + 2 * xo;
    float2 r0 = *(const float2*)p;
    float2 r1 = *(const float2*)(p + 16);
    float m = fmaxf(fmaxf(r0.x, r0.y), fmaxf(r1.x, r1.y));
    g_p2[idx] = fmaxf(fmaf(m, sc, sh), 0.f);
}

// fc1 via warp mma: M=64/block, N=64, k-split 7 x 7 chunks of 64
__global__ __launch_bounds__(256) void fc1_mma() {
    __shared__ __align__(16) uint32_t A0[64 * 33];
    __shared__ __align__(16) uint32_t A1[64 * 33];
    const int tid = threadIdx.x;
    const int m0 = blockIdx.x * 64;
    const int warp = tid >> 5, lane = tid & 31;
    const int wm = warp >> 1, wn = warp & 1;
    const int gid = lane >> 2, tig = lane & 3;

    float d[4][4];
#pragma unroll
    for (int j = 0; j < 4; j++)
#pragma unroll
        for (int e = 0; e < 4; e++) d[j][e] = 0.f;

    for (int cc = 0; cc < 7; cc++) {
        int chunk = blockIdx.y * 7 + cc;
        int k0 = chunk * 64;
        __syncthreads();
        for (int q = tid; q < 2048; q += 256) {
            int row = q >> 5, col = q & 31;
            const float* src = g_p2 + (m0 + row) * 3136 + k0 + col * 2;
            float f0 = src[0], f1 = src[1];
            float r0 = f0 - __half2float(__float2half_rn(f0));
            float r1 = f1 - __half2float(__float2half_rn(f1));
            A0[row * 33 + col] = packh(f0, f1);
            A1[row * 33 + col] = packh(r0, r1);
        }
        __syncthreads();
#pragma unroll
        for (int ks = 0; ks < 4; ks++) {
            uint32_t ah[4], al[4];
            int kw = ks * 8 + tig;
            int rlo = wm * 16 + gid;
            const uint32_t* p0l = A0 + rlo * 33;
            const uint32_t* p0h = A0 + (rlo + 8) * 33;
            const uint32_t* p1l = A1 + rlo * 33;
            const uint32_t* p1h = A1 + (rlo + 8) * 33;
            ah[0] = p0l[kw]; ah[1] = p0h[kw]; ah[2] = p0l[kw + 4]; ah[3] = p0h[kw + 4];
            al[0] = p1l[kw]; al[1] = p1h[kw]; al[2] = p1l[kw + 4]; al[3] = p1h[kw + 4];
#pragma unroll
            for (int j = 0; j < 4; j++) {
                int idx = ((chunk * 4 + ks) * 8 + wn * 4 + j) * 32 + lane;
                uint2 bh = g_Wf0[idx];
                uint2 bl = g_Wf1[idx];
                mma16816(d[j], ah, bh);
                mma16816(d[j], ah, bl);
                mma16816(d[j], al, bh);
            }
        }
    }
    float* dst = g_fc1p + blockIdx.y * 65536;
    int row_lo = m0 + wm * 16 + gid, row_hi = row_lo + 8;
#pragma unroll
    for (int j = 0; j < 4; j++) {
        int n = (wn * 4 + j) * 8 + tig * 2;
        dst[row_lo * 64 + n]     = d[j][0];
        dst[row_lo * 64 + n + 1] = d[j][1];
        dst[row_hi * 64 + n]     = d[j][2];
        dst[row_hi * 64 + n + 1] = d[j][3];
    }
}

__global__ void bn3_kernel(const float* __restrict__ fc1b,
                           const float* __restrict__ gam, const float* __restrict__ bet) {
    __shared__ float rs[256], rq[256];
    int c = blockIdx.x;
    float bias = fc1b[c];
    float s = 0.f, ss = 0.f;
    for (int b = threadIdx.x; b < 1024; b += 256) {
        float v = bias;
#pragma unroll
        for (int k = 0; k < 7; k++) v += g_fc1p[k * 65536 + b * 64 + c];
        g_a1[b * 64 + c] = v;
        s += v; ss += v * v;
    }
    rs[threadIdx.x] = s; rq[threadIdx.x] = ss; __syncthreads();
    for (int st = 128; st; st >>= 1) {
        if (threadIdx.x < st) { rs[threadIdx.x] += rs[threadIdx.x + st]; rq[threadIdx.x] += rq[threadIdx.x + st]; }
        __syncthreads();
    }
    if (threadIdx.x == 0) {
        float mean = rs[0] / 1024.f;
        float var  = rq[0] / 1024.f - mean * mean;
        float sc   = gam[c] * rsqrtf(var + EPSBN);
        g_bn3p[2 * c + 0] = sc;
        g_bn3p[2 * c + 1] = bet[c] - mean * sc;
    }
}

__global__ void final_kernel(const float* __restrict__ w2, const float* __restrict__ b2,
                             float* __restrict__ out) {
    __shared__ float hm[64];
    int b = blockIdx.x, tid = threadIdx.x;
    float v = g_a1[b * 64 + tid];
    hm[tid] = fmaxf(fmaf(v, g_bn3p[2 * tid], g_bn3p[2 * tid + 1]), 0.f);
    __syncthreads();
    if (tid < 10) {
        float acc = b2[tid];
#pragma unroll
        for (int k = 0; k < 64; k++) acc = fmaf(hm[k], w2[tid * 64 + k], acc);
        out[b * 10 + tid] = acc;
    }
}

extern "C" void kernel_launch(void* const* d_in, const int* in_sizes, int n_in,
                              void* d_out, int out_size) {
    const float* x    = (const float*)d_in[0];
    const float* bw1  = (const float*)d_in[1];
    const float* sw1  = (const float*)d_in[2];
    const float* bn1g = (const float*)d_in[3];
    const float* bn1b = (const float*)d_in[4];
    const float* bw2  = (const float*)d_in[5];
    const float* sw2  = (const float*)d_in[6];
    const float* bn2g = (const float*)d_in[7];
    const float* bn2b = (const float*)d_in[8];
    const float* fc1w = (const float*)d_in[9];
    const float* fc1b = (const float*)d_in[10];
    const float* bn3g = (const float*)d_in[11];
    const float* bn3b = (const float*)d_in[12];
    const float* fc2w = (const float*)d_in[13];
    const float* fc2b = (const float*)d_in[14];
    float* out = (float*)d_out;

    wprep1_kernel<<<3, 256>>>(bw1, sw1);
    wprep2_kernel<<<48, 256>>>(bw2, sw2);
    wprepf_kernel<<<196, 256>>>(fc1w);
    conv1_mma<<<NB1, 256>>>(x);
    finalize_bn<<<32, 1024>>>(0, bn1g, bn1b);
    pool1_kernel<<<28800, 256>>>();
    conv2_mma<<<NB2, 256>>>();
    finalize_bn<<<64, 1024>>>(1, bn2g, bn2b);
    pool2_kernel<<<12544, 256>>>();
    fc1_mma<<<dim3(16, 7), 256>>>();
    bn3_kernel<<<64, 256>>>(fc1b, bn3g, bn3b);
    final_kernel<<<1024, 64>>>(fc2w, fc2b, out);
}